// round 2
// baseline (speedup 1.0000x reference)
#include <cuda_runtime.h>
#include <math.h>

#define NNODES 4096
#define FEAT   128
#define NEDGES 65536
#define NG     317
#define NB     64
#define NC     64
#define HID    512
#define DH     64
#define NROWS  (NG*NB)
#define FFD    1024

__device__ float g_deg[NNODES];
__device__ float g_agg[NNODES*FEAT];
__device__ float g_pooled[NB*FEAT];
__device__ float g_X  [(size_t)NROWS*HID];
__device__ float g_Qm [(size_t)NROWS*HID];
__device__ float g_Km [(size_t)NROWS*HID];
__device__ float g_Vm [(size_t)NROWS*HID];
__device__ float g_att[(size_t)NROWS*HID];
__device__ float g_csum[NC*HID];
__device__ float g_meanh[NC*HID];
__device__ float g_h1[NC*FFD];
__device__ float g_h2[NC*HID];
__device__ float g_int[NC*HID];
__device__ int   g_cs[NC+1];

// ---------------- init: zero deg/agg, prefix-sum counts ----------------
__global__ void k_init(const int* __restrict__ counts) {
    int i = blockIdx.x * blockDim.x + threadIdx.x;
    int nt = gridDim.x * blockDim.x;
    if (i < NNODES) g_deg[i] = 0.f;
    for (int j = i; j < NNODES*FEAT; j += nt) g_agg[j] = 0.f;
    if (i == 0) {
        int s = 0;
        for (int c = 0; c < NC; c++) { g_cs[c] = s; s += counts[c]; }
        g_cs[NC] = s;
    }
}

// ---------------- edge aggregation (warp per edge) ----------------
__global__ void k_edges(const float* __restrict__ x, const int* __restrict__ ei) {
    int t = blockIdx.x * blockDim.x + threadIdx.x;
    int e = t >> 5, lane = t & 31;
    if (e >= NEDGES) return;
    int s = ei[e], d = ei[NEDGES + e];
    float4 v = *(const float4*)(x + (size_t)s*FEAT + lane*4);
    float* a = g_agg + (size_t)d*FEAT + lane*4;
    atomicAdd(a+0, v.x); atomicAdd(a+1, v.y);
    atomicAdd(a+2, v.z); atomicAdd(a+3, v.w);
    if (lane == 0) atomicAdd(g_deg + d, 1.f);
}

// ---------------- per-graph mean pool of xn = x + agg/max(deg,1) ----------------
__global__ void k_pool(const float* __restrict__ x) {
    int g = blockIdx.x, f = threadIdx.x;  // 128 threads
    float s = 0.f;
    for (int n = g*64; n < g*64 + 64; n++) {
        float inv = 1.f / fmaxf(g_deg[n], 1.f);
        s += x[(size_t)n*FEAT + f] + g_agg[(size_t)n*FEAT + f] * inv;
    }
    g_pooled[g*FEAT + f] = s * (1.f/64.f);
}

// ---------------- per-gene GEMM: X[g*64+b,h] = relu(pooled@gene_W[g]+gene_b[g]) ----------------
__global__ void __launch_bounds__(256) k_gene(const float* __restrict__ gW,
                                              const float* __restrict__ gb) {
    int g = blockIdx.x, h0 = blockIdx.y * 128;
    __shared__ float sp[128][68];   // pooled^T [f][b]
    __shared__ float sw[16][128];
    for (int i = threadIdx.x; i < 64*32; i += 256) {
        int b = i >> 5, fq = i & 31;
        float4 v = *(const float4*)(g_pooled + b*FEAT + fq*4);
        sp[fq*4+0][b] = v.x; sp[fq*4+1][b] = v.y;
        sp[fq*4+2][b] = v.z; sp[fq*4+3][b] = v.w;
    }
    float acc[4][8];
    #pragma unroll
    for (int i = 0; i < 4; i++)
        #pragma unroll
        for (int j = 0; j < 8; j++) acc[i][j] = 0.f;
    int tb = (threadIdx.x & 15) * 4;
    int th = (threadIdx.x >> 4) * 8;
    const float* W = gW + (size_t)g*FEAT*HID + h0;
    int lr = threadIdx.x >> 4, lc = (threadIdx.x & 15) * 8;
    __syncthreads();
    for (int k0 = 0; k0 < 128; k0 += 16) {
        *(float4*)&sw[lr][lc]   = *(const float4*)(W + (size_t)(k0+lr)*HID + lc);
        *(float4*)&sw[lr][lc+4] = *(const float4*)(W + (size_t)(k0+lr)*HID + lc + 4);
        __syncthreads();
        #pragma unroll
        for (int kk = 0; kk < 16; kk++) {
            float4 a  = *(float4*)&sp[k0+kk][tb];
            float4 b0 = *(float4*)&sw[kk][th];
            float4 b1 = *(float4*)&sw[kk][th+4];
            float av[4] = {a.x,a.y,a.z,a.w};
            float bv[8] = {b0.x,b0.y,b0.z,b0.w,b1.x,b1.y,b1.z,b1.w};
            #pragma unroll
            for (int i = 0; i < 4; i++)
                #pragma unroll
                for (int j = 0; j < 8; j++) acc[i][j] += av[i]*bv[j];
        }
        __syncthreads();
    }
    #pragma unroll
    for (int i = 0; i < 4; i++) {
        int row = g*64 + tb + i, col = h0 + th;
        float o[8];
        #pragma unroll
        for (int j = 0; j < 8; j++)
            o[j] = fmaxf(acc[i][j] + gb[(size_t)g*HID + col + j], 0.f);
        *(float4*)(g_X + (size_t)row*HID + col)     = make_float4(o[0],o[1],o[2],o[3]);
        *(float4*)(g_X + (size_t)row*HID + col + 4) = make_float4(o[4],o[5],o[6],o[7]);
    }
}

// ---------------- fused QKV SGEMM (128x128 tile, 8x8 micro) ----------------
__global__ void __launch_bounds__(256) k_qkv(
        const float* __restrict__ Wq, const float* __restrict__ bq,
        const float* __restrict__ Wk, const float* __restrict__ bk,
        const float* __restrict__ Wv, const float* __restrict__ bv) {
    int m0 = blockIdx.x * 128;
    int nt = blockIdx.y;                 // 0..11
    int wsel = nt >> 2, n0 = (nt & 3) * 128;
    const float* W    = (wsel == 0) ? Wq : (wsel == 1) ? Wk : Wv;
    const float* bias = (wsel == 0) ? bq : (wsel == 1) ? bk : bv;
    float* out        = (wsel == 0) ? g_Qm : (wsel == 1) ? g_Km : g_Vm;

    __shared__ float As[16][132];
    __shared__ float Bs[16][128];
    float acc[8][8];
    #pragma unroll
    for (int i = 0; i < 8; i++)
        #pragma unroll
        for (int j = 0; j < 8; j++) acc[i][j] = 0.f;

    int tx = threadIdx.x & 15, ty = threadIdx.x >> 4;
    int rr = threadIdx.x >> 2, kq = (threadIdx.x & 3) * 4;
    int br = threadIdx.x >> 4, bc = (threadIdx.x & 15) * 8;

    for (int k0 = 0; k0 < HID; k0 += 16) {
        #pragma unroll
        for (int p = 0; p < 2; p++) {
            int m = rr + p*64, grow = m0 + m;
            float4 v = make_float4(0.f,0.f,0.f,0.f);
            if (grow < NROWS) v = *(const float4*)(g_X + (size_t)grow*HID + k0 + kq);
            As[kq+0][m] = v.x; As[kq+1][m] = v.y;
            As[kq+2][m] = v.z; As[kq+3][m] = v.w;
        }
        *(float4*)&Bs[br][bc]   = *(const float4*)(W + (size_t)(k0+br)*HID + n0 + bc);
        *(float4*)&Bs[br][bc+4] = *(const float4*)(W + (size_t)(k0+br)*HID + n0 + bc + 4);
        __syncthreads();
        #pragma unroll
        for (int kk = 0; kk < 16; kk++) {
            float4 a0 = *(float4*)&As[kk][ty*4];
            float4 a1 = *(float4*)&As[kk][64 + ty*4];
            float4 b0 = *(float4*)&Bs[kk][tx*4];
            float4 b1 = *(float4*)&Bs[kk][64 + tx*4];
            float av[8]  = {a0.x,a0.y,a0.z,a0.w,a1.x,a1.y,a1.z,a1.w};
            float bv8[8] = {b0.x,b0.y,b0.z,b0.w,b1.x,b1.y,b1.z,b1.w};
            #pragma unroll
            for (int i = 0; i < 8; i++)
                #pragma unroll
                for (int j = 0; j < 8; j++) acc[i][j] += av[i]*bv8[j];
        }
        __syncthreads();
    }
    #pragma unroll
    for (int i = 0; i < 8; i++) {
        int mloc = (i < 4) ? (ty*4 + i) : (64 + ty*4 + i - 4);
        int m = m0 + mloc;
        if (m >= NROWS) continue;
        #pragma unroll
        for (int half = 0; half < 2; half++) {
            int nloc = half*64 + tx*4, jb = half*4;
            float4 v = make_float4(acc[i][jb+0] + bias[n0+nloc+0],
                                   acc[i][jb+1] + bias[n0+nloc+1],
                                   acc[i][jb+2] + bias[n0+nloc+2],
                                   acc[i][jb+3] + bias[n0+nloc+3]);
            *(float4*)(out + (size_t)m*HID + n0 + nloc) = v;
        }
    }
}

// ---------------- flash attention per (gene block, head); all rows valid ----------------
#define ATTN_SMEM (4*64*68*4)
__global__ void __launch_bounds__(256) k_attn(const int* __restrict__ cell_ids,
                                              const int* __restrict__ counts) {
    extern __shared__ float sm[];
    float (*Qs)[68] = (float(*)[68])sm;              // [d][q]
    float (*Ks)[68] = (float(*)[68])(sm + 64*68);    // [d][k]
    float (*Ps)[68] = (float(*)[68])(sm + 2*64*68);  // [q][k]
    float (*Vs)[68] = (float(*)[68])(sm + 3*64*68);  // [k][d]

    int g = blockIdx.x, h = blockIdx.y, tid = threadIdx.x;
    int c  = cell_ids[g];
    int nt = counts[c];
    int ks0 = g_cs[c];

    for (int i = tid; i < 4096; i += 256) {          // Q transposed stage
        int d = i & 63, q = i >> 6;
        Qs[d][q] = g_Qm[(size_t)(g*64 + q)*HID + h*DH + d];
    }
    int iq = tid >> 4, jg = tid & 15;
    float o[4][4];
    #pragma unroll
    for (int r = 0; r < 4; r++)
        #pragma unroll
        for (int j = 0; j < 4; j++) o[r][j] = 0.f;
    float mrow[4] = {-1e30f,-1e30f,-1e30f,-1e30f};
    float lrow[4] = {0.f,0.f,0.f,0.f};

    for (int kt = 0; kt < nt; kt++) {
        int kg = ks0 + kt;
        __syncthreads();   // prev PV done / Q staged
        for (int i = tid; i < 4096; i += 256) {
            int d = i & 63, r = i >> 6;
            Ks[d][r] = g_Km[(size_t)(kg*64 + r)*HID + h*DH + d];
        }
        for (int i = tid; i < 64*16; i += 256) {
            int r = i >> 4, dq = (i & 15) << 2;
            *(float4*)&Vs[r][dq] = *(const float4*)(g_Vm + (size_t)(kg*64 + r)*HID + h*DH + dq);
        }
        __syncthreads();
        float s[4][4];
        #pragma unroll
        for (int r = 0; r < 4; r++)
            #pragma unroll
            for (int j = 0; j < 4; j++) s[r][j] = 0.f;
        #pragma unroll 8
        for (int d = 0; d < 64; d++) {
            float4 a = *(float4*)&Qs[d][iq*4];
            float4 b = *(float4*)&Ks[d][jg*4];
            float av[4]  = {a.x,a.y,a.z,a.w};
            float bv4[4] = {b.x,b.y,b.z,b.w};
            #pragma unroll
            for (int r = 0; r < 4; r++)
                #pragma unroll
                for (int j = 0; j < 4; j++) s[r][j] += av[r]*bv4[j];
        }
        #pragma unroll
        for (int r = 0; r < 4; r++) {
            #pragma unroll
            for (int j = 0; j < 4; j++) s[r][j] *= 0.125f;
            float mt = fmaxf(fmaxf(s[r][0],s[r][1]), fmaxf(s[r][2],s[r][3]));
            #pragma unroll
            for (int off = 8; off > 0; off >>= 1)
                mt = fmaxf(mt, __shfl_xor_sync(0xffffffffu, mt, off, 16));
            float mnew  = fmaxf(mrow[r], mt);
            float alpha = __expf(mrow[r] - mnew);
            float p[4], lt = 0.f;
            #pragma unroll
            for (int j = 0; j < 4; j++) { p[j] = __expf(s[r][j]-mnew); lt += p[j]; }
            #pragma unroll
            for (int off = 8; off > 0; off >>= 1)
                lt += __shfl_xor_sync(0xffffffffu, lt, off, 16);
            lrow[r] = lrow[r]*alpha + lt;
            mrow[r] = mnew;
            #pragma unroll
            for (int j = 0; j < 4; j++) { o[r][j] *= alpha; Ps[iq*4+r][jg*4+j] = p[j]; }
        }
        __syncthreads();
        #pragma unroll 4
        for (int k0 = 0; k0 < 64; k0 += 4) {
            float4 pr[4], vv[4];
            #pragma unroll
            for (int r = 0; r < 4; r++) pr[r] = *(float4*)&Ps[iq*4+r][k0];
            #pragma unroll
            for (int kk = 0; kk < 4; kk++) vv[kk] = *(float4*)&Vs[k0+kk][jg*4];
            #pragma unroll
            for (int r = 0; r < 4; r++) {
                float pv[4] = {pr[r].x, pr[r].y, pr[r].z, pr[r].w};
                #pragma unroll
                for (int kk = 0; kk < 4; kk++) {
                    o[r][0] += pv[kk]*vv[kk].x; o[r][1] += pv[kk]*vv[kk].y;
                    o[r][2] += pv[kk]*vv[kk].z; o[r][3] += pv[kk]*vv[kk].w;
                }
            }
        }
    }
    #pragma unroll
    for (int r = 0; r < 4; r++) {
        float inv = 1.f / lrow[r];
        int row = g*64 + iq*4 + r;
        *(float4*)(g_att + (size_t)row*HID + h*DH + jg*4) =
            make_float4(o[r][0]*inv, o[r][1]*inv, o[r][2]*inv, o[r][3]*inv);
    }
}

// ---------------- per-cell mean of attention output (pre-Wo) ----------------
__global__ void k_csum() {
    int c = blockIdx.x;
    int hh = blockIdx.y * 128 + threadIdx.x;
    int r0 = g_cs[c] * 64;
    int S  = (g_cs[c+1] - g_cs[c]) * 64;
    float s0=0.f,s1=0.f,s2=0.f,s3=0.f;
    for (int r = 0; r < S; r += 4) {
        s0 += g_att[(size_t)(r0+r+0)*HID + hh];
        s1 += g_att[(size_t)(r0+r+1)*HID + hh];
        s2 += g_att[(size_t)(r0+r+2)*HID + hh];
        s3 += g_att[(size_t)(r0+r+3)*HID + hh];
    }
    g_csum[c*HID + hh] = ((s0+s1)+(s2+s3)) / (float)S;
}

// ---------------- per-cell vec-mat (shared weights) ----------------
template<int KDIM, int NCOL, int RELU, int SRC>
__global__ void k_vm(const float* __restrict__ W, const float* __restrict__ bias) {
    const float* vin  = (SRC == 0) ? g_csum  : (SRC == 1) ? g_meanh : g_h1;
    float*       vout = (SRC == 0) ? g_meanh : (SRC == 1) ? g_h1    : g_h2;
    int c = blockIdx.x;
    int n = blockIdx.y * 128 + threadIdx.x;
    __shared__ float a[KDIM];
    for (int k = threadIdx.x; k < KDIM; k += 128) a[k] = vin[c*KDIM + k];
    __syncthreads();
    float acc = bias[n];
    #pragma unroll 8
    for (int k = 0; k < KDIM; k++) acc += a[k] * W[(size_t)k*NCOL + n];
    vout[c*NCOL + n] = RELU ? fmaxf(acc, 0.f) : acc;
}

// ---------------- layernorm, write integrated ----------------
__global__ void k_ln(const float* __restrict__ lng, const float* __restrict__ lnb,
                     float* __restrict__ out) {
    int c = blockIdx.x, t = threadIdx.x;   // 256
    __shared__ float sh[34];
    float v0 = g_h2[c*HID + t], v1 = g_h2[c*HID + 256 + t];
    int lane = t & 31, w = t >> 5;
    float s = v0 + v1;
    #pragma unroll
    for (int off = 16; off; off >>= 1) s += __shfl_xor_sync(~0u, s, off);
    if (lane == 0) sh[w] = s;
    __syncthreads();
    if (w == 0) {
        float tot = (t < 8) ? sh[t] : 0.f;
        #pragma unroll
        for (int off = 4; off; off >>= 1) tot += __shfl_xor_sync(~0u, tot, off);
        if (t == 0) sh[32] = tot;
    }
    __syncthreads();
    float mu = sh[32] * (1.f/512.f);
    float d0 = v0 - mu, d1 = v1 - mu;
    float q = d0*d0 + d1*d1;
    #pragma unroll
    for (int off = 16; off; off >>= 1) q += __shfl_xor_sync(~0u, q, off);
    if (lane == 0) sh[w] = q;
    __syncthreads();
    if (w == 0) {
        float tot = (t < 8) ? sh[t] : 0.f;
        #pragma unroll
        for (int off = 4; off; off >>= 1) tot += __shfl_xor_sync(~0u, tot, off);
        if (t == 0) sh[33] = tot;
    }
    __syncthreads();
    float inv = rsqrtf(sh[33] * (1.f/512.f) + 1e-5f);
    float r0 = d0*inv*lng[t]     + lnb[t];
    float r1 = d1*inv*lng[256+t] + lnb[256+t];
    g_int[c*HID + t]       = r0;
    g_int[c*HID + 256 + t] = r1;
    out[64 + c*HID + t]       = r0;
    out[64 + c*HID + 256 + t] = r1;
}

// ---------------- per-cell affinity head ----------------
__global__ void k_aff(const float* __restrict__ Aw1, const float* __restrict__ Ab1,
                      const float* __restrict__ Aw2, const float* __restrict__ Ab2,
                      float* __restrict__ out) {
    int c = blockIdx.x, t = threadIdx.x;   // 256
    __shared__ float a[HID];
    __shared__ float red[8];
    a[t]       = g_int[c*HID + t];
    a[t + 256] = g_int[c*HID + 256 + t];
    __syncthreads();
    float part = 0.f;
    #pragma unroll
    for (int half = 0; half < 2; half++) {
        int k = t + half*256;
        float acc = Ab1[c*HID + k];
        const float* W = Aw1 + (size_t)c*HID*HID + k;
        #pragma unroll 8
        for (int j = 0; j < HID; j++) acc += a[j] * W[(size_t)j*HID];
        part += fmaxf(acc, 0.f) * Aw2[c*HID + k];
    }
    int lane = t & 31, w = t >> 5;
    #pragma unroll
    for (int off = 16; off; off >>= 1) part += __shfl_xor_sync(~0u, part, off);
    if (lane == 0) red[w] = part;
    __syncthreads();
    if (t == 0) {
        float s = 0.f;
        #pragma unroll
        for (int i = 0; i < 8; i++) s += red[i];
        out[c] = 1.f / (1.f + expf(-(s + Ab2[c])));
    }
}

extern "C" void kernel_launch(void* const* d_in, const int* in_sizes, int n_in,
                              void* d_out, int out_size) {
    const float* x       = (const float*)d_in[0];
    const int*   ei      = (const int*)  d_in[1];
    const float* gene_W  = (const float*)d_in[3];
    const float* gene_b  = (const float*)d_in[4];
    const int*   cell_ids= (const int*)  d_in[5];
    const int*   counts  = (const int*)  d_in[7];
    const float* Wq = (const float*)d_in[8],  *bq = (const float*)d_in[9];
    const float* Wk = (const float*)d_in[10], *bk = (const float*)d_in[11];
    const float* Wv = (const float*)d_in[12], *bv = (const float*)d_in[13];
    const float* Wo = (const float*)d_in[14], *bo = (const float*)d_in[15];
    const float* Wi1= (const float*)d_in[16], *bi1= (const float*)d_in[17];
    const float* Wi2= (const float*)d_in[18], *bi2= (const float*)d_in[19];
    const float* lng= (const float*)d_in[20], *lnb= (const float*)d_in[21];
    const float* Aw1= (const float*)d_in[22], *Ab1= (const float*)d_in[23];
    const float* Aw2= (const float*)d_in[24], *Ab2= (const float*)d_in[25];
    float* out = (float*)d_out;

    cudaFuncSetAttribute(k_attn, cudaFuncAttributeMaxDynamicSharedMemorySize, ATTN_SMEM);

    k_init <<<256, 256>>>(counts);
    k_edges<<<(NEDGES*32)/256, 256>>>(x, ei);
    k_pool <<<NB, 128>>>(x);
    k_gene <<<dim3(NG, 4), 256>>>(gene_W, gene_b);
    k_qkv  <<<dim3((NROWS+127)/128, 12), 256>>>(Wq, bq, Wk, bk, Wv, bv);
    k_attn <<<dim3(NG, 8), 256, ATTN_SMEM>>>(cell_ids, counts);
    k_csum <<<dim3(NC, 4), 128>>>();
    k_vm<512, 512, 0, 0><<<dim3(NC, 4), 128>>>(Wo,  bo);
    k_vm<512,1024, 1, 1><<<dim3(NC, 8), 128>>>(Wi1, bi1);
    k_vm<1024,512, 0, 2><<<dim3(NC, 4), 128>>>(Wi2, bi2);
    k_ln  <<<NC, 256>>>(lng, lnb, out);
    k_aff <<<NC, 256>>>(Aw1, Ab1, Aw2, Ab2, out);
}

// round 3
// speedup vs baseline: 1.0842x; 1.0842x over previous
#include <cuda_runtime.h>
#include <math.h>

#define NNODES 4096
#define FEAT   128
#define NEDGES 65536
#define NG     317
#define NB     64
#define NC     64
#define HID    512
#define DH     64
#define NROWS  (NG*NB)
#define FFD    1024

typedef unsigned long long u64;

__device__ __forceinline__ u64 pk2(float lo, float hi) {
    u64 r; asm("mov.b64 %0,{%1,%2};" : "=l"(r) : "f"(lo), "f"(hi)); return r;
}
__device__ __forceinline__ u64 dup2(float x) {
    u64 r; asm("mov.b64 %0,{%1,%1};" : "=l"(r) : "f"(x)); return r;
}
__device__ __forceinline__ u64 ffma2(u64 a, u64 b, u64 c) {
    u64 d; asm("fma.rn.f32x2 %0,%1,%2,%3;" : "=l"(d) : "l"(a), "l"(b), "l"(c)); return d;
}
__device__ __forceinline__ u64 fmul2(u64 a, u64 b) {
    u64 d; asm("mul.rn.f32x2 %0,%1,%2;" : "=l"(d) : "l"(a), "l"(b)); return d;
}
__device__ __forceinline__ float2 up2(u64 v) {
    float2 f; asm("mov.b64 {%0,%1},%2;" : "=f"(f.x), "=f"(f.y) : "l"(v)); return f;
}

__device__ float g_deg[NNODES];
__device__ float g_agg[NNODES*FEAT];
__device__ float g_pooled[NB*FEAT];
__device__ float g_X  [(size_t)NROWS*HID];
__device__ float g_Qm [(size_t)NROWS*HID];
__device__ float g_Km [(size_t)NROWS*HID];
__device__ float g_Vm [(size_t)NROWS*HID];
__device__ float g_att[(size_t)NROWS*HID];
__device__ float g_csum[NC*HID];
__device__ float g_meanh[NC*HID];
__device__ float g_h1[NC*FFD];
__device__ float g_h2[NC*HID];
__device__ float g_int[NC*HID];
__device__ int   g_cs[NC+1];

// ---------------- init: zero deg/agg, prefix-sum counts ----------------
__global__ void k_init(const int* __restrict__ counts) {
    int i = blockIdx.x * blockDim.x + threadIdx.x;
    int nt = gridDim.x * blockDim.x;
    if (i < NNODES) g_deg[i] = 0.f;
    for (int j = i; j < NNODES*FEAT; j += nt) g_agg[j] = 0.f;
    if (i == 0) {
        int s = 0;
        for (int c = 0; c < NC; c++) { g_cs[c] = s; s += counts[c]; }
        g_cs[NC] = s;
    }
}

// ---------------- edge aggregation (warp per edge) ----------------
__global__ void k_edges(const float* __restrict__ x, const int* __restrict__ ei) {
    int t = blockIdx.x * blockDim.x + threadIdx.x;
    int e = t >> 5, lane = t & 31;
    if (e >= NEDGES) return;
    int s = ei[e], d = ei[NEDGES + e];
    float4 v = *(const float4*)(x + (size_t)s*FEAT + lane*4);
    float* a = g_agg + (size_t)d*FEAT + lane*4;
    atomicAdd(a+0, v.x); atomicAdd(a+1, v.y);
    atomicAdd(a+2, v.z); atomicAdd(a+3, v.w);
    if (lane == 0) atomicAdd(g_deg + d, 1.f);
}

// ---------------- per-graph mean pool ----------------
__global__ void k_pool(const float* __restrict__ x) {
    int g = blockIdx.x, f = threadIdx.x;  // 128 threads
    float s = 0.f;
    for (int n = g*64; n < g*64 + 64; n++) {
        float inv = 1.f / fmaxf(g_deg[n], 1.f);
        s += x[(size_t)n*FEAT + f] + g_agg[(size_t)n*FEAT + f] * inv;
    }
    g_pooled[g*FEAT + f] = s * (1.f/64.f);
}

// ---------------- per-gene GEMM (f32x2) ----------------
__global__ void __launch_bounds__(256) k_gene(const float* __restrict__ gW,
                                              const float* __restrict__ gb) {
    int g = blockIdx.x, h0 = blockIdx.y * 128;
    __shared__ float sp[128][68];   // pooled^T [f][b]
    __shared__ float sw[16][128];
    for (int i = threadIdx.x; i < 64*32; i += 256) {
        int b = i >> 5, fq = i & 31;
        float4 v = *(const float4*)(g_pooled + b*FEAT + fq*4);
        sp[fq*4+0][b] = v.x; sp[fq*4+1][b] = v.y;
        sp[fq*4+2][b] = v.z; sp[fq*4+3][b] = v.w;
    }
    u64 acc2[4][4];
    #pragma unroll
    for (int i = 0; i < 4; i++)
        #pragma unroll
        for (int p = 0; p < 4; p++) acc2[i][p] = 0ull;
    int tb = (threadIdx.x & 15) * 4;
    int th = (threadIdx.x >> 4) * 8;
    const float* W = gW + (size_t)g*FEAT*HID + h0;
    int lr = threadIdx.x >> 4, lc = (threadIdx.x & 15) * 8;
    __syncthreads();
    for (int k0 = 0; k0 < 128; k0 += 16) {
        *(float4*)&sw[lr][lc]   = *(const float4*)(W + (size_t)(k0+lr)*HID + lc);
        *(float4*)&sw[lr][lc+4] = *(const float4*)(W + (size_t)(k0+lr)*HID + lc + 4);
        __syncthreads();
        #pragma unroll
        for (int kk = 0; kk < 16; kk++) {
            float4 a  = *(float4*)&sp[k0+kk][tb];
            u64 b2[4];
            b2[0] = *(u64*)&sw[kk][th];   b2[1] = *(u64*)&sw[kk][th+2];
            b2[2] = *(u64*)&sw[kk][th+4]; b2[3] = *(u64*)&sw[kk][th+6];
            float av[4] = {a.x,a.y,a.z,a.w};
            #pragma unroll
            for (int i = 0; i < 4; i++) {
                u64 ad = dup2(av[i]);
                #pragma unroll
                for (int p = 0; p < 4; p++) acc2[i][p] = ffma2(ad, b2[p], acc2[i][p]);
            }
        }
        __syncthreads();
    }
    #pragma unroll
    for (int i = 0; i < 4; i++) {
        int row = g*64 + tb + i, col = h0 + th;
        float2 f0 = up2(acc2[i][0]), f1 = up2(acc2[i][1]);
        float2 f2 = up2(acc2[i][2]), f3 = up2(acc2[i][3]);
        const float* B = gb + (size_t)g*HID + col;
        *(float4*)(g_X + (size_t)row*HID + col) =
            make_float4(fmaxf(f0.x+B[0],0.f), fmaxf(f0.y+B[1],0.f),
                        fmaxf(f1.x+B[2],0.f), fmaxf(f1.y+B[3],0.f));
        *(float4*)(g_X + (size_t)row*HID + col + 4) =
            make_float4(fmaxf(f2.x+B[4],0.f), fmaxf(f2.y+B[5],0.f),
                        fmaxf(f3.x+B[6],0.f), fmaxf(f3.y+B[7],0.f));
    }
}

// ---------------- fused QKV SGEMM (128x128 tile, 8x8 micro, f32x2) ----------------
__global__ void __launch_bounds__(256) k_qkv(
        const float* __restrict__ Wq, const float* __restrict__ bq,
        const float* __restrict__ Wk, const float* __restrict__ bk,
        const float* __restrict__ Wv, const float* __restrict__ bv) {
    int m0 = blockIdx.x * 128;
    int nt = blockIdx.y;                 // 0..11
    int wsel = nt >> 2, n0 = (nt & 3) * 128;
    const float* W    = (wsel == 0) ? Wq : (wsel == 1) ? Wk : Wv;
    const float* bias = (wsel == 0) ? bq : (wsel == 1) ? bk : bv;
    float* out        = (wsel == 0) ? g_Qm : (wsel == 1) ? g_Km : g_Vm;

    __shared__ float As[16][132];
    __shared__ float Bs[16][128];
    u64 acc2[8][4];
    #pragma unroll
    for (int i = 0; i < 8; i++)
        #pragma unroll
        for (int p = 0; p < 4; p++) acc2[i][p] = 0ull;

    int tx = threadIdx.x & 15, ty = threadIdx.x >> 4;
    int rr = threadIdx.x >> 2, kq = (threadIdx.x & 3) * 4;
    int br = threadIdx.x >> 4, bc = (threadIdx.x & 15) * 8;

    for (int k0 = 0; k0 < HID; k0 += 16) {
        #pragma unroll
        for (int p = 0; p < 2; p++) {
            int m = rr + p*64, grow = m0 + m;
            float4 v = make_float4(0.f,0.f,0.f,0.f);
            if (grow < NROWS) v = *(const float4*)(g_X + (size_t)grow*HID + k0 + kq);
            As[kq+0][m] = v.x; As[kq+1][m] = v.y;
            As[kq+2][m] = v.z; As[kq+3][m] = v.w;
        }
        *(float4*)&Bs[br][bc]   = *(const float4*)(W + (size_t)(k0+br)*HID + n0 + bc);
        *(float4*)&Bs[br][bc+4] = *(const float4*)(W + (size_t)(k0+br)*HID + n0 + bc + 4);
        __syncthreads();
        #pragma unroll
        for (int kk = 0; kk < 16; kk++) {
            float4 a0 = *(float4*)&As[kk][ty*4];
            float4 a1 = *(float4*)&As[kk][64 + ty*4];
            u64 b2[4];
            b2[0] = *(u64*)&Bs[kk][tx*4];      b2[1] = *(u64*)&Bs[kk][tx*4+2];
            b2[2] = *(u64*)&Bs[kk][64+tx*4];   b2[3] = *(u64*)&Bs[kk][64+tx*4+2];
            float av[8] = {a0.x,a0.y,a0.z,a0.w,a1.x,a1.y,a1.z,a1.w};
            #pragma unroll
            for (int i = 0; i < 8; i++) {
                u64 ad = dup2(av[i]);
                #pragma unroll
                for (int p = 0; p < 4; p++) acc2[i][p] = ffma2(ad, b2[p], acc2[i][p]);
            }
        }
        __syncthreads();
    }
    #pragma unroll
    for (int i = 0; i < 8; i++) {
        int mloc = (i < 4) ? (ty*4 + i) : (64 + ty*4 + i - 4);
        int m = m0 + mloc;
        if (m >= NROWS) continue;
        #pragma unroll
        for (int half = 0; half < 2; half++) {
            int nloc = half*64 + tx*4;
            float2 lo = up2(acc2[i][2*half]), hi = up2(acc2[i][2*half+1]);
            float4 v = make_float4(lo.x + bias[n0+nloc+0], lo.y + bias[n0+nloc+1],
                                   hi.x + bias[n0+nloc+2], hi.y + bias[n0+nloc+3]);
            *(float4*)(out + (size_t)m*HID + n0 + nloc) = v;
        }
    }
}

// ---------------- flash attention per (gene block, head), f32x2 ----------------
#define ATTN_SMEM (4*64*68*4)
__global__ void __launch_bounds__(256) k_attn(const int* __restrict__ cell_ids,
                                              const int* __restrict__ counts) {
    extern __shared__ float sm[];
    float (*Qs)[68] = (float(*)[68])sm;              // [d][q]
    float (*Ks)[68] = (float(*)[68])(sm + 64*68);    // [d][k]
    float (*Ps)[68] = (float(*)[68])(sm + 2*64*68);  // [q][k]
    float (*Vs)[68] = (float(*)[68])(sm + 3*64*68);  // [k][d]

    int g = blockIdx.x, h = blockIdx.y, tid = threadIdx.x;
    int c  = cell_ids[g];
    int nt = counts[c];
    int ks0 = g_cs[c];

    for (int i = tid; i < 4096; i += 256) {
        int d = i & 63, q = i >> 6;
        Qs[d][q] = g_Qm[(size_t)(g*64 + q)*HID + h*DH + d];
    }
    int iq = tid >> 4, jg = tid & 15;
    u64 o2[4][2];
    #pragma unroll
    for (int r = 0; r < 4; r++) { o2[r][0] = 0ull; o2[r][1] = 0ull; }
    float mrow[4] = {-1e30f,-1e30f,-1e30f,-1e30f};
    float lrow[4] = {0.f,0.f,0.f,0.f};

    for (int kt = 0; kt < nt; kt++) {
        int kg = ks0 + kt;
        __syncthreads();
        for (int i = tid; i < 4096; i += 256) {
            int d = i & 63, r = i >> 6;
            Ks[d][r] = g_Km[(size_t)(kg*64 + r)*HID + h*DH + d];
        }
        for (int i = tid; i < 64*16; i += 256) {
            int r = i >> 4, dq = (i & 15) << 2;
            *(float4*)&Vs[r][dq] = *(const float4*)(g_Vm + (size_t)(kg*64 + r)*HID + h*DH + dq);
        }
        __syncthreads();
        u64 s2[4][2];
        #pragma unroll
        for (int r = 0; r < 4; r++) { s2[r][0] = 0ull; s2[r][1] = 0ull; }
        #pragma unroll 8
        for (int d = 0; d < 64; d++) {
            float4 a = *(float4*)&Qs[d][iq*4];
            u64 b0 = *(u64*)&Ks[d][jg*4];
            u64 b1 = *(u64*)&Ks[d][jg*4+2];
            float av[4] = {a.x,a.y,a.z,a.w};
            #pragma unroll
            for (int r = 0; r < 4; r++) {
                u64 ad = dup2(av[r]);
                s2[r][0] = ffma2(ad, b0, s2[r][0]);
                s2[r][1] = ffma2(ad, b1, s2[r][1]);
            }
        }
        #pragma unroll
        for (int r = 0; r < 4; r++) {
            float2 sa = up2(s2[r][0]), sb = up2(s2[r][1]);
            float s0 = sa.x*0.125f, s1 = sa.y*0.125f;
            float ss2 = sb.x*0.125f, s3 = sb.y*0.125f;
            float mt = fmaxf(fmaxf(s0,s1), fmaxf(ss2,s3));
            #pragma unroll
            for (int off = 8; off > 0; off >>= 1)
                mt = fmaxf(mt, __shfl_xor_sync(0xffffffffu, mt, off, 16));
            float mnew  = fmaxf(mrow[r], mt);
            float alpha = __expf(mrow[r] - mnew);
            float p0 = __expf(s0-mnew), p1 = __expf(s1-mnew);
            float p2 = __expf(ss2-mnew), p3 = __expf(s3-mnew);
            float lt = (p0+p1)+(p2+p3);
            #pragma unroll
            for (int off = 8; off > 0; off >>= 1)
                lt += __shfl_xor_sync(0xffffffffu, lt, off, 16);
            lrow[r] = lrow[r]*alpha + lt;
            mrow[r] = mnew;
            u64 ad = dup2(alpha);
            o2[r][0] = fmul2(o2[r][0], ad);
            o2[r][1] = fmul2(o2[r][1], ad);
            Ps[iq*4+r][jg*4+0] = p0; Ps[iq*4+r][jg*4+1] = p1;
            Ps[iq*4+r][jg*4+2] = p2; Ps[iq*4+r][jg*4+3] = p3;
        }
        __syncthreads();
        #pragma unroll 4
        for (int k0 = 0; k0 < 64; k0 += 4) {
            float4 pr[4];
            u64 vv0[4], vv1[4];
            #pragma unroll
            for (int r = 0; r < 4; r++) pr[r] = *(float4*)&Ps[iq*4+r][k0];
            #pragma unroll
            for (int kk = 0; kk < 4; kk++) {
                vv0[kk] = *(u64*)&Vs[k0+kk][jg*4];
                vv1[kk] = *(u64*)&Vs[k0+kk][jg*4+2];
            }
            #pragma unroll
            for (int r = 0; r < 4; r++) {
                float pv[4] = {pr[r].x, pr[r].y, pr[r].z, pr[r].w};
                #pragma unroll
                for (int kk = 0; kk < 4; kk++) {
                    u64 pd = dup2(pv[kk]);
                    o2[r][0] = ffma2(pd, vv0[kk], o2[r][0]);
                    o2[r][1] = ffma2(pd, vv1[kk], o2[r][1]);
                }
            }
        }
    }
    #pragma unroll
    for (int r = 0; r < 4; r++) {
        float inv = 1.f / lrow[r];
        int row = g*64 + iq*4 + r;
        float2 f0 = up2(o2[r][0]), f1 = up2(o2[r][1]);
        *(float4*)(g_att + (size_t)row*HID + h*DH + jg*4) =
            make_float4(f0.x*inv, f0.y*inv, f1.x*inv, f1.y*inv);
    }
}

// ---------------- per-cell mean of attention output (pre-Wo) ----------------
__global__ void k_csum() {
    int c = blockIdx.x;
    int hh = blockIdx.y * 128 + threadIdx.x;
    int r0 = g_cs[c] * 64;
    int S  = (g_cs[c+1] - g_cs[c]) * 64;
    float s0=0.f,s1=0.f,s2=0.f,s3=0.f;
    for (int r = 0; r < S; r += 4) {
        s0 += g_att[(size_t)(r0+r+0)*HID + hh];
        s1 += g_att[(size_t)(r0+r+1)*HID + hh];
        s2 += g_att[(size_t)(r0+r+2)*HID + hh];
        s3 += g_att[(size_t)(r0+r+3)*HID + hh];
    }
    g_csum[c*HID + hh] = ((s0+s1)+(s2+s3)) / (float)S;
}

// ---------------- per-cell vec-mat (shared weights) ----------------
template<int KDIM, int NCOL, int RELU, int SRC>
__global__ void k_vm(const float* __restrict__ W, const float* __restrict__ bias) {
    const float* vin  = (SRC == 0) ? g_csum  : (SRC == 1) ? g_meanh : g_h1;
    float*       vout = (SRC == 0) ? g_meanh : (SRC == 1) ? g_h1    : g_h2;
    int c = blockIdx.x;
    int n = blockIdx.y * 128 + threadIdx.x;
    __shared__ float a[KDIM];
    for (int k = threadIdx.x; k < KDIM; k += 128) a[k] = vin[c*KDIM + k];
    __syncthreads();
    float acc = bias[n];
    #pragma unroll 8
    for (int k = 0; k < KDIM; k++) acc += a[k] * W[(size_t)k*NCOL + n];
    vout[c*NCOL + n] = RELU ? fmaxf(acc, 0.f) : acc;
}

// ---------------- layernorm, write integrated ----------------
__global__ void k_ln(const float* __restrict__ lng, const float* __restrict__ lnb,
                     float* __restrict__ out) {
    int c = blockIdx.x, t = threadIdx.x;   // 256
    __shared__ float sh[34];
    float v0 = g_h2[c*HID + t], v1 = g_h2[c*HID + 256 + t];
    int lane = t & 31, w = t >> 5;
    float s = v0 + v1;
    #pragma unroll
    for (int off = 16; off; off >>= 1) s += __shfl_xor_sync(~0u, s, off);
    if (lane == 0) sh[w] = s;
    __syncthreads();
    if (w == 0) {
        float tot = (t < 8) ? sh[t] : 0.f;
        #pragma unroll
        for (int off = 4; off; off >>= 1) tot += __shfl_xor_sync(~0u, tot, off);
        if (t == 0) sh[32] = tot;
    }
    __syncthreads();
    float mu = sh[32] * (1.f/512.f);
    float d0 = v0 - mu, d1 = v1 - mu;
    float q = d0*d0 + d1*d1;
    #pragma unroll
    for (int off = 16; off; off >>= 1) q += __shfl_xor_sync(~0u, q, off);
    if (lane == 0) sh[w] = q;
    __syncthreads();
    if (w == 0) {
        float tot = (t < 8) ? sh[t] : 0.f;
        #pragma unroll
        for (int off = 4; off; off >>= 1) tot += __shfl_xor_sync(~0u, tot, off);
        if (t == 0) sh[33] = tot;
    }
    __syncthreads();
    float inv = rsqrtf(sh[33] * (1.f/512.f) + 1e-5f);
    float r0 = d0*inv*lng[t]     + lnb[t];
    float r1 = d1*inv*lng[256+t] + lnb[256+t];
    g_int[c*HID + t]       = r0;
    g_int[c*HID + 256 + t] = r1;
    out[64 + c*HID + t]       = r0;
    out[64 + c*HID + 256 + t] = r1;
}

// ---------------- per-cell affinity head ----------------
__global__ void k_aff(const float* __restrict__ Aw1, const float* __restrict__ Ab1,
                      const float* __restrict__ Aw2, const float* __restrict__ Ab2,
                      float* __restrict__ out) {
    int c = blockIdx.x, t = threadIdx.x;   // 256
    __shared__ float a[HID];
    __shared__ float red[8];
    a[t]       = g_int[c*HID + t];
    a[t + 256] = g_int[c*HID + 256 + t];
    __syncthreads();
    float part = 0.f;
    #pragma unroll
    for (int half = 0; half < 2; half++) {
        int k = t + half*256;
        float acc = Ab1[c*HID + k];
        const float* W = Aw1 + (size_t)c*HID*HID + k;
        #pragma unroll 8
        for (int j = 0; j < HID; j++) acc += a[j] * W[(size_t)j*HID];
        part += fmaxf(acc, 0.f) * Aw2[c*HID + k];
    }
    int lane = t & 31, w = t >> 5;
    #pragma unroll
    for (int off = 16; off; off >>= 1) part += __shfl_xor_sync(~0u, part, off);
    if (lane == 0) red[w] = part;
    __syncthreads();
    if (t == 0) {
        float s = 0.f;
        #pragma unroll
        for (int i = 0; i < 8; i++) s += red[i];
        out[c] = 1.f / (1.f + expf(-(s + Ab2[c])));
    }
}

extern "C" void kernel_launch(void* const* d_in, const int* in_sizes, int n_in,
                              void* d_out, int out_size) {
    const float* x       = (const float*)d_in[0];
    const int*   ei      = (const int*)  d_in[1];
    const float* gene_W  = (const float*)d_in[3];
    const float* gene_b  = (const float*)d_in[4];
    const int*   cell_ids= (const int*)  d_in[5];
    const int*   counts  = (const int*)  d_in[7];
    const float* Wq = (const float*)d_in[8],  *bq = (const float*)d_in[9];
    const float* Wk = (const float*)d_in[10], *bk = (const float*)d_in[11];
    const float* Wv = (const float*)d_in[12], *bv = (const float*)d_in[13];
    const float* Wo = (const float*)d_in[14], *bo = (const float*)d_in[15];
    const float* Wi1= (const float*)d_in[16], *bi1= (const float*)d_in[17];
    const float* Wi2= (const float*)d_in[18], *bi2= (const float*)d_in[19];
    const float* lng= (const float*)d_in[20], *lnb= (const float*)d_in[21];
    const float* Aw1= (const float*)d_in[22], *Ab1= (const float*)d_in[23];
    const float* Aw2= (const float*)d_in[24], *Ab2= (const float*)d_in[25];
    float* out = (float*)d_out;

    cudaFuncSetAttribute(k_attn, cudaFuncAttributeMaxDynamicSharedMemorySize, ATTN_SMEM);

    k_init <<<256, 256>>>(counts);
    k_edges<<<(NEDGES*32)/256, 256>>>(x, ei);
    k_pool <<<NB, 128>>>(x);
    k_gene <<<dim3(NG, 4), 256>>>(gene_W, gene_b);
    k_qkv  <<<dim3((NROWS+127)/128, 12), 256>>>(Wq, bq, Wk, bk, Wv, bv);
    k_attn <<<dim3(NG, 8), 256, ATTN_SMEM>>>(cell_ids, counts);
    k_csum <<<dim3(NC, 4), 128>>>();
    k_vm<512, 512, 0, 0><<<dim3(NC, 4), 128>>>(Wo,  bo);
    k_vm<512,1024, 1, 1><<<dim3(NC, 8), 128>>>(Wi1, bi1);
    k_vm<1024,512, 0, 2><<<dim3(NC, 4), 128>>>(Wi2, bi2);
    k_ln  <<<NC, 256>>>(lng, lnb, out);
    k_aff <<<NC, 256>>>(Aw1, Ab1, Aw2, Ab2, out);
}

// round 5
// speedup vs baseline: 1.3697x; 1.2633x over previous
#include <cuda_runtime.h>
#include <cuda_bf16.h>
#include <math.h>
#include <cstdint>

#define NNODES 4096
#define FEAT   128
#define NEDGES 65536
#define NG     317
#define NB     64
#define NC     64
#define HID    512
#define DH     64
#define NROWS  (NG*NB)
#define FFD    1024
#define MTILES 159
#define PADROWS (MTILES*128)

typedef unsigned long long u64;

// ---------------- f32x2 helpers ----------------
__device__ __forceinline__ u64 dup2(float x) {
    u64 r; asm("mov.b64 %0,{%1,%1};" : "=l"(r) : "f"(x)); return r;
}
__device__ __forceinline__ u64 ffma2(u64 a, u64 b, u64 c) {
    u64 d; asm("fma.rn.f32x2 %0,%1,%2,%3;" : "=l"(d) : "l"(a), "l"(b), "l"(c)); return d;
}
__device__ __forceinline__ u64 fmul2(u64 a, u64 b) {
    u64 d; asm("mul.rn.f32x2 %0,%1,%2;" : "=l"(d) : "l"(a), "l"(b)); return d;
}
__device__ __forceinline__ float2 up2(u64 v) {
    float2 f; asm("mov.b64 {%0,%1},%2;" : "=f"(f.x), "=f"(f.y) : "l"(v)); return f;
}

// ---------------- mma.sync helpers (baseline PTX, compiles for compute_103) ----
__device__ __forceinline__ uint32_t smem_u32(const void* p) {
    uint32_t a; asm("{ .reg .u64 t; cvta.to.shared.u64 t, %1; cvt.u32.u64 %0, t; }"
                    : "=r"(a) : "l"(p)); return a;
}
__device__ __forceinline__ void ldsm_x4(uint32_t* r, uint32_t addr) {
    asm volatile("ldmatrix.sync.aligned.m8n8.x4.shared.b16 {%0,%1,%2,%3}, [%4];"
        : "=r"(r[0]), "=r"(r[1]), "=r"(r[2]), "=r"(r[3]) : "r"(addr));
}
__device__ __forceinline__ void mma16816(float* d, const uint32_t* a, const uint32_t* b) {
    asm volatile("mma.sync.aligned.m16n8k16.row.col.f32.bf16.bf16.f32 "
        "{%0,%1,%2,%3}, {%4,%5,%6,%7}, {%8,%9}, {%0,%1,%2,%3};"
        : "+f"(d[0]), "+f"(d[1]), "+f"(d[2]), "+f"(d[3])
        : "r"(a[0]), "r"(a[1]), "r"(a[2]), "r"(a[3]), "r"(b[0]), "r"(b[1]));
}

// ---------------- scratch ----------------
__device__ float g_deg[NNODES];
__device__ float g_agg[NNODES*FEAT];
__device__ float g_pooled[NB*FEAT];
__device__ float g_X  [(size_t)NROWS*HID];
__device__ float g_Qm [(size_t)NROWS*HID];
__device__ float g_Km [(size_t)NROWS*HID];
__device__ float g_Vm [(size_t)NROWS*HID];
__device__ float g_att[(size_t)NROWS*HID];
__device__ float g_csum[NC*HID];
__device__ float g_meanh[NC*HID];
__device__ float g_h1[NC*FFD];
__device__ float g_h2[NC*HID];
__device__ float g_int[NC*HID];
__device__ int   g_cs[NC+1];
__device__ __nv_bfloat16 g_Xhi[(size_t)PADROWS*HID];
__device__ __nv_bfloat16 g_Xlo[(size_t)PADROWS*HID];
__device__ __nv_bfloat16 g_Wthi[3*HID*HID];   // [w][n][k] (transposed)
__device__ __nv_bfloat16 g_Wtlo[3*HID*HID];

// ---------------- init ----------------
__global__ void k_init(const int* __restrict__ counts) {
    int i = blockIdx.x * blockDim.x + threadIdx.x;
    int nt = gridDim.x * blockDim.x;
    if (i < NNODES) g_deg[i] = 0.f;
    for (int j = i; j < NNODES*FEAT; j += nt) g_agg[j] = 0.f;
    if (i == 0) {
        int s = 0;
        for (int c = 0; c < NC; c++) { g_cs[c] = s; s += counts[c]; }
        g_cs[NC] = s;
    }
}

// ---------------- edge aggregation ----------------
__global__ void k_edges(const float* __restrict__ x, const int* __restrict__ ei) {
    int t = blockIdx.x * blockDim.x + threadIdx.x;
    int e = t >> 5, lane = t & 31;
    if (e >= NEDGES) return;
    int s = ei[e], d = ei[NEDGES + e];
    float4 v = *(const float4*)(x + (size_t)s*FEAT + lane*4);
    float* a = g_agg + (size_t)d*FEAT + lane*4;
    atomicAdd(a+0, v.x); atomicAdd(a+1, v.y);
    atomicAdd(a+2, v.z); atomicAdd(a+3, v.w);
    if (lane == 0) atomicAdd(g_deg + d, 1.f);
}

// ---------------- per-graph mean pool ----------------
__global__ void k_pool(const float* __restrict__ x) {
    int g = blockIdx.x, f = threadIdx.x;
    float s = 0.f;
    for (int n = g*64; n < g*64 + 64; n++) {
        float inv = 1.f / fmaxf(g_deg[n], 1.f);
        s += x[(size_t)n*FEAT + f] + g_agg[(size_t)n*FEAT + f] * inv;
    }
    g_pooled[g*FEAT + f] = s * (1.f/64.f);
}

// ---------------- per-gene GEMM (f32x2) ----------------
__global__ void __launch_bounds__(256) k_gene(const float* __restrict__ gW,
                                              const float* __restrict__ gb) {
    int g = blockIdx.x, h0 = blockIdx.y * 128;
    __shared__ float sp[128][68];
    __shared__ float sw[16][128];
    for (int i = threadIdx.x; i < 64*32; i += 256) {
        int b = i >> 5, fq = i & 31;
        float4 v = *(const float4*)(g_pooled + b*FEAT + fq*4);
        sp[fq*4+0][b] = v.x; sp[fq*4+1][b] = v.y;
        sp[fq*4+2][b] = v.z; sp[fq*4+3][b] = v.w;
    }
    u64 acc2[4][4];
    #pragma unroll
    for (int i = 0; i < 4; i++)
        #pragma unroll
        for (int p = 0; p < 4; p++) acc2[i][p] = 0ull;
    int tb = (threadIdx.x & 15) * 4;
    int th = (threadIdx.x >> 4) * 8;
    const float* W = gW + (size_t)g*FEAT*HID + h0;
    int lr = threadIdx.x >> 4, lc = (threadIdx.x & 15) * 8;
    __syncthreads();
    for (int k0 = 0; k0 < 128; k0 += 16) {
        *(float4*)&sw[lr][lc]   = *(const float4*)(W + (size_t)(k0+lr)*HID + lc);
        *(float4*)&sw[lr][lc+4] = *(const float4*)(W + (size_t)(k0+lr)*HID + lc + 4);
        __syncthreads();
        #pragma unroll
        for (int kk = 0; kk < 16; kk++) {
            float4 a  = *(float4*)&sp[k0+kk][tb];
            u64 b2[4];
            b2[0] = *(u64*)&sw[kk][th];   b2[1] = *(u64*)&sw[kk][th+2];
            b2[2] = *(u64*)&sw[kk][th+4]; b2[3] = *(u64*)&sw[kk][th+6];
            float av[4] = {a.x,a.y,a.z,a.w};
            #pragma unroll
            for (int i = 0; i < 4; i++) {
                u64 ad = dup2(av[i]);
                #pragma unroll
                for (int p = 0; p < 4; p++) acc2[i][p] = ffma2(ad, b2[p], acc2[i][p]);
            }
        }
        __syncthreads();
    }
    #pragma unroll
    for (int i = 0; i < 4; i++) {
        int row = g*64 + tb + i, col = h0 + th;
        float2 f0 = up2(acc2[i][0]), f1 = up2(acc2[i][1]);
        float2 f2 = up2(acc2[i][2]), f3 = up2(acc2[i][3]);
        const float* B = gb + (size_t)g*HID + col;
        *(float4*)(g_X + (size_t)row*HID + col) =
            make_float4(fmaxf(f0.x+B[0],0.f), fmaxf(f0.y+B[1],0.f),
                        fmaxf(f1.x+B[2],0.f), fmaxf(f1.y+B[3],0.f));
        *(float4*)(g_X + (size_t)row*HID + col + 4) =
            make_float4(fmaxf(f2.x+B[4],0.f), fmaxf(f2.y+B[5],0.f),
                        fmaxf(f3.x+B[6],0.f), fmaxf(f3.y+B[7],0.f));
    }
}

// ---------------- convert X -> bf16 hi/lo (padded) ----------------
__global__ void k_cvtX() {
    size_t i = ((size_t)blockIdx.x * 256 + threadIdx.x) * 4;
    if (i >= (size_t)PADROWS*HID) return;
    float4 v = make_float4(0.f,0.f,0.f,0.f);
    if (i < (size_t)NROWS*HID) v = *(const float4*)(g_X + i);
    float vv[4] = {v.x, v.y, v.z, v.w};
    #pragma unroll
    for (int j = 0; j < 4; j++) {
        __nv_bfloat16 h = __float2bfloat16(vv[j]);
        g_Xhi[i+j] = h;
        g_Xlo[i+j] = __float2bfloat16(vv[j] - __bfloat162float(h));
    }
}

// ---------------- transpose+convert W -> bf16 hi/lo [n][k] ----------------
__global__ void k_cvtW(const float* __restrict__ Wq, const float* __restrict__ Wk,
                       const float* __restrict__ Wv) {
    __shared__ float tile[32][33];
    int w = blockIdx.x;
    const float* W = (w == 0) ? Wq : (w == 1) ? Wk : Wv;
    int kb = blockIdx.y * 32, nb = blockIdx.z * 32;
    #pragma unroll
    for (int i = 0; i < 4; i++)
        tile[threadIdx.y + i*8][threadIdx.x] =
            W[(size_t)(kb + threadIdx.y + i*8)*HID + nb + threadIdx.x];
    __syncthreads();
    #pragma unroll
    for (int i = 0; i < 4; i++) {
        int n = nb + threadIdx.y + i*8, k = kb + threadIdx.x;
        float v = tile[threadIdx.x][threadIdx.y + i*8];
        __nv_bfloat16 h = __float2bfloat16(v);
        size_t o = (size_t)w*HID*HID + (size_t)n*HID + k;
        g_Wthi[o] = h;
        g_Wtlo[o] = __float2bfloat16(v - __bfloat162float(h));
    }
}

// ---------------- QKV GEMM via mma.sync bf16 (compensated hi/lo) ----------------
// CTA: 128 (m) x 64 (n), 8 warps each 32x64. K chunked by 64.
// smem layout (16B chunks, XOR swizzle on chunk index by row&7):
#define AHI 0
#define ALO 16384
#define BHI 32768
#define BLO 40960
#define QKV_SMEM 49152

__global__ void __launch_bounds__(256) k_qkv_mma(
        const float* __restrict__ bq, const float* __restrict__ bk,
        const float* __restrict__ bv) {
    extern __shared__ char smem[];
    uint32_t sb = smem_u32(smem);
    int tid = threadIdx.x;
    int wid = tid >> 5, lane = tid & 31;
    int m0 = blockIdx.x * 128;
    int nt = blockIdx.y;                 // 0..23
    int wsel = nt >> 3, n0 = (nt & 7) * 64;
    const float* bias = (wsel == 0) ? bq : (wsel == 1) ? bk : bv;
    float* out        = (wsel == 0) ? g_Qm : (wsel == 1) ? g_Km : g_Vm;
    const __nv_bfloat16* Bh = g_Wthi + (size_t)wsel*HID*HID;
    const __nv_bfloat16* Bl = g_Wtlo + (size_t)wsel*HID*HID;

    int wr = wid & 3, wc = wid >> 2;     // warp tile: rows wr*32..+31, cols wc*32..+31 -> wait
    // 8 warps: 4 row-groups x 2 col-groups; warp tile 32 rows x 32 cols covers 128x64. ✓

    float acc[2][4][4];
    #pragma unroll
    for (int a = 0; a < 2; a++)
        #pragma unroll
        for (int b = 0; b < 4; b++)
            #pragma unroll
            for (int c = 0; c < 4; c++) acc[a][b][c] = 0.f;

    for (int ch = 0; ch < 8; ch++) {
        int k0 = ch * 64;
        __syncthreads();
        // stage A (128 rows x 8 chunks), hi+lo
        for (int u = tid; u < 1024; u += 256) {
            int row = u >> 3, c = u & 7;
            uint32_t dst = (uint32_t)(((row << 3) | (c ^ (row & 7))) << 4);
            size_t go = (size_t)(m0 + row)*HID + k0 + c*8;
            *(uint4*)(smem + AHI + dst) = *(const uint4*)(g_Xhi + go);
            *(uint4*)(smem + ALO + dst) = *(const uint4*)(g_Xlo + go);
        }
        // stage B (64 rows x 8 chunks), hi+lo
        for (int u = tid; u < 512; u += 256) {
            int row = u >> 3, c = u & 7;
            uint32_t dst = (uint32_t)(((row << 3) | (c ^ (row & 7))) << 4);
            size_t go = (size_t)(n0 + row)*HID + k0 + c*8;
            *(uint4*)(smem + BHI + dst) = *(const uint4*)(Bh + go);
            *(uint4*)(smem + BLO + dst) = *(const uint4*)(Bl + go);
        }
        __syncthreads();
        #pragma unroll
        for (int s = 0; s < 4; s++) {
            // A fragments: 2 m16 tiles, hi+lo
            uint32_t ah[2][4], al[2][4];
            {
                int arow = wr*32 + (lane & 15);
                int ac   = s*2 + (lane >> 4);
                #pragma unroll
                for (int mt = 0; mt < 2; mt++) {
                    int r = arow + mt*16;
                    uint32_t off = (uint32_t)(((r << 3) | (ac ^ (r & 7))) << 4);
                    ldsm_x4(ah[mt], sb + AHI + off);
                    ldsm_x4(al[mt], sb + ALO + off);
                }
            }
            // B fragments: 4 n8 tiles via 2 x4 loads, hi+lo
            uint32_t bh[2][4], bl[2][4];
            {
                int brow = wc*32 + (lane & 7) + ((lane >> 4) << 3);
                int bc   = s*2 + ((lane >> 3) & 1);
                #pragma unroll
                for (int bt = 0; bt < 2; bt++) {
                    int r = brow + bt*16;
                    uint32_t off = (uint32_t)(((r << 3) | (bc ^ (r & 7))) << 4);
                    ldsm_x4(bh[bt], sb + BHI + off);
                    ldsm_x4(bl[bt], sb + BLO + off);
                }
            }
            #pragma unroll
            for (int mt = 0; mt < 2; mt++)
                #pragma unroll
                for (int n8 = 0; n8 < 4; n8++) {
                    const uint32_t* B0 = &bh[n8 >> 1][(n8 & 1) * 2];
                    const uint32_t* L0 = &bl[n8 >> 1][(n8 & 1) * 2];
                    mma16816(acc[mt][n8], ah[mt], B0);   // hi*hi
                    mma16816(acc[mt][n8], ah[mt], L0);   // hi*lo
                    mma16816(acc[mt][n8], al[mt], B0);   // lo*hi
                }
        }
    }
    // epilogue: c0,c1 -> (row, col..col+1); c2,c3 -> (row+8, ...)
    int rbase = m0 + wr*32 + (lane >> 2);
    int cbase = n0 + wc*32 + 2*(lane & 3);
    #pragma unroll
    for (int mt = 0; mt < 2; mt++) {
        #pragma unroll
        for (int n8 = 0; n8 < 4; n8++) {
            int col = cbase + n8*8;
            float b0 = bias[col], b1 = bias[col+1];
            int r0 = rbase + mt*16;
            if (r0 < NROWS)
                *(float2*)(out + (size_t)r0*HID + col) =
                    make_float2(acc[mt][n8][0] + b0, acc[mt][n8][1] + b1);
            if (r0 + 8 < NROWS)
                *(float2*)(out + (size_t)(r0+8)*HID + col) =
                    make_float2(acc[mt][n8][2] + b0, acc[mt][n8][3] + b1);
        }
    }
}

// ---------------- flash attention (f32x2) ----------------
#define ATTN_SMEM (4*64*68*4)
__global__ void __launch_bounds__(256) k_attn(const int* __restrict__ cell_ids,
                                              const int* __restrict__ counts) {
    extern __shared__ float sm[];
    float (*Qs)[68] = (float(*)[68])sm;
    float (*Ks)[68] = (float(*)[68])(sm + 64*68);
    float (*Ps)[68] = (float(*)[68])(sm + 2*64*68);
    float (*Vs)[68] = (float(*)[68])(sm + 3*64*68);

    int g = blockIdx.x, h = blockIdx.y, tid = threadIdx.x;
    int c  = cell_ids[g];
    int nt = counts[c];
    int ks0 = g_cs[c];

    for (int i = tid; i < 4096; i += 256) {
        int d = i & 63, q = i >> 6;
        Qs[d][q] = g_Qm[(size_t)(g*64 + q)*HID + h*DH + d];
    }
    int iq = tid >> 4, jg = tid & 15;
    u64 o2[4][2];
    #pragma unroll
    for (int r = 0; r < 4; r++) { o2[r][0] = 0ull; o2[r][1] = 0ull; }
    float mrow[4] = {-1e30f,-1e30f,-1e30f,-1e30f};
    float lrow[4] = {0.f,0.f,0.f,0.f};

    for (int kt = 0; kt < nt; kt++) {
        int kg = ks0 + kt;
        __syncthreads();
        for (int i = tid; i < 4096; i += 256) {
            int d = i & 63, r = i >> 6;
            Ks[d][r] = g_Km[(size_t)(kg*64 + r)*HID + h*DH + d];
        }
        for (int i = tid; i < 64*16; i += 256) {
            int r = i >> 4, dq = (i & 15) << 2;
            *(float4*)&Vs[r][dq] = *(const float4*)(g_Vm + (size_t)(kg*64 + r)*HID + h*DH + dq);
        }
        __syncthreads();
        u64 s2[4][2];
        #pragma unroll
        for (int r = 0; r < 4; r++) { s2[r][0] = 0ull; s2[r][1] = 0ull; }
        #pragma unroll 8
        for (int d = 0; d < 64; d++) {
            float4 a = *(float4*)&Qs[d][iq*4];
            u64 b0 = *(u64*)&Ks[d][jg*4];
            u64 b1 = *(u64*)&Ks[d][jg*4+2];
            float av[4] = {a.x,a.y,a.z,a.w};
            #pragma unroll
            for (int r = 0; r < 4; r++) {
                u64 ad = dup2(av[r]);
                s2[r][0] = ffma2(ad, b0, s2[r][0]);
                s2[r][1] = ffma2(ad, b1, s2[r][1]);
            }
        }
        #pragma unroll
        for (int r = 0; r < 4; r++) {
            float2 sa = up2(s2[r][0]), sb2 = up2(s2[r][1]);
            float s0 = sa.x*0.125f, s1 = sa.y*0.125f;
            float ss2 = sb2.x*0.125f, s3 = sb2.y*0.125f;
            float mt = fmaxf(fmaxf(s0,s1), fmaxf(ss2,s3));
            #pragma unroll
            for (int off = 8; off > 0; off >>= 1)
                mt = fmaxf(mt, __shfl_xor_sync(0xffffffffu, mt, off, 16));
            float mnew  = fmaxf(mrow[r], mt);
            float alpha = __expf(mrow[r] - mnew);
            float p0 = __expf(s0-mnew), p1 = __expf(s1-mnew);
            float p2 = __expf(ss2-mnew), p3 = __expf(s3-mnew);
            float lt = (p0+p1)+(p2+p3);
            #pragma unroll
            for (int off = 8; off > 0; off >>= 1)
                lt += __shfl_xor_sync(0xffffffffu, lt, off, 16);
            lrow[r] = lrow[r]*alpha + lt;
            mrow[r] = mnew;
            u64 ad = dup2(alpha);
            o2[r][0] = fmul2(o2[r][0], ad);
            o2[r][1] = fmul2(o2[r][1], ad);
            Ps[iq*4+r][jg*4+0] = p0; Ps[iq*4+r][jg*4+1] = p1;
            Ps[iq*4+r][jg*4+2] = p2; Ps[iq*4+r][jg*4+3] = p3;
        }
        __syncthreads();
        #pragma unroll 4
        for (int k0 = 0; k0 < 64; k0 += 4) {
            float4 pr[4];
            u64 vv0[4], vv1[4];
            #pragma unroll
            for (int r = 0; r < 4; r++) pr[r] = *(float4*)&Ps[iq*4+r][k0];
            #pragma unroll
            for (int kk = 0; kk < 4; kk++) {
                vv0[kk] = *(u64*)&Vs[k0+kk][jg*4];
                vv1[kk] = *(u64*)&Vs[k0+kk][jg*4+2];
            }
            #pragma unroll
            for (int r = 0; r < 4; r++) {
                float pv[4] = {pr[r].x, pr[r].y, pr[r].z, pr[r].w};
                #pragma unroll
                for (int kk = 0; kk < 4; kk++) {
                    u64 pd = dup2(pv[kk]);
                    o2[r][0] = ffma2(pd, vv0[kk], o2[r][0]);
                    o2[r][1] = ffma2(pd, vv1[kk], o2[r][1]);
                }
            }
        }
    }
    #pragma unroll
    for (int r = 0; r < 4; r++) {
        float inv = 1.f / lrow[r];
        int row = g*64 + iq*4 + r;
        float2 f0 = up2(o2[r][0]), f1 = up2(o2[r][1]);
        *(float4*)(g_att + (size_t)row*HID + h*DH + jg*4) =
            make_float4(f0.x*inv, f0.y*inv, f1.x*inv, f1.y*inv);
    }
}

// ---------------- per-cell mean of attention output ----------------
__global__ void k_csum() {
    int c = blockIdx.x;
    int hh = blockIdx.y * 128 + threadIdx.x;
    int r0 = g_cs[c] * 64;
    int S  = (g_cs[c+1] - g_cs[c]) * 64;
    float s0=0.f,s1=0.f,s2=0.f,s3=0.f;
    for (int r = 0; r < S; r += 4) {
        s0 += g_att[(size_t)(r0+r+0)*HID + hh];
        s1 += g_att[(size_t)(r0+r+1)*HID + hh];
        s2 += g_att[(size_t)(r0+r+2)*HID + hh];
        s3 += g_att[(size_t)(r0+r+3)*HID + hh];
    }
    g_csum[c*HID + hh] = ((s0+s1)+(s2+s3)) / (float)S;
}

// ---------------- per-cell vec-mat ----------------
template<int KDIM, int NCOL, int RELU, int SRC>
__global__ void k_vm(const float* __restrict__ W, const float* __restrict__ bias) {
    const float* vin  = (SRC == 0) ? g_csum  : (SRC == 1) ? g_meanh : g_h1;
    float*       vout = (SRC == 0) ? g_meanh : (SRC == 1) ? g_h1    : g_h2;
    int c = blockIdx.x;
    int n = blockIdx.y * 128 + threadIdx.x;
    __shared__ float a[KDIM];
    for (int k = threadIdx.x; k < KDIM; k += 128) a[k] = vin[c*KDIM + k];
    __syncthreads();
    float acc = bias[n];
    #pragma unroll 8
    for (int k = 0; k < KDIM; k++) acc += a[k] * W[(size_t)k*NCOL + n];
    vout[c*NCOL + n] = RELU ? fmaxf(acc, 0.f) : acc;
}

// ---------------- layernorm ----------------
__global__ void k_ln(const float* __restrict__ lng, const float* __restrict__ lnb,
                     float* __restrict__ out) {
    int c = blockIdx.x, t = threadIdx.x;
    __shared__ float sh[34];
    float v0 = g_h2[c*HID + t], v1 = g_h2[c*HID + 256 + t];
    int lane = t & 31, w = t >> 5;
    float s = v0 + v1;
    #pragma unroll
    for (int off = 16; off; off >>= 1) s += __shfl_xor_sync(~0u, s, off);
    if (lane == 0) sh[w] = s;
    __syncthreads();
    if (w == 0) {
        float tot = (t < 8) ? sh[t] : 0.f;
        #pragma unroll
        for (int off = 4; off; off >>= 1) tot += __shfl_xor_sync(~0u, tot, off);
        if (t == 0) sh[32] = tot;
    }
    __syncthreads();
    float mu = sh[32] * (1.f/512.f);
    float d0 = v0 - mu, d1 = v1 - mu;
    float q = d0*d0 + d1*d1;
    #pragma unroll
    for (int off = 16; off; off >>= 1) q += __shfl_xor_sync(~0u, q, off);
    if (lane == 0) sh[w] = q;
    __syncthreads();
    if (w == 0) {
        float tot = (t < 8) ? sh[t] : 0.f;
        #pragma unroll
        for (int off = 4; off; off >>= 1) tot += __shfl_xor_sync(~0u, tot, off);
        if (t == 0) sh[33] = tot;
    }
    __syncthreads();
    float inv = rsqrtf(sh[33] * (1.f/512.f) + 1e-5f);
    float r0 = d0*inv*lng[t]     + lnb[t];
    float r1 = d1*inv*lng[256+t] + lnb[256+t];
    g_int[c*HID + t]       = r0;
    g_int[c*HID + 256 + t] = r1;
    out[64 + c*HID + t]       = r0;
    out[64 + c*HID + 256 + t] = r1;
}

// ---------------- per-cell affinity head ----------------
__global__ void k_aff(const float* __restrict__ Aw1, const float* __restrict__ Ab1,
                      const float* __restrict__ Aw2, const float* __restrict__ Ab2,
                      float* __restrict__ out) {
    int c = blockIdx.x, t = threadIdx.x;
    __shared__ float a[HID];
    __shared__ float red[8];
    a[t]       = g_int[c*HID + t];
    a[t + 256] = g_int[c*HID + 256 + t];
    __syncthreads();
    float part = 0.f;
    #pragma unroll
    for (int half = 0; half < 2; half++) {
        int k = t + half*256;
        float acc = Ab1[c*HID + k];
        const float* W = Aw1 + (size_t)c*HID*HID + k;
        #pragma unroll 8
        for (int j = 0; j < HID; j++) acc += a[j] * W[(size_t)j*HID];
        part += fmaxf(acc, 0.f) * Aw2[c*HID + k];
    }
    int lane = t & 31, w = t >> 5;
    #pragma unroll
    for (int off = 16; off; off >>= 1) part += __shfl_xor_sync(~0u, part, off);
    if (lane == 0) red[w] = part;
    __syncthreads();
    if (t == 0) {
        float s = 0.f;
        #pragma unroll
        for (int i = 0; i < 8; i++) s += red[i];
        out[c] = 1.f / (1.f + expf(-(s + Ab2[c])));
    }
}

extern "C" void kernel_launch(void* const* d_in, const int* in_sizes, int n_in,
                              void* d_out, int out_size) {
    const float* x       = (const float*)d_in[0];
    const int*   ei      = (const int*)  d_in[1];
    const float* gene_W  = (const float*)d_in[3];
    const float* gene_b  = (const float*)d_in[4];
    const int*   cell_ids= (const int*)  d_in[5];
    const int*   counts  = (const int*)  d_in[7];
    const float* Wq = (const float*)d_in[8],  *bq = (const float*)d_in[9];
    const float* Wk = (const float*)d_in[10], *bk = (const float*)d_in[11];
    const float* Wv = (const float*)d_in[12], *bv = (const float*)d_in[13];
    const float* Wo = (const float*)d_in[14], *bo = (const float*)d_in[15];
    const float* Wi1= (const float*)d_in[16], *bi1= (const float*)d_in[17];
    const float* Wi2= (const float*)d_in[18], *bi2= (const float*)d_in[19];
    const float* lng= (const float*)d_in[20], *lnb= (const float*)d_in[21];
    const float* Aw1= (const float*)d_in[22], *Ab1= (const float*)d_in[23];
    const float* Aw2= (const float*)d_in[24], *Ab2= (const float*)d_in[25];
    float* out = (float*)d_out;

    cudaFuncSetAttribute(k_attn, cudaFuncAttributeMaxDynamicSharedMemorySize, ATTN_SMEM);
    cudaFuncSetAttribute(k_qkv_mma, cudaFuncAttributeMaxDynamicSharedMemorySize, QKV_SMEM);

    k_init <<<256, 256>>>(counts);
    k_edges<<<(NEDGES*32)/256, 256>>>(x, ei);
    k_pool <<<NB, 128>>>(x);
    k_gene <<<dim3(NG, 4), 256>>>(gene_W, gene_b);
    k_cvtX <<<(int)(((size_t)PADROWS*HID/4 + 255)/256), 256>>>();
    k_cvtW <<<dim3(3, 16, 16), dim3(32, 8)>>>(Wq, Wk, Wv);
    k_qkv_mma<<<dim3(MTILES, 24), 256, QKV_SMEM>>>(bq, bk, bv);
    k_attn <<<dim3(NG, 8), 256, ATTN_SMEM>>>(cell_ids, counts);
    k_csum <<<dim3(NC, 4), 128>>>();
    k_vm<512, 512, 0, 0><<<dim3(NC, 4), 128>>>(Wo,  bo);
    k_vm<512,1024, 1, 1><<<dim3(NC, 8), 128>>>(Wi1, bi1);
    k_vm<1024,512, 0, 2><<<dim3(NC, 4), 128>>>(Wi2, bi2);
    k_ln  <<<NC, 256>>>(lng, lnb, out);
    k_aff <<<NC, 256>>>(Aw1, Ab1, Aw2, Ab2, out);
}

// round 6
// speedup vs baseline: 1.8645x; 1.3613x over previous
#include <cuda_runtime.h>
#include <cuda_bf16.h>
#include <math.h>
#include <cstdint>

#define NNODES 4096
#define FEAT   128
#define NEDGES 65536
#define NG     317
#define NB     64
#define NC     64
#define HID    512
#define DH     64
#define NROWS  (NG*NB)
#define FFD    1024
#define MTILES 159
#define PADROWS (MTILES*128)

typedef unsigned long long u64;

// ---------------- f32x2 helpers ----------------
__device__ __forceinline__ u64 dup2(float x) {
    u64 r; asm("mov.b64 %0,{%1,%1};" : "=l"(r) : "f"(x)); return r;
}
__device__ __forceinline__ u64 ffma2(u64 a, u64 b, u64 c) {
    u64 d; asm("fma.rn.f32x2 %0,%1,%2,%3;" : "=l"(d) : "l"(a), "l"(b), "l"(c)); return d;
}
__device__ __forceinline__ float2 up2(u64 v) {
    float2 f; asm("mov.b64 {%0,%1},%2;" : "=f"(f.x), "=f"(f.y) : "l"(v)); return f;
}

// ---------------- mma.sync helpers ----------------
__device__ __forceinline__ uint32_t smem_u32(const void* p) {
    uint32_t a; asm("{ .reg .u64 t; cvta.to.shared.u64 t, %1; cvt.u32.u64 %0, t; }"
                    : "=r"(a) : "l"(p)); return a;
}
__device__ __forceinline__ void ldsm_x4(uint32_t* r, uint32_t addr) {
    asm volatile("ldmatrix.sync.aligned.m8n8.x4.shared.b16 {%0,%1,%2,%3}, [%4];"
        : "=r"(r[0]), "=r"(r[1]), "=r"(r[2]), "=r"(r[3]) : "r"(addr));
}
__device__ __forceinline__ void ldsm_x4_t(uint32_t* r, uint32_t addr) {
    asm volatile("ldmatrix.sync.aligned.m8n8.x4.trans.shared.b16 {%0,%1,%2,%3}, [%4];"
        : "=r"(r[0]), "=r"(r[1]), "=r"(r[2]), "=r"(r[3]) : "r"(addr));
}
__device__ __forceinline__ void mma16816(float* d, const uint32_t* a, const uint32_t* b) {
    asm volatile("mma.sync.aligned.m16n8k16.row.col.f32.bf16.bf16.f32 "
        "{%0,%1,%2,%3}, {%4,%5,%6,%7}, {%8,%9}, {%0,%1,%2,%3};"
        : "+f"(d[0]), "+f"(d[1]), "+f"(d[2]), "+f"(d[3])
        : "r"(a[0]), "r"(a[1]), "r"(a[2]), "r"(a[3]), "r"(b[0]), "r"(b[1]));
}
// pack two f32 -> bf16x2 (lo in low half)
__device__ __forceinline__ uint32_t pkbf2(float lo, float hi) {
    uint32_t r; asm("cvt.rn.bf16x2.f32 %0, %1, %2;" : "=r"(r) : "f"(hi), "f"(lo)); return r;
}

// ---------------- scratch ----------------
__device__ float g_deg[NNODES];
__device__ float g_agg[NNODES*FEAT];
__device__ float g_pooled[NB*FEAT];
__device__ float g_X  [(size_t)NROWS*HID];
__device__ float g_att[(size_t)NROWS*HID];
__device__ float g_csum[NC*HID];
__device__ float g_meanh[NC*HID];
__device__ float g_h1[NC*FFD];
__device__ float g_h2[NC*HID];
__device__ float g_int[NC*HID];
__device__ int   g_cs[NC+1];
__device__ __nv_bfloat16 g_Xhi[(size_t)PADROWS*HID];
__device__ __nv_bfloat16 g_Xlo[(size_t)PADROWS*HID];
__device__ __nv_bfloat16 g_Wthi[3*HID*HID];   // [w][n][k]
__device__ __nv_bfloat16 g_Wtlo[3*HID*HID];
__device__ __nv_bfloat16 g_Qhi[(size_t)NROWS*HID];
__device__ __nv_bfloat16 g_Qlo[(size_t)NROWS*HID];
__device__ __nv_bfloat16 g_Khi[(size_t)NROWS*HID];
__device__ __nv_bfloat16 g_Klo[(size_t)NROWS*HID];
__device__ __nv_bfloat16 g_Vhi[(size_t)NROWS*HID];

// ---------------- init ----------------
__global__ void k_init(const int* __restrict__ counts) {
    int i = blockIdx.x * blockDim.x + threadIdx.x;
    int nt = gridDim.x * blockDim.x;
    if (i < NNODES) g_deg[i] = 0.f;
    for (int j = i; j < NNODES*FEAT; j += nt) g_agg[j] = 0.f;
    if (i == 0) {
        int s = 0;
        for (int c = 0; c < NC; c++) { g_cs[c] = s; s += counts[c]; }
        g_cs[NC] = s;
    }
}

// ---------------- edge aggregation ----------------
__global__ void k_edges(const float* __restrict__ x, const int* __restrict__ ei) {
    int t = blockIdx.x * blockDim.x + threadIdx.x;
    int e = t >> 5, lane = t & 31;
    if (e >= NEDGES) return;
    int s = ei[e], d = ei[NEDGES + e];
    float4 v = *(const float4*)(x + (size_t)s*FEAT + lane*4);
    float* a = g_agg + (size_t)d*FEAT + lane*4;
    atomicAdd(a+0, v.x); atomicAdd(a+1, v.y);
    atomicAdd(a+2, v.z); atomicAdd(a+3, v.w);
    if (lane == 0) atomicAdd(g_deg + d, 1.f);
}

// ---------------- per-graph mean pool ----------------
__global__ void k_pool(const float* __restrict__ x) {
    int g = blockIdx.x, f = threadIdx.x;
    float s = 0.f;
    for (int n = g*64; n < g*64 + 64; n++) {
        float inv = 1.f / fmaxf(g_deg[n], 1.f);
        s += x[(size_t)n*FEAT + f] + g_agg[(size_t)n*FEAT + f] * inv;
    }
    g_pooled[g*FEAT + f] = s * (1.f/64.f);
}

// ---------------- per-gene GEMM (f32x2) ----------------
__global__ void __launch_bounds__(256) k_gene(const float* __restrict__ gW,
                                              const float* __restrict__ gb) {
    int g = blockIdx.x, h0 = blockIdx.y * 128;
    __shared__ float sp[128][68];
    __shared__ float sw[16][128];
    for (int i = threadIdx.x; i < 64*32; i += 256) {
        int b = i >> 5, fq = i & 31;
        float4 v = *(const float4*)(g_pooled + b*FEAT + fq*4);
        sp[fq*4+0][b] = v.x; sp[fq*4+1][b] = v.y;
        sp[fq*4+2][b] = v.z; sp[fq*4+3][b] = v.w;
    }
    u64 acc2[4][4];
    #pragma unroll
    for (int i = 0; i < 4; i++)
        #pragma unroll
        for (int p = 0; p < 4; p++) acc2[i][p] = 0ull;
    int tb = (threadIdx.x & 15) * 4;
    int th = (threadIdx.x >> 4) * 8;
    const float* W = gW + (size_t)g*FEAT*HID + h0;
    int lr = threadIdx.x >> 4, lc = (threadIdx.x & 15) * 8;
    __syncthreads();
    for (int k0 = 0; k0 < 128; k0 += 16) {
        *(float4*)&sw[lr][lc]   = *(const float4*)(W + (size_t)(k0+lr)*HID + lc);
        *(float4*)&sw[lr][lc+4] = *(const float4*)(W + (size_t)(k0+lr)*HID + lc + 4);
        __syncthreads();
        #pragma unroll
        for (int kk = 0; kk < 16; kk++) {
            float4 a  = *(float4*)&sp[k0+kk][tb];
            u64 b2[4];
            b2[0] = *(u64*)&sw[kk][th];   b2[1] = *(u64*)&sw[kk][th+2];
            b2[2] = *(u64*)&sw[kk][th+4]; b2[3] = *(u64*)&sw[kk][th+6];
            float av[4] = {a.x,a.y,a.z,a.w};
            #pragma unroll
            for (int i = 0; i < 4; i++) {
                u64 ad = dup2(av[i]);
                #pragma unroll
                for (int p = 0; p < 4; p++) acc2[i][p] = ffma2(ad, b2[p], acc2[i][p]);
            }
        }
        __syncthreads();
    }
    #pragma unroll
    for (int i = 0; i < 4; i++) {
        int row = g*64 + tb + i, col = h0 + th;
        float2 f0 = up2(acc2[i][0]), f1 = up2(acc2[i][1]);
        float2 f2 = up2(acc2[i][2]), f3 = up2(acc2[i][3]);
        const float* B = gb + (size_t)g*HID + col;
        *(float4*)(g_X + (size_t)row*HID + col) =
            make_float4(fmaxf(f0.x+B[0],0.f), fmaxf(f0.y+B[1],0.f),
                        fmaxf(f1.x+B[2],0.f), fmaxf(f1.y+B[3],0.f));
        *(float4*)(g_X + (size_t)row*HID + col + 4) =
            make_float4(fmaxf(f2.x+B[4],0.f), fmaxf(f2.y+B[5],0.f),
                        fmaxf(f3.x+B[6],0.f), fmaxf(f3.y+B[7],0.f));
    }
}

// ---------------- convert X -> bf16 hi/lo (padded) ----------------
__global__ void k_cvtX() {
    size_t i = ((size_t)blockIdx.x * 256 + threadIdx.x) * 4;
    if (i >= (size_t)PADROWS*HID) return;
    float4 v = make_float4(0.f,0.f,0.f,0.f);
    if (i < (size_t)NROWS*HID) v = *(const float4*)(g_X + i);
    float vv[4] = {v.x, v.y, v.z, v.w};
    #pragma unroll
    for (int j = 0; j < 4; j++) {
        __nv_bfloat16 h = __float2bfloat16(vv[j]);
        g_Xhi[i+j] = h;
        g_Xlo[i+j] = __float2bfloat16(vv[j] - __bfloat162float(h));
    }
}

// ---------------- transpose+convert W -> bf16 hi/lo [n][k] ----------------
__global__ void k_cvtW(const float* __restrict__ Wq, const float* __restrict__ Wk,
                       const float* __restrict__ Wv) {
    __shared__ float tile[32][33];
    int w = blockIdx.x;
    const float* W = (w == 0) ? Wq : (w == 1) ? Wk : Wv;
    int kb = blockIdx.y * 32, nb = blockIdx.z * 32;
    #pragma unroll
    for (int i = 0; i < 4; i++)
        tile[threadIdx.y + i*8][threadIdx.x] =
            W[(size_t)(kb + threadIdx.y + i*8)*HID + nb + threadIdx.x];
    __syncthreads();
    #pragma unroll
    for (int i = 0; i < 4; i++) {
        int n = nb + threadIdx.y + i*8, k = kb + threadIdx.x;
        float v = tile[threadIdx.x][threadIdx.y + i*8];
        __nv_bfloat16 h = __float2bfloat16(v);
        size_t o = (size_t)w*HID*HID + (size_t)n*HID + k;
        g_Wthi[o] = h;
        g_Wtlo[o] = __float2bfloat16(v - __bfloat162float(h));
    }
}

// ---------------- QKV GEMM via mma.sync bf16, outputs bf16 hi/lo ----------------
#define AHI 0
#define ALO 16384
#define BHI 32768
#define BLO 40960
#define QKV_SMEM 49152

__global__ void __launch_bounds__(256) k_qkv_mma(
        const float* __restrict__ bq, const float* __restrict__ bk,
        const float* __restrict__ bv) {
    extern __shared__ char smem[];
    uint32_t sb = smem_u32(smem);
    int tid = threadIdx.x;
    int wid = tid >> 5, lane = tid & 31;
    int m0 = blockIdx.x * 128;
    int nt = blockIdx.y;                 // 0..23
    int wsel = nt >> 3, n0 = (nt & 7) * 64;
    const float* bias = (wsel == 0) ? bq : (wsel == 1) ? bk : bv;
    __nv_bfloat16* outhi = (wsel == 0) ? g_Qhi : (wsel == 1) ? g_Khi : g_Vhi;
    __nv_bfloat16* outlo = (wsel == 0) ? g_Qlo : (wsel == 1) ? g_Klo : (__nv_bfloat16*)0;
    const __nv_bfloat16* Bh = g_Wthi + (size_t)wsel*HID*HID;
    const __nv_bfloat16* Bl = g_Wtlo + (size_t)wsel*HID*HID;

    int wr = wid & 3, wc = wid >> 2;

    float acc[2][4][4];
    #pragma unroll
    for (int a = 0; a < 2; a++)
        #pragma unroll
        for (int b = 0; b < 4; b++)
            #pragma unroll
            for (int c = 0; c < 4; c++) acc[a][b][c] = 0.f;

    for (int ch = 0; ch < 8; ch++) {
        int k0 = ch * 64;
        __syncthreads();
        for (int u = tid; u < 1024; u += 256) {
            int row = u >> 3, c = u & 7;
            uint32_t dst = (uint32_t)(((row << 3) | (c ^ (row & 7))) << 4);
            size_t go = (size_t)(m0 + row)*HID + k0 + c*8;
            *(uint4*)(smem + AHI + dst) = *(const uint4*)(g_Xhi + go);
            *(uint4*)(smem + ALO + dst) = *(const uint4*)(g_Xlo + go);
        }
        for (int u = tid; u < 512; u += 256) {
            int row = u >> 3, c = u & 7;
            uint32_t dst = (uint32_t)(((row << 3) | (c ^ (row & 7))) << 4);
            size_t go = (size_t)(n0 + row)*HID + k0 + c*8;
            *(uint4*)(smem + BHI + dst) = *(const uint4*)(Bh + go);
            *(uint4*)(smem + BLO + dst) = *(const uint4*)(Bl + go);
        }
        __syncthreads();
        #pragma unroll
        for (int s = 0; s < 4; s++) {
            uint32_t ah[2][4], al[2][4];
            {
                int arow = wr*32 + (lane & 15);
                int ac   = s*2 + (lane >> 4);
                #pragma unroll
                for (int mt = 0; mt < 2; mt++) {
                    int r = arow + mt*16;
                    uint32_t off = (uint32_t)(((r << 3) | (ac ^ (r & 7))) << 4);
                    ldsm_x4(ah[mt], sb + AHI + off);
                    ldsm_x4(al[mt], sb + ALO + off);
                }
            }
            uint32_t bh[2][4], bl[2][4];
            {
                int brow = wc*32 + (lane & 7) + ((lane >> 4) << 3);
                int bc   = s*2 + ((lane >> 3) & 1);
                #pragma unroll
                for (int bt = 0; bt < 2; bt++) {
                    int r = brow + bt*16;
                    uint32_t off = (uint32_t)(((r << 3) | (bc ^ (r & 7))) << 4);
                    ldsm_x4(bh[bt], sb + BHI + off);
                    ldsm_x4(bl[bt], sb + BLO + off);
                }
            }
            #pragma unroll
            for (int mt = 0; mt < 2; mt++)
                #pragma unroll
                for (int n8 = 0; n8 < 4; n8++) {
                    const uint32_t* B0 = &bh[n8 >> 1][(n8 & 1) * 2];
                    const uint32_t* L0 = &bl[n8 >> 1][(n8 & 1) * 2];
                    mma16816(acc[mt][n8], ah[mt], B0);
                    mma16816(acc[mt][n8], ah[mt], L0);
                    mma16816(acc[mt][n8], al[mt], B0);
                }
        }
    }
    // epilogue -> bf16 hi/lo
    int rbase = m0 + wr*32 + (lane >> 2);
    int cbase = n0 + wc*32 + 2*(lane & 3);
    #pragma unroll
    for (int mt = 0; mt < 2; mt++) {
        #pragma unroll
        for (int n8 = 0; n8 < 4; n8++) {
            int col = cbase + n8*8;
            float b0 = bias[col], b1 = bias[col+1];
            #pragma unroll
            for (int half = 0; half < 2; half++) {
                int r0 = rbase + mt*16 + half*8;
                if (r0 >= NROWS) continue;
                float v0 = acc[mt][n8][half*2+0] + b0;
                float v1 = acc[mt][n8][half*2+1] + b1;
                float h0 = __bfloat162float(__float2bfloat16(v0));
                float h1 = __bfloat162float(__float2bfloat16(v1));
                *(uint32_t*)(outhi + (size_t)r0*HID + col) = pkbf2(v0, v1);
                if (outlo)
                    *(uint32_t*)(outlo + (size_t)r0*HID + col) = pkbf2(v0 - h0, v1 - h1);
            }
        }
    }
}

// ---------------- flash attention via mma.sync bf16 ----------------
// smem: QH 8K | QL 8K | KH 8K | KL 8K | VH 8K = 40KB
#define AQH 0
#define AQL 8192
#define AKH 16384
#define AKL 24576
#define AVH 32768
#define ATTN_SMEM 40960

__global__ void __launch_bounds__(128) k_attn_mma(const int* __restrict__ cell_ids,
                                                  const int* __restrict__ counts) {
    extern __shared__ char smem[];
    uint32_t sb = smem_u32(smem);
    int g = blockIdx.x, h = blockIdx.y;
    int tid = threadIdx.x, wid = tid >> 5, lane = tid & 31;
    int c = cell_ids[g];
    int nt = counts[c];
    int ks0 = g_cs[c];

    // stage Q hi/lo (swizzled rows of 128B)
    for (int u = tid; u < 512; u += 128) {
        int row = u >> 3, ch = u & 7;
        uint32_t dst = (uint32_t)(((row << 3) | (ch ^ (row & 7))) << 4);
        size_t go = (size_t)(g*64 + row)*HID + h*64 + ch*8;
        *(uint4*)(smem + AQH + dst) = *(const uint4*)(g_Qhi + go);
        *(uint4*)(smem + AQL + dst) = *(const uint4*)(g_Qlo + go);
    }

    float oacc[8][4];
    #pragma unroll
    for (int t = 0; t < 8; t++)
        #pragma unroll
        for (int j = 0; j < 4; j++) oacc[t][j] = 0.f;
    float mA = -1e30f, mB = -1e30f, lA = 0.f, lB = 0.f;

    int arow = wid*16 + (lane & 15);

    for (int kt = 0; kt < nt; kt++) {
        int kg = ks0 + kt;
        __syncthreads();
        for (int u = tid; u < 512; u += 128) {
            int row = u >> 3, ch = u & 7;
            uint32_t dst = (uint32_t)(((row << 3) | (ch ^ (row & 7))) << 4);
            size_t go = (size_t)(kg*64 + row)*HID + h*64 + ch*8;
            *(uint4*)(smem + AKH + dst) = *(const uint4*)(g_Khi + go);
            *(uint4*)(smem + AKL + dst) = *(const uint4*)(g_Klo + go);
            *(uint4*)(smem + AVH + dst) = *(const uint4*)(g_Vhi + go);
        }
        __syncthreads();

        // S = Q K^T (compensated)
        float sacc[8][4];
        #pragma unroll
        for (int t = 0; t < 8; t++)
            #pragma unroll
            for (int j = 0; j < 4; j++) sacc[t][j] = 0.f;
        #pragma unroll
        for (int s = 0; s < 4; s++) {
            int ac = s*2 + (lane >> 4);
            uint32_t aoff = (uint32_t)(((arow << 3) | (ac ^ (arow & 7))) << 4);
            uint32_t ah[4], al[4];
            ldsm_x4(ah, sb + AQH + aoff);
            ldsm_x4(al, sb + AQL + aoff);
            #pragma unroll
            for (int bt = 0; bt < 4; bt++) {
                int brow = bt*16 + (lane & 7) + ((lane >> 4) << 3);
                int bc   = s*2 + ((lane >> 3) & 1);
                uint32_t boff = (uint32_t)(((brow << 3) | (bc ^ (brow & 7))) << 4);
                uint32_t bh[4], bl[4];
                ldsm_x4(bh, sb + AKH + boff);
                ldsm_x4(bl, sb + AKL + boff);
                mma16816(sacc[bt*2],   ah, &bh[0]);
                mma16816(sacc[bt*2],   ah, &bl[0]);
                mma16816(sacc[bt*2],   al, &bh[0]);
                mma16816(sacc[bt*2+1], ah, &bh[2]);
                mma16816(sacc[bt*2+1], ah, &bl[2]);
                mma16816(sacc[bt*2+1], al, &bh[2]);
            }
        }
        // online softmax (rows rA = lane>>2, rB = rA+8 within warp strip)
        float mtA = -1e30f, mtB = -1e30f;
        #pragma unroll
        for (int t = 0; t < 8; t++) {
            sacc[t][0] *= 0.125f; sacc[t][1] *= 0.125f;
            sacc[t][2] *= 0.125f; sacc[t][3] *= 0.125f;
            mtA = fmaxf(mtA, fmaxf(sacc[t][0], sacc[t][1]));
            mtB = fmaxf(mtB, fmaxf(sacc[t][2], sacc[t][3]));
        }
        mtA = fmaxf(mtA, __shfl_xor_sync(~0u, mtA, 1));
        mtA = fmaxf(mtA, __shfl_xor_sync(~0u, mtA, 2));
        mtB = fmaxf(mtB, __shfl_xor_sync(~0u, mtB, 1));
        mtB = fmaxf(mtB, __shfl_xor_sync(~0u, mtB, 2));
        float mnA = fmaxf(mA, mtA), mnB = fmaxf(mB, mtB);
        float alA = __expf(mA - mnA), alB = __expf(mB - mnB);
        float ltA = 0.f, ltB = 0.f;
        #pragma unroll
        for (int t = 0; t < 8; t++) {
            sacc[t][0] = __expf(sacc[t][0] - mnA);
            sacc[t][1] = __expf(sacc[t][1] - mnA);
            sacc[t][2] = __expf(sacc[t][2] - mnB);
            sacc[t][3] = __expf(sacc[t][3] - mnB);
            ltA += sacc[t][0] + sacc[t][1];
            ltB += sacc[t][2] + sacc[t][3];
        }
        ltA += __shfl_xor_sync(~0u, ltA, 1); ltA += __shfl_xor_sync(~0u, ltA, 2);
        ltB += __shfl_xor_sync(~0u, ltB, 1); ltB += __shfl_xor_sync(~0u, ltB, 2);
        lA = lA*alA + ltA; lB = lB*alB + ltB;
        mA = mnA; mB = mnB;
        #pragma unroll
        for (int t = 0; t < 8; t++) {
            oacc[t][0] *= alA; oacc[t][1] *= alA;
            oacc[t][2] *= alB; oacc[t][3] *= alB;
        }
        // O += P V  (P from accumulators -> A-frags; V via ldmatrix.trans)
        #pragma unroll
        for (int t2 = 0; t2 < 4; t2++) {
            uint32_t pa[4];
            pa[0] = pkbf2(sacc[2*t2][0],   sacc[2*t2][1]);
            pa[1] = pkbf2(sacc[2*t2][2],   sacc[2*t2][3]);
            pa[2] = pkbf2(sacc[2*t2+1][0], sacc[2*t2+1][1]);
            pa[3] = pkbf2(sacc[2*t2+1][2], sacc[2*t2+1][3]);
            int grp = lane >> 3;
            int vrow = t2*16 + (lane & 7) + ((grp & 1) << 3);
            #pragma unroll
            for (int dblk = 0; dblk < 4; dblk++) {
                int vch = dblk*2 + (grp >> 1);
                uint32_t voff = (uint32_t)(((vrow << 3) | (vch ^ (vrow & 7))) << 4);
                uint32_t vb[4];
                ldsm_x4_t(vb, sb + AVH + voff);
                mma16816(oacc[dblk*2],   pa, &vb[0]);
                mma16816(oacc[dblk*2+1], pa, &vb[2]);
            }
        }
    }
    // writeout
    float invA = 1.f / lA, invB = 1.f / lB;
    int rA = g*64 + wid*16 + (lane >> 2);
    int cb = h*64 + 2*(lane & 3);
    #pragma unroll
    for (int t = 0; t < 8; t++) {
        *(float2*)(g_att + (size_t)rA*HID + cb + t*8) =
            make_float2(oacc[t][0]*invA, oacc[t][1]*invA);
        *(float2*)(g_att + (size_t)(rA+8)*HID + cb + t*8) =
            make_float2(oacc[t][2]*invB, oacc[t][3]*invB);
    }
}

// ---------------- per-cell mean of attention output ----------------
__global__ void k_csum() {
    int c = blockIdx.x;
    int hh = blockIdx.y * 128 + threadIdx.x;
    int r0 = g_cs[c] * 64;
    int S  = (g_cs[c+1] - g_cs[c]) * 64;
    float s0=0.f,s1=0.f,s2=0.f,s3=0.f;
    for (int r = 0; r < S; r += 4) {
        s0 += g_att[(size_t)(r0+r+0)*HID + hh];
        s1 += g_att[(size_t)(r0+r+1)*HID + hh];
        s2 += g_att[(size_t)(r0+r+2)*HID + hh];
        s3 += g_att[(size_t)(r0+r+3)*HID + hh];
    }
    g_csum[c*HID + hh] = ((s0+s1)+(s2+s3)) / (float)S;
}

// ---------------- per-cell vec-mat ----------------
template<int KDIM, int NCOL, int RELU, int SRC>
__global__ void k_vm(const float* __restrict__ W, const float* __restrict__ bias) {
    const float* vin  = (SRC == 0) ? g_csum  : (SRC == 1) ? g_meanh : g_h1;
    float*       vout = (SRC == 0) ? g_meanh : (SRC == 1) ? g_h1    : g_h2;
    int c = blockIdx.x;
    int n = blockIdx.y * 128 + threadIdx.x;
    __shared__ float a[KDIM];
    for (int k = threadIdx.x; k < KDIM; k += 128) a[k] = vin[c*KDIM + k];
    __syncthreads();
    float acc = bias[n];
    #pragma unroll 8
    for (int k = 0; k < KDIM; k++) acc += a[k] * W[(size_t)k*NCOL + n];
    vout[c*NCOL + n] = RELU ? fmaxf(acc, 0.f) : acc;
}

// ---------------- layernorm ----------------
__global__ void k_ln(const float* __restrict__ lng, const float* __restrict__ lnb,
                     float* __restrict__ out) {
    int c = blockIdx.x, t = threadIdx.x;
    __shared__ float sh[34];
    float v0 = g_h2[c*HID + t], v1 = g_h2[c*HID + 256 + t];
    int lane = t & 31, w = t >> 5;
    float s = v0 + v1;
    #pragma unroll
    for (int off = 16; off; off >>= 1) s += __shfl_xor_sync(~0u, s, off);
    if (lane == 0) sh[w] = s;
    __syncthreads();
    if (w == 0) {
        float tot = (t < 8) ? sh[t] : 0.f;
        #pragma unroll
        for (int off = 4; off; off >>= 1) tot += __shfl_xor_sync(~0u, tot, off);
        if (t == 0) sh[32] = tot;
    }
    __syncthreads();
    float mu = sh[32] * (1.f/512.f);
    float d0 = v0 - mu, d1 = v1 - mu;
    float q = d0*d0 + d1*d1;
    #pragma unroll
    for (int off = 16; off; off >>= 1) q += __shfl_xor_sync(~0u, q, off);
    if (lane == 0) sh[w] = q;
    __syncthreads();
    if (w == 0) {
        float tot = (t < 8) ? sh[t] : 0.f;
        #pragma unroll
        for (int off = 4; off; off >>= 1) tot += __shfl_xor_sync(~0u, tot, off);
        if (t == 0) sh[33] = tot;
    }
    __syncthreads();
    float inv = rsqrtf(sh[33] * (1.f/512.f) + 1e-5f);
    float r0 = d0*inv*lng[t]     + lnb[t];
    float r1 = d1*inv*lng[256+t] + lnb[256+t];
    g_int[c*HID + t]       = r0;
    g_int[c*HID + 256 + t] = r1;
    out[64 + c*HID + t]       = r0;
    out[64 + c*HID + 256 + t] = r1;
}

// ---------------- per-cell affinity head ----------------
__global__ void k_aff(const float* __restrict__ Aw1, const float* __restrict__ Ab1,
                      const float* __restrict__ Aw2, const float* __restrict__ Ab2,
                      float* __restrict__ out) {
    int c = blockIdx.x, t = threadIdx.x;
    __shared__ float a[HID];
    __shared__ float red[8];
    a[t]       = g_int[c*HID + t];
    a[t + 256] = g_int[c*HID + 256 + t];
    __syncthreads();
    float part = 0.f;
    #pragma unroll
    for (int half = 0; half < 2; half++) {
        int k = t + half*256;
        float acc = Ab1[c*HID + k];
        const float* W = Aw1 + (size_t)c*HID*HID + k;
        #pragma unroll 8
        for (int j = 0; j < HID; j++) acc += a[j] * W[(size_t)j*HID];
        part += fmaxf(acc, 0.f) * Aw2[c*HID + k];
    }
    int lane = t & 31, w = t >> 5;
    #pragma unroll
    for (int off = 16; off; off >>= 1) part += __shfl_xor_sync(~0u, part, off);
    if (lane == 0) red[w] = part;
    __syncthreads();
    if (t == 0) {
        float s = 0.f;
        #pragma unroll
        for (int i = 0; i < 8; i++) s += red[i];
        out[c] = 1.f / (1.f + expf(-(s + Ab2[c])));
    }
}

extern "C" void kernel_launch(void* const* d_in, const int* in_sizes, int n_in,
                              void* d_out, int out_size) {
    const float* x       = (const float*)d_in[0];
    const int*   ei      = (const int*)  d_in[1];
    const float* gene_W  = (const float*)d_in[3];
    const float* gene_b  = (const float*)d_in[4];
    const int*   cell_ids= (const int*)  d_in[5];
    const int*   counts  = (const int*)  d_in[7];
    const float* Wq = (const float*)d_in[8],  *bq = (const float*)d_in[9];
    const float* Wk = (const float*)d_in[10], *bk = (const float*)d_in[11];
    const float* Wv = (const float*)d_in[12], *bv = (const float*)d_in[13];
    const float* Wo = (const float*)d_in[14], *bo = (const float*)d_in[15];
    const float* Wi1= (const float*)d_in[16], *bi1= (const float*)d_in[17];
    const float* Wi2= (const float*)d_in[18], *bi2= (const float*)d_in[19];
    const float* lng= (const float*)d_in[20], *lnb= (const float*)d_in[21];
    const float* Aw1= (const float*)d_in[22], *Ab1= (const float*)d_in[23];
    const float* Aw2= (const float*)d_in[24], *Ab2= (const float*)d_in[25];
    float* out = (float*)d_out;

    cudaFuncSetAttribute(k_attn_mma, cudaFuncAttributeMaxDynamicSharedMemorySize, ATTN_SMEM);
    cudaFuncSetAttribute(k_qkv_mma, cudaFuncAttributeMaxDynamicSharedMemorySize, QKV_SMEM);

    k_init <<<256, 256>>>(counts);
    k_edges<<<(NEDGES*32)/256, 256>>>(x, ei);
    k_pool <<<NB, 128>>>(x);
    k_gene <<<dim3(NG, 4), 256>>>(gene_W, gene_b);
    k_cvtX <<<(int)(((size_t)PADROWS*HID/4 + 255)/256), 256>>>();
    k_cvtW <<<dim3(3, 16, 16), dim3(32, 8)>>>(Wq, Wk, Wv);
    k_qkv_mma<<<dim3(MTILES, 24), 256, QKV_SMEM>>>(bq, bk, bv);
    k_attn_mma<<<dim3(NG, 8), 128, ATTN_SMEM>>>(cell_ids, counts);
    k_csum <<<dim3(NC, 4), 128>>>();
    k_vm<512, 512, 0, 0><<<dim3(NC, 4), 128>>>(Wo,  bo);
    k_vm<512,1024, 1, 1><<<dim3(NC, 8), 128>>>(Wi1, bi1);
    k_vm<1024,512, 0, 2><<<dim3(NC, 4), 128>>>(Wi2, bi2);
    k_ln  <<<NC, 256>>>(lng, lnb, out);
    k_aff <<<NC, 256>>>(Aw1, Ab1, Aw2, Ab2, out);
}

// round 7
// speedup vs baseline: 2.0638x; 1.1069x over previous
#include <cuda_runtime.h>
#include <cuda_bf16.h>
#include <math.h>
#include <cstdint>

#define NNODES 4096
#define FEAT   128
#define NEDGES 65536
#define NG     317
#define NB     64
#define NC     64
#define HID    512
#define DH     64
#define NROWS  (NG*NB)
#define FFD    1024
#define MTILES 159
#define PADROWS (MTILES*128)

typedef unsigned long long u64;

// ---------------- f32x2 helpers ----------------
__device__ __forceinline__ u64 dup2(float x) {
    u64 r; asm("mov.b64 %0,{%1,%1};" : "=l"(r) : "f"(x)); return r;
}
__device__ __forceinline__ u64 ffma2(u64 a, u64 b, u64 c) {
    u64 d; asm("fma.rn.f32x2 %0,%1,%2,%3;" : "=l"(d) : "l"(a), "l"(b), "l"(c)); return d;
}
__device__ __forceinline__ float2 up2(u64 v) {
    float2 f; asm("mov.b64 {%0,%1},%2;" : "=f"(f.x), "=f"(f.y) : "l"(v)); return f;
}

// ---------------- mma.sync helpers ----------------
__device__ __forceinline__ uint32_t smem_u32(const void* p) {
    uint32_t a; asm("{ .reg .u64 t; cvta.to.shared.u64 t, %1; cvt.u32.u64 %0, t; }"
                    : "=r"(a) : "l"(p)); return a;
}
__device__ __forceinline__ void ldsm_x4(uint32_t* r, uint32_t addr) {
    asm volatile("ldmatrix.sync.aligned.m8n8.x4.shared.b16 {%0,%1,%2,%3}, [%4];"
        : "=r"(r[0]), "=r"(r[1]), "=r"(r[2]), "=r"(r[3]) : "r"(addr));
}
__device__ __forceinline__ void ldsm_x4_t(uint32_t* r, uint32_t addr) {
    asm volatile("ldmatrix.sync.aligned.m8n8.x4.trans.shared.b16 {%0,%1,%2,%3}, [%4];"
        : "=r"(r[0]), "=r"(r[1]), "=r"(r[2]), "=r"(r[3]) : "r"(addr));
}
__device__ __forceinline__ void mma16816(float* d, const uint32_t* a, const uint32_t* b) {
    asm volatile("mma.sync.aligned.m16n8k16.row.col.f32.bf16.bf16.f32 "
        "{%0,%1,%2,%3}, {%4,%5,%6,%7}, {%8,%9}, {%0,%1,%2,%3};"
        : "+f"(d[0]), "+f"(d[1]), "+f"(d[2]), "+f"(d[3])
        : "r"(a[0]), "r"(a[1]), "r"(a[2]), "r"(a[3]), "r"(b[0]), "r"(b[1]));
}
__device__ __forceinline__ uint32_t pkbf2(float lo, float hi) {
    uint32_t r; asm("cvt.rn.bf16x2.f32 %0, %1, %2;" : "=r"(r) : "f"(hi), "f"(lo)); return r;
}

// ---------------- scratch ----------------
__device__ float g_deg[NNODES];
__device__ float g_agg[NNODES*FEAT];
__device__ float g_pooled[NB*FEAT];
__device__ float g_csum[NC*HID];
__device__ float g_meanh[NC*HID];
__device__ float g_h1[NC*FFD];
__device__ float g_h2[NC*HID];
__device__ float g_int[NC*HID];
__device__ float g_affacc[NC];
__device__ int   g_cs[NC+1];
__device__ __nv_bfloat16 g_Xhi[(size_t)PADROWS*HID];
__device__ __nv_bfloat16 g_Xlo[(size_t)PADROWS*HID];
__device__ __nv_bfloat16 g_Wthi[3*HID*HID];   // [w][n][k]
__device__ __nv_bfloat16 g_Wtlo[3*HID*HID];
__device__ __nv_bfloat16 g_Qhi[(size_t)NROWS*HID];
__device__ __nv_bfloat16 g_Qlo[(size_t)NROWS*HID];
__device__ __nv_bfloat16 g_Khi[(size_t)NROWS*HID];
__device__ __nv_bfloat16 g_Klo[(size_t)NROWS*HID];
__device__ __nv_bfloat16 g_Vhi[(size_t)NROWS*HID];

// ---------------- init: zero deg/agg/csum/affacc/X-pad, prefix counts ----------------
__global__ void k_init(const int* __restrict__ counts) {
    int i = blockIdx.x * blockDim.x + threadIdx.x;
    int nt = gridDim.x * blockDim.x;
    if (i < NNODES) g_deg[i] = 0.f;
    for (int j = i; j < NNODES*FEAT; j += nt) g_agg[j] = 0.f;
    if (i < NC*HID) g_csum[i] = 0.f;
    if (i < NC) g_affacc[i] = 0.f;
    // zero pad rows [NROWS, PADROWS) of Xhi/Xlo: 64*512 = 32768 elems
    if (i < (PADROWS - NROWS) * HID) {
        g_Xhi[(size_t)NROWS*HID + i] = __float2bfloat16(0.f);
        g_Xlo[(size_t)NROWS*HID + i] = __float2bfloat16(0.f);
    }
    if (i == 0) {
        int s = 0;
        for (int c = 0; c < NC; c++) { g_cs[c] = s; s += counts[c]; }
        g_cs[NC] = s;
    }
}

// ---------------- edge aggregation ----------------
__global__ void k_edges(const float* __restrict__ x, const int* __restrict__ ei) {
    int t = blockIdx.x * blockDim.x + threadIdx.x;
    int e = t >> 5, lane = t & 31;
    if (e >= NEDGES) return;
    int s = ei[e], d = ei[NEDGES + e];
    float4 v = *(const float4*)(x + (size_t)s*FEAT + lane*4);
    float* a = g_agg + (size_t)d*FEAT + lane*4;
    atomicAdd(a+0, v.x); atomicAdd(a+1, v.y);
    atomicAdd(a+2, v.z); atomicAdd(a+3, v.w);
    if (lane == 0) atomicAdd(g_deg + d, 1.f);
}

// ---------------- per-graph mean pool ----------------
__global__ void k_pool(const float* __restrict__ x) {
    int g = blockIdx.x, f = threadIdx.x;
    float s = 0.f;
    for (int n = g*64; n < g*64 + 64; n++) {
        float inv = 1.f / fmaxf(g_deg[n], 1.f);
        s += x[(size_t)n*FEAT + f] + g_agg[(size_t)n*FEAT + f] * inv;
    }
    g_pooled[g*FEAT + f] = s * (1.f/64.f);
}

// ---------------- per-gene GEMM (f32x2), emits bf16 hi/lo directly ----------------
__global__ void __launch_bounds__(256) k_gene(const float* __restrict__ gW,
                                              const float* __restrict__ gb) {
    int g = blockIdx.x, h0 = blockIdx.y * 128;
    __shared__ float sp[128][68];
    __shared__ float sw[16][128];
    for (int i = threadIdx.x; i < 64*32; i += 256) {
        int b = i >> 5, fq = i & 31;
        float4 v = *(const float4*)(g_pooled + b*FEAT + fq*4);
        sp[fq*4+0][b] = v.x; sp[fq*4+1][b] = v.y;
        sp[fq*4+2][b] = v.z; sp[fq*4+3][b] = v.w;
    }
    u64 acc2[4][4];
    #pragma unroll
    for (int i = 0; i < 4; i++)
        #pragma unroll
        for (int p = 0; p < 4; p++) acc2[i][p] = 0ull;
    int tb = (threadIdx.x & 15) * 4;
    int th = (threadIdx.x >> 4) * 8;
    const float* W = gW + (size_t)g*FEAT*HID + h0;
    int lr = threadIdx.x >> 4, lc = (threadIdx.x & 15) * 8;
    __syncthreads();
    for (int k0 = 0; k0 < 128; k0 += 16) {
        *(float4*)&sw[lr][lc]   = *(const float4*)(W + (size_t)(k0+lr)*HID + lc);
        *(float4*)&sw[lr][lc+4] = *(const float4*)(W + (size_t)(k0+lr)*HID + lc + 4);
        __syncthreads();
        #pragma unroll
        for (int kk = 0; kk < 16; kk++) {
            float4 a  = *(float4*)&sp[k0+kk][tb];
            u64 b2[4];
            b2[0] = *(u64*)&sw[kk][th];   b2[1] = *(u64*)&sw[kk][th+2];
            b2[2] = *(u64*)&sw[kk][th+4]; b2[3] = *(u64*)&sw[kk][th+6];
            float av[4] = {a.x,a.y,a.z,a.w};
            #pragma unroll
            for (int i = 0; i < 4; i++) {
                u64 ad = dup2(av[i]);
                #pragma unroll
                for (int p = 0; p < 4; p++) acc2[i][p] = ffma2(ad, b2[p], acc2[i][p]);
            }
        }
        __syncthreads();
    }
    #pragma unroll
    for (int i = 0; i < 4; i++) {
        int row = g*64 + tb + i, col = h0 + th;
        float2 f[4] = {up2(acc2[i][0]), up2(acc2[i][1]), up2(acc2[i][2]), up2(acc2[i][3])};
        const float* B = gb + (size_t)g*HID + col;
        float o[8];
        #pragma unroll
        for (int p = 0; p < 4; p++) {
            o[2*p]   = fmaxf(f[p].x + B[2*p],   0.f);
            o[2*p+1] = fmaxf(f[p].y + B[2*p+1], 0.f);
        }
        uint4 hv, lv;
        float hh[8];
        #pragma unroll
        for (int p = 0; p < 8; p++) hh[p] = __bfloat162float(__float2bfloat16(o[p]));
        hv.x = pkbf2(o[0],o[1]); hv.y = pkbf2(o[2],o[3]);
        hv.z = pkbf2(o[4],o[5]); hv.w = pkbf2(o[6],o[7]);
        lv.x = pkbf2(o[0]-hh[0],o[1]-hh[1]); lv.y = pkbf2(o[2]-hh[2],o[3]-hh[3]);
        lv.z = pkbf2(o[4]-hh[4],o[5]-hh[5]); lv.w = pkbf2(o[6]-hh[6],o[7]-hh[7]);
        *(uint4*)(g_Xhi + (size_t)row*HID + col) = hv;
        *(uint4*)(g_Xlo + (size_t)row*HID + col) = lv;
    }
}

// ---------------- transpose+convert W -> bf16 hi/lo [n][k] ----------------
__global__ void k_cvtW(const float* __restrict__ Wq, const float* __restrict__ Wk,
                       const float* __restrict__ Wv) {
    __shared__ float tile[32][33];
    int w = blockIdx.x;
    const float* W = (w == 0) ? Wq : (w == 1) ? Wk : Wv;
    int kb = blockIdx.y * 32, nb = blockIdx.z * 32;
    #pragma unroll
    for (int i = 0; i < 4; i++)
        tile[threadIdx.y + i*8][threadIdx.x] =
            W[(size_t)(kb + threadIdx.y + i*8)*HID + nb + threadIdx.x];
    __syncthreads();
    #pragma unroll
    for (int i = 0; i < 4; i++) {
        int n = nb + threadIdx.y + i*8, k = kb + threadIdx.x;
        float v = tile[threadIdx.x][threadIdx.y + i*8];
        __nv_bfloat16 h = __float2bfloat16(v);
        size_t o = (size_t)w*HID*HID + (size_t)n*HID + k;
        g_Wthi[o] = h;
        g_Wtlo[o] = __float2bfloat16(v - __bfloat162float(h));
    }
}

// ---------------- QKV GEMM via mma.sync bf16, outputs bf16 hi/lo ----------------
#define AHI 0
#define ALO 16384
#define BHI 32768
#define BLO 40960
#define QKV_SMEM 49152

__global__ void __launch_bounds__(256) k_qkv_mma(
        const float* __restrict__ bq, const float* __restrict__ bk,
        const float* __restrict__ bv) {
    extern __shared__ char smem[];
    uint32_t sb = smem_u32(smem);
    int tid = threadIdx.x;
    int wid = tid >> 5, lane = tid & 31;
    int m0 = blockIdx.x * 128;
    int nt = blockIdx.y;
    int wsel = nt >> 3, n0 = (nt & 7) * 64;
    const float* bias = (wsel == 0) ? bq : (wsel == 1) ? bk : bv;
    __nv_bfloat16* outhi = (wsel == 0) ? g_Qhi : (wsel == 1) ? g_Khi : g_Vhi;
    __nv_bfloat16* outlo = (wsel == 0) ? g_Qlo : (wsel == 1) ? g_Klo : (__nv_bfloat16*)0;
    const __nv_bfloat16* Bh = g_Wthi + (size_t)wsel*HID*HID;
    const __nv_bfloat16* Bl = g_Wtlo + (size_t)wsel*HID*HID;

    int wr = wid & 3, wc = wid >> 2;

    float acc[2][4][4];
    #pragma unroll
    for (int a = 0; a < 2; a++)
        #pragma unroll
        for (int b = 0; b < 4; b++)
            #pragma unroll
            for (int c = 0; c < 4; c++) acc[a][b][c] = 0.f;

    for (int ch = 0; ch < 8; ch++) {
        int k0 = ch * 64;
        __syncthreads();
        for (int u = tid; u < 1024; u += 256) {
            int row = u >> 3, c = u & 7;
            uint32_t dst = (uint32_t)(((row << 3) | (c ^ (row & 7))) << 4);
            size_t go = (size_t)(m0 + row)*HID + k0 + c*8;
            *(uint4*)(smem + AHI + dst) = *(const uint4*)(g_Xhi + go);
            *(uint4*)(smem + ALO + dst) = *(const uint4*)(g_Xlo + go);
        }
        for (int u = tid; u < 512; u += 256) {
            int row = u >> 3, c = u & 7;
            uint32_t dst = (uint32_t)(((row << 3) | (c ^ (row & 7))) << 4);
            size_t go = (size_t)(n0 + row)*HID + k0 + c*8;
            *(uint4*)(smem + BHI + dst) = *(const uint4*)(Bh + go);
            *(uint4*)(smem + BLO + dst) = *(const uint4*)(Bl + go);
        }
        __syncthreads();
        #pragma unroll
        for (int s = 0; s < 4; s++) {
            uint32_t ah[2][4], al[2][4];
            {
                int arow = wr*32 + (lane & 15);
                int ac   = s*2 + (lane >> 4);
                #pragma unroll
                for (int mt = 0; mt < 2; mt++) {
                    int r = arow + mt*16;
                    uint32_t off = (uint32_t)(((r << 3) | (ac ^ (r & 7))) << 4);
                    ldsm_x4(ah[mt], sb + AHI + off);
                    ldsm_x4(al[mt], sb + ALO + off);
                }
            }
            uint32_t bh[2][4], bl[2][4];
            {
                int brow = wc*32 + (lane & 7) + ((lane >> 4) << 3);
                int bc   = s*2 + ((lane >> 3) & 1);
                #pragma unroll
                for (int bt = 0; bt < 2; bt++) {
                    int r = brow + bt*16;
                    uint32_t off = (uint32_t)(((r << 3) | (bc ^ (r & 7))) << 4);
                    ldsm_x4(bh[bt], sb + BHI + off);
                    ldsm_x4(bl[bt], sb + BLO + off);
                }
            }
            #pragma unroll
            for (int mt = 0; mt < 2; mt++)
                #pragma unroll
                for (int n8 = 0; n8 < 4; n8++) {
                    const uint32_t* B0 = &bh[n8 >> 1][(n8 & 1) * 2];
                    const uint32_t* L0 = &bl[n8 >> 1][(n8 & 1) * 2];
                    mma16816(acc[mt][n8], ah[mt], B0);
                    mma16816(acc[mt][n8], ah[mt], L0);
                    mma16816(acc[mt][n8], al[mt], B0);
                }
        }
    }
    int rbase = m0 + wr*32 + (lane >> 2);
    int cbase = n0 + wc*32 + 2*(lane & 3);
    #pragma unroll
    for (int mt = 0; mt < 2; mt++) {
        #pragma unroll
        for (int n8 = 0; n8 < 4; n8++) {
            int col = cbase + n8*8;
            float b0 = bias[col], b1 = bias[col+1];
            #pragma unroll
            for (int half = 0; half < 2; half++) {
                int r0 = rbase + mt*16 + half*8;
                if (r0 >= NROWS) continue;
                float v0 = acc[mt][n8][half*2+0] + b0;
                float v1 = acc[mt][n8][half*2+1] + b1;
                float h0 = __bfloat162float(__float2bfloat16(v0));
                float h1 = __bfloat162float(__float2bfloat16(v1));
                *(uint32_t*)(outhi + (size_t)r0*HID + col) = pkbf2(v0, v1);
                if (outlo)
                    *(uint32_t*)(outlo + (size_t)r0*HID + col) = pkbf2(v0 - h0, v1 - h1);
            }
        }
    }
}

// ---------------- flash attention via mma.sync bf16, fused per-cell mean ----------------
#define AQH 0
#define AQL 8192
#define AKH 16384
#define AKL 24576
#define AVH 32768
#define ATTN_SMEM 40960

__global__ void __launch_bounds__(128) k_attn_mma(const int* __restrict__ cell_ids,
                                                  const int* __restrict__ counts) {
    extern __shared__ char smem[];
    uint32_t sb = smem_u32(smem);
    int g = blockIdx.x, h = blockIdx.y;
    int tid = threadIdx.x, wid = tid >> 5, lane = tid & 31;
    int c = cell_ids[g];
    int nt = counts[c];
    int ks0 = g_cs[c];

    for (int u = tid; u < 512; u += 128) {
        int row = u >> 3, ch = u & 7;
        uint32_t dst = (uint32_t)(((row << 3) | (ch ^ (row & 7))) << 4);
        size_t go = (size_t)(g*64 + row)*HID + h*64 + ch*8;
        *(uint4*)(smem + AQH + dst) = *(const uint4*)(g_Qhi + go);
        *(uint4*)(smem + AQL + dst) = *(const uint4*)(g_Qlo + go);
    }

    float oacc[8][4];
    #pragma unroll
    for (int t = 0; t < 8; t++)
        #pragma unroll
        for (int j = 0; j < 4; j++) oacc[t][j] = 0.f;
    float mA = -1e30f, mB = -1e30f, lA = 0.f, lB = 0.f;

    int arow = wid*16 + (lane & 15);

    for (int kt = 0; kt < nt; kt++) {
        int kg = ks0 + kt;
        __syncthreads();
        for (int u = tid; u < 512; u += 128) {
            int row = u >> 3, ch = u & 7;
            uint32_t dst = (uint32_t)(((row << 3) | (ch ^ (row & 7))) << 4);
            size_t go = (size_t)(kg*64 + row)*HID + h*64 + ch*8;
            *(uint4*)(smem + AKH + dst) = *(const uint4*)(g_Khi + go);
            *(uint4*)(smem + AKL + dst) = *(const uint4*)(g_Klo + go);
            *(uint4*)(smem + AVH + dst) = *(const uint4*)(g_Vhi + go);
        }
        __syncthreads();

        float sacc[8][4];
        #pragma unroll
        for (int t = 0; t < 8; t++)
            #pragma unroll
            for (int j = 0; j < 4; j++) sacc[t][j] = 0.f;
        #pragma unroll
        for (int s = 0; s < 4; s++) {
            int ac = s*2 + (lane >> 4);
            uint32_t aoff = (uint32_t)(((arow << 3) | (ac ^ (arow & 7))) << 4);
            uint32_t ah[4], al[4];
            ldsm_x4(ah, sb + AQH + aoff);
            ldsm_x4(al, sb + AQL + aoff);
            #pragma unroll
            for (int bt = 0; bt < 4; bt++) {
                int brow = bt*16 + (lane & 7) + ((lane >> 4) << 3);
                int bc   = s*2 + ((lane >> 3) & 1);
                uint32_t boff = (uint32_t)(((brow << 3) | (bc ^ (brow & 7))) << 4);
                uint32_t bh[4], bl[4];
                ldsm_x4(bh, sb + AKH + boff);
                ldsm_x4(bl, sb + AKL + boff);
                mma16816(sacc[bt*2],   ah, &bh[0]);
                mma16816(sacc[bt*2],   ah, &bl[0]);
                mma16816(sacc[bt*2],   al, &bh[0]);
                mma16816(sacc[bt*2+1], ah, &bh[2]);
                mma16816(sacc[bt*2+1], ah, &bl[2]);
                mma16816(sacc[bt*2+1], al, &bh[2]);
            }
        }
        float mtA = -1e30f, mtB = -1e30f;
        #pragma unroll
        for (int t = 0; t < 8; t++) {
            sacc[t][0] *= 0.125f; sacc[t][1] *= 0.125f;
            sacc[t][2] *= 0.125f; sacc[t][3] *= 0.125f;
            mtA = fmaxf(mtA, fmaxf(sacc[t][0], sacc[t][1]));
            mtB = fmaxf(mtB, fmaxf(sacc[t][2], sacc[t][3]));
        }
        mtA = fmaxf(mtA, __shfl_xor_sync(~0u, mtA, 1));
        mtA = fmaxf(mtA, __shfl_xor_sync(~0u, mtA, 2));
        mtB = fmaxf(mtB, __shfl_xor_sync(~0u, mtB, 1));
        mtB = fmaxf(mtB, __shfl_xor_sync(~0u, mtB, 2));
        float mnA = fmaxf(mA, mtA), mnB = fmaxf(mB, mtB);
        float alA = __expf(mA - mnA), alB = __expf(mB - mnB);
        float ltA = 0.f, ltB = 0.f;
        #pragma unroll
        for (int t = 0; t < 8; t++) {
            sacc[t][0] = __expf(sacc[t][0] - mnA);
            sacc[t][1] = __expf(sacc[t][1] - mnA);
            sacc[t][2] = __expf(sacc[t][2] - mnB);
            sacc[t][3] = __expf(sacc[t][3] - mnB);
            ltA += sacc[t][0] + sacc[t][1];
            ltB += sacc[t][2] + sacc[t][3];
        }
        ltA += __shfl_xor_sync(~0u, ltA, 1); ltA += __shfl_xor_sync(~0u, ltA, 2);
        ltB += __shfl_xor_sync(~0u, ltB, 1); ltB += __shfl_xor_sync(~0u, ltB, 2);
        lA = lA*alA + ltA; lB = lB*alB + ltB;
        mA = mnA; mB = mnB;
        #pragma unroll
        for (int t = 0; t < 8; t++) {
            oacc[t][0] *= alA; oacc[t][1] *= alA;
            oacc[t][2] *= alB; oacc[t][3] *= alB;
        }
        #pragma unroll
        for (int t2 = 0; t2 < 4; t2++) {
            uint32_t pa[4];
            pa[0] = pkbf2(sacc[2*t2][0],   sacc[2*t2][1]);
            pa[1] = pkbf2(sacc[2*t2][2],   sacc[2*t2][3]);
            pa[2] = pkbf2(sacc[2*t2+1][0], sacc[2*t2+1][1]);
            pa[3] = pkbf2(sacc[2*t2+1][2], sacc[2*t2+1][3]);
            int grp = lane >> 3;
            int vrow = t2*16 + (lane & 7) + ((grp & 1) << 3);
            #pragma unroll
            for (int dblk = 0; dblk < 4; dblk++) {
                int vch = dblk*2 + (grp >> 1);
                uint32_t voff = (uint32_t)(((vrow << 3) | (vch ^ (vrow & 7))) << 4);
                uint32_t vb[4];
                ldsm_x4_t(vb, sb + AVH + voff);
                mma16816(oacc[dblk*2],   pa, &vb[0]);
                mma16816(oacc[dblk*2+1], pa, &vb[2]);
            }
        }
    }
    // fused per-cell mean: scale rows by 1/l, sum this CTA's 64 rows, atomicAdd/S
    float invA = 1.f / lA, invB = 1.f / lB;
    float invS = 1.f / (float)(nt * 64);
    #pragma unroll
    for (int t = 0; t < 8; t++) {
        float s0 = oacc[t][0]*invA + oacc[t][2]*invB;
        float s1 = oacc[t][1]*invA + oacc[t][3]*invB;
        #pragma unroll
        for (int off = 4; off < 32; off <<= 1) {
            s0 += __shfl_xor_sync(~0u, s0, off);
            s1 += __shfl_xor_sync(~0u, s1, off);
        }
        if (lane < 4) {
            int col = h*64 + 2*lane + t*8;
            atomicAdd(g_csum + c*HID + col,     s0 * invS);
            atomicAdd(g_csum + c*HID + col + 1, s1 * invS);
        }
    }
}

// ---------------- per-cell vec-mat ----------------
template<int KDIM, int NCOL, int RELU, int SRC>
__global__ void k_vm(const float* __restrict__ W, const float* __restrict__ bias) {
    const float* vin  = (SRC == 0) ? g_csum  : (SRC == 1) ? g_meanh : g_h1;
    float*       vout = (SRC == 0) ? g_meanh : (SRC == 1) ? g_h1    : g_h2;
    int c = blockIdx.x;
    int n = blockIdx.y * 128 + threadIdx.x;
    __shared__ float a[KDIM];
    for (int k = threadIdx.x; k < KDIM; k += 128) a[k] = vin[c*KDIM + k];
    __syncthreads();
    float acc = bias[n];
    #pragma unroll 8
    for (int k = 0; k < KDIM; k++) acc += a[k] * W[(size_t)k*NCOL + n];
    vout[c*NCOL + n] = RELU ? fmaxf(acc, 0.f) : acc;
}

// ---------------- layernorm ----------------
__global__ void k_ln(const float* __restrict__ lng, const float* __restrict__ lnb,
                     float* __restrict__ out) {
    int c = blockIdx.x, t = threadIdx.x;
    __shared__ float sh[34];
    float v0 = g_h2[c*HID + t], v1 = g_h2[c*HID + 256 + t];
    int lane = t & 31, w = t >> 5;
    float s = v0 + v1;
    #pragma unroll
    for (int off = 16; off; off >>= 1) s += __shfl_xor_sync(~0u, s, off);
    if (lane == 0) sh[w] = s;
    __syncthreads();
    if (w == 0) {
        float tot = (t < 8) ? sh[t] : 0.f;
        #pragma unroll
        for (int off = 4; off; off >>= 1) tot += __shfl_xor_sync(~0u, tot, off);
        if (t == 0) sh[32] = tot;
    }
    __syncthreads();
    float mu = sh[32] * (1.f/512.f);
    float d0 = v0 - mu, d1 = v1 - mu;
    float q = d0*d0 + d1*d1;
    #pragma unroll
    for (int off = 16; off; off >>= 1) q += __shfl_xor_sync(~0u, q, off);
    if (lane == 0) sh[w] = q;
    __syncthreads();
    if (w == 0) {
        float tot = (t < 8) ? sh[t] : 0.f;
        #pragma unroll
        for (int off = 4; off; off >>= 1) tot += __shfl_xor_sync(~0u, tot, off);
        if (t == 0) sh[33] = tot;
    }
    __syncthreads();
    float inv = rsqrtf(sh[33] * (1.f/512.f) + 1e-5f);
    float r0 = d0*inv*lng[t]     + lnb[t];
    float r1 = d1*inv*lng[256+t] + lnb[256+t];
    g_int[c*HID + t]       = r0;
    g_int[c*HID + 256 + t] = r1;
    out[64 + c*HID + t]       = r0;
    out[64 + c*HID + 256 + t] = r1;
}

// ---------------- per-cell affinity head (4 blocks/cell) ----------------
__global__ void k_aff(const float* __restrict__ Aw1, const float* __restrict__ Ab1,
                      const float* __restrict__ Aw2) {
    int c = blockIdx.x;
    int k = blockIdx.y * 128 + threadIdx.x;
    __shared__ float a[HID];
    __shared__ float red[4];
    for (int j = threadIdx.x; j < HID; j += 128) a[j] = g_int[c*HID + j];
    __syncthreads();
    float acc = Ab1[c*HID + k];
    const float* W = Aw1 + (size_t)c*HID*HID + k;
    #pragma unroll 8
    for (int j = 0; j < HID; j++) acc += a[j] * W[(size_t)j*HID];
    float part = fmaxf(acc, 0.f) * Aw2[c*HID + k];
    int lane = threadIdx.x & 31, w = threadIdx.x >> 5;
    #pragma unroll
    for (int off = 16; off; off >>= 1) part += __shfl_xor_sync(~0u, part, off);
    if (lane == 0) red[w] = part;
    __syncthreads();
    if (threadIdx.x == 0)
        atomicAdd(&g_affacc[c], red[0] + red[1] + red[2] + red[3]);
}

__global__ void k_sig(const float* __restrict__ Ab2, float* __restrict__ out) {
    int c = threadIdx.x;
    out[c] = 1.f / (1.f + expf(-(g_affacc[c] + Ab2[c])));
}

extern "C" void kernel_launch(void* const* d_in, const int* in_sizes, int n_in,
                              void* d_out, int out_size) {
    const float* x       = (const float*)d_in[0];
    const int*   ei      = (const int*)  d_in[1];
    const float* gene_W  = (const float*)d_in[3];
    const float* gene_b  = (const float*)d_in[4];
    const int*   cell_ids= (const int*)  d_in[5];
    const int*   counts  = (const int*)  d_in[7];
    const float* Wq = (const float*)d_in[8],  *bq = (const float*)d_in[9];
    const float* Wk = (const float*)d_in[10], *bk = (const float*)d_in[11];
    const float* Wv = (const float*)d_in[12], *bv = (const float*)d_in[13];
    const float* Wo = (const float*)d_in[14], *bo = (const float*)d_in[15];
    const float* Wi1= (const float*)d_in[16], *bi1= (const float*)d_in[17];
    const float* Wi2= (const float*)d_in[18], *bi2= (const float*)d_in[19];
    const float* lng= (const float*)d_in[20], *lnb= (const float*)d_in[21];
    const float* Aw1= (const float*)d_in[22], *Ab1= (const float*)d_in[23];
    const float* Aw2= (const float*)d_in[24], *Ab2= (const float*)d_in[25];
    float* out = (float*)d_out;

    cudaFuncSetAttribute(k_attn_mma, cudaFuncAttributeMaxDynamicSharedMemorySize, ATTN_SMEM);
    cudaFuncSetAttribute(k_qkv_mma, cudaFuncAttributeMaxDynamicSharedMemorySize, QKV_SMEM);

    k_init <<<256, 256>>>(counts);
    k_edges<<<(NEDGES*32)/256, 256>>>(x, ei);
    k_pool <<<NB, 128>>>(x);
    k_gene <<<dim3(NG, 4), 256>>>(gene_W, gene_b);
    k_cvtW <<<dim3(3, 16, 16), dim3(32, 8)>>>(Wq, Wk, Wv);
    k_qkv_mma<<<dim3(MTILES, 24), 256, QKV_SMEM>>>(bq, bk, bv);
    k_attn_mma<<<dim3(NG, 8), 128, ATTN_SMEM>>>(cell_ids, counts);
    k_vm<512, 512, 0, 0><<<dim3(NC, 4), 128>>>(Wo,  bo);
    k_vm<512,1024, 1, 1><<<dim3(NC, 8), 128>>>(Wi1, bi1);
    k_vm<1024,512, 0, 2><<<dim3(NC, 4), 128>>>(Wi2, bi2);
    k_ln  <<<NC, 256>>>(lng, lnb, out);
    k_aff <<<dim3(NC, 4), 128>>>(Aw1, Ab1, Aw2);
    k_sig <<<1, NC>>>(Ab2, out);
}

// round 8
// speedup vs baseline: 2.5015x; 1.2121x over previous
#include <cuda_runtime.h>
#include <cuda_bf16.h>
#include <math.h>
#include <cstdint>

#define NNODES 4096
#define FEAT   128
#define NEDGES 65536
#define NG     317
#define NB     64
#define NC     64
#define HID    512
#define DH     64
#define NROWS  (NG*NB)
#define FFD    1024
#define MTILES 159
#define PADROWS (MTILES*128)

typedef unsigned long long u64;

// ---------------- f32x2 helpers ----------------
__device__ __forceinline__ u64 dup2(float x) {
    u64 r; asm("mov.b64 %0,{%1,%1};" : "=l"(r) : "f"(x)); return r;
}
__device__ __forceinline__ u64 ffma2(u64 a, u64 b, u64 c) {
    u64 d; asm("fma.rn.f32x2 %0,%1,%2,%3;" : "=l"(d) : "l"(a), "l"(b), "l"(c)); return d;
}
__device__ __forceinline__ float2 up2(u64 v) {
    float2 f; asm("mov.b64 {%0,%1},%2;" : "=f"(f.x), "=f"(f.y) : "l"(v)); return f;
}

// ---------------- mma.sync helpers ----------------
__device__ __forceinline__ uint32_t smem_u32(const void* p) {
    uint32_t a; asm("{ .reg .u64 t; cvta.to.shared.u64 t, %1; cvt.u32.u64 %0, t; }"
                    : "=r"(a) : "l"(p)); return a;
}
__device__ __forceinline__ void ldsm_x4(uint32_t* r, uint32_t addr) {
    asm volatile("ldmatrix.sync.aligned.m8n8.x4.shared.b16 {%0,%1,%2,%3}, [%4];"
        : "=r"(r[0]), "=r"(r[1]), "=r"(r[2]), "=r"(r[3]) : "r"(addr));
}
__device__ __forceinline__ void ldsm_x4_t(uint32_t* r, uint32_t addr) {
    asm volatile("ldmatrix.sync.aligned.m8n8.x4.trans.shared.b16 {%0,%1,%2,%3}, [%4];"
        : "=r"(r[0]), "=r"(r[1]), "=r"(r[2]), "=r"(r[3]) : "r"(addr));
}
__device__ __forceinline__ void mma16816(float* d, const uint32_t* a, const uint32_t* b) {
    asm volatile("mma.sync.aligned.m16n8k16.row.col.f32.bf16.bf16.f32 "
        "{%0,%1,%2,%3}, {%4,%5,%6,%7}, {%8,%9}, {%0,%1,%2,%3};"
        : "+f"(d[0]), "+f"(d[1]), "+f"(d[2]), "+f"(d[3])
        : "r"(a[0]), "r"(a[1]), "r"(a[2]), "r"(a[3]), "r"(b[0]), "r"(b[1]));
}
__device__ __forceinline__ uint32_t pkbf2(float lo, float hi) {
    uint32_t r; asm("cvt.rn.bf16x2.f32 %0, %1, %2;" : "=r"(r) : "f"(hi), "f"(lo)); return r;
}

// ---------------- scratch ----------------
__device__ float g_deg[NNODES];
__device__ float g_agg[NNODES*FEAT];
__device__ float g_csum[NC*HID];
__device__ float g_meanh[NC*HID];
__device__ float g_h1[NC*FFD];
__device__ float g_h2[NC*HID];
__device__ float g_int[NC*HID];
__device__ float g_affacc[NC];
__device__ int   g_cs[NC+1];
__device__ __nv_bfloat16 g_ph[NB*FEAT];
__device__ __nv_bfloat16 g_pl[NB*FEAT];
__device__ __nv_bfloat16 g_Xhi[(size_t)PADROWS*HID];
__device__ __nv_bfloat16 g_Xlo[(size_t)PADROWS*HID];
__device__ __nv_bfloat16 g_Wthi[3*HID*HID];   // [w][n][k]
__device__ __nv_bfloat16 g_Wtlo[3*HID*HID];
__device__ __nv_bfloat16 g_Qhi[(size_t)NROWS*HID];
__device__ __nv_bfloat16 g_Qlo[(size_t)NROWS*HID];
__device__ __nv_bfloat16 g_Khi[(size_t)NROWS*HID];
__device__ __nv_bfloat16 g_Klo[(size_t)NROWS*HID];
__device__ __nv_bfloat16 g_Vhi[(size_t)NROWS*HID];

// ---------------- init ----------------
__global__ void k_init(const int* __restrict__ counts) {
    int i = blockIdx.x * blockDim.x + threadIdx.x;
    int nt = gridDim.x * blockDim.x;
    if (i < NNODES) g_deg[i] = 0.f;
    for (int j = i; j < NNODES*FEAT; j += nt) g_agg[j] = 0.f;
    if (i < NC*HID) { g_csum[i] = 0.f; g_meanh[i] = 0.f; g_h2[i] = 0.f; }
    for (int j = i; j < NC*FFD; j += nt) g_h1[j] = 0.f;
    if (i < NC) g_affacc[i] = 0.f;
    if (i < (PADROWS - NROWS) * HID) {
        g_Xhi[(size_t)NROWS*HID + i] = __float2bfloat16(0.f);
        g_Xlo[(size_t)NROWS*HID + i] = __float2bfloat16(0.f);
    }
    if (i == 0) {
        int s = 0;
        for (int c = 0; c < NC; c++) { g_cs[c] = s; s += counts[c]; }
        g_cs[NC] = s;
    }
}

// ---------------- edge aggregation ----------------
__global__ void k_edges(const float* __restrict__ x, const int* __restrict__ ei) {
    int t = blockIdx.x * blockDim.x + threadIdx.x;
    int e = t >> 5, lane = t & 31;
    if (e >= NEDGES) return;
    int s = ei[e], d = ei[NEDGES + e];
    float4 v = *(const float4*)(x + (size_t)s*FEAT + lane*4);
    float* a = g_agg + (size_t)d*FEAT + lane*4;
    atomicAdd(a+0, v.x); atomicAdd(a+1, v.y);
    atomicAdd(a+2, v.z); atomicAdd(a+3, v.w);
    if (lane == 0) atomicAdd(g_deg + d, 1.f);
}

// ---------------- per-graph mean pool -> bf16 hi/lo ----------------
__global__ void k_pool(const float* __restrict__ x) {
    int g = blockIdx.x, f = threadIdx.x;
    float s = 0.f;
    for (int n = g*64; n < g*64 + 64; n++) {
        float inv = 1.f / fmaxf(g_deg[n], 1.f);
        s += x[(size_t)n*FEAT + f] + g_agg[(size_t)n*FEAT + f] * inv;
    }
    s *= (1.f/64.f);
    __nv_bfloat16 h = __float2bfloat16(s);
    g_ph[g*FEAT + f] = h;
    g_pl[g*FEAT + f] = __float2bfloat16(s - __bfloat162float(h));
}

// ---------------- per-gene GEMM via mma.sync bf16 (compensated) ----------------
// CTA = (gene, 128-col n-block). A = pooled[64,128] (hi/lo), B = gene_W[g][k][n]
// converted fp32->bf16 hi/lo in-flight. Emits g_Xhi/g_Xlo.
#define GAH 0
#define GAL 8192
#define GBH 16384
#define GBL 32768
#define GENE_SMEM 49152

__global__ void __launch_bounds__(256) k_gene_mma(const float* __restrict__ gW,
                                                  const float* __restrict__ gb) {
    extern __shared__ char smem[];
    uint32_t sb = smem_u32(smem);
    int tid = threadIdx.x, wid = tid >> 5, lane = tid & 31;
    int g = blockIdx.x, n0 = blockIdx.y * 128;
    int wr = wid & 3, wc = wid >> 2;   // warp: rows wr*16..+15, cols wc*64..+63

    float acc[8][4];
    #pragma unroll
    for (int t = 0; t < 8; t++)
        #pragma unroll
        for (int j = 0; j < 4; j++) acc[t][j] = 0.f;

    for (int ch = 0; ch < 2; ch++) {
        int k0 = ch * 64;
        __syncthreads();
        // A: pooled hi/lo, 64 rows x 8 chunks (row = graph/cell-batch index)
        for (int u = tid; u < 512; u += 256) {
            int row = u >> 3, c = u & 7;
            uint32_t dst = (uint32_t)(((row << 3) | (c ^ (row & 7))) << 4);
            int go = row*FEAT + k0 + c*8;
            *(uint4*)(smem + GAH + dst) = *(const uint4*)(g_ph + go);
            *(uint4*)(smem + GAL + dst) = *(const uint4*)(g_pl + go);
        }
        // B: gene_W fp32 -> bf16 hi/lo, [64 k-rows][128 n], 16-chunk rows
        for (int u = tid; u < 1024; u += 256) {
            int row = u >> 4, c = u & 15;
            const float* src = gW + (size_t)g*FEAT*HID + (size_t)(k0+row)*HID + n0 + c*8;
            float4 f0 = *(const float4*)src;
            float4 f1 = *(const float4*)(src + 4);
            float v[8] = {f0.x,f0.y,f0.z,f0.w,f1.x,f1.y,f1.z,f1.w};
            float hh[8];
            #pragma unroll
            for (int p = 0; p < 8; p++) hh[p] = __bfloat162float(__float2bfloat16(v[p]));
            uint4 hv, lv;
            hv.x = pkbf2(v[0],v[1]); hv.y = pkbf2(v[2],v[3]);
            hv.z = pkbf2(v[4],v[5]); hv.w = pkbf2(v[6],v[7]);
            lv.x = pkbf2(v[0]-hh[0],v[1]-hh[1]); lv.y = pkbf2(v[2]-hh[2],v[3]-hh[3]);
            lv.z = pkbf2(v[4]-hh[4],v[5]-hh[5]); lv.w = pkbf2(v[6]-hh[6],v[7]-hh[7]);
            uint32_t dst = (uint32_t)(((row << 4) | (c ^ (row & 7))) << 4);
            *(uint4*)(smem + GBH + dst) = hv;
            *(uint4*)(smem + GBL + dst) = lv;
        }
        __syncthreads();
        #pragma unroll
        for (int s = 0; s < 4; s++) {
            int arow = wr*16 + (lane & 15);
            int ac   = s*2 + (lane >> 4);
            uint32_t aoff = (uint32_t)(((arow << 3) | (ac ^ (arow & 7))) << 4);
            uint32_t ah[4], al[4];
            ldsm_x4(ah, sb + GAH + aoff);
            ldsm_x4(al, sb + GAL + aoff);
            int grp = lane >> 3;
            int vrow = s*16 + (lane & 7) + ((grp & 1) << 3);
            #pragma unroll
            for (int dblk = 0; dblk < 4; dblk++) {
                int vch = wc*8 + dblk*2 + (grp >> 1);
                uint32_t voff = (uint32_t)(((vrow << 4) | (vch ^ (vrow & 7))) << 4);
                uint32_t vbh[4], vbl[4];
                ldsm_x4_t(vbh, sb + GBH + voff);
                ldsm_x4_t(vbl, sb + GBL + voff);
                mma16816(acc[dblk*2],   ah, &vbh[0]);
                mma16816(acc[dblk*2],   ah, &vbl[0]);
                mma16816(acc[dblk*2],   al, &vbh[0]);
                mma16816(acc[dblk*2+1], ah, &vbh[2]);
                mma16816(acc[dblk*2+1], ah, &vbl[2]);
                mma16816(acc[dblk*2+1], al, &vbh[2]);
            }
        }
    }
    // epilogue: bias + relu -> bf16 hi/lo
    int row0 = wr*16 + (lane >> 2);
    int cb = n0 + wc*64 + 2*(lane & 3);
    #pragma unroll
    for (int n8 = 0; n8 < 8; n8++) {
        int col = cb + n8*8;
        float b0 = gb[(size_t)g*HID + col], b1 = gb[(size_t)g*HID + col + 1];
        #pragma unroll
        for (int half = 0; half < 2; half++) {
            int row = g*64 + row0 + half*8;
            float v0 = fmaxf(acc[n8][half*2+0] + b0, 0.f);
            float v1 = fmaxf(acc[n8][half*2+1] + b1, 0.f);
            float h0 = __bfloat162float(__float2bfloat16(v0));
            float h1 = __bfloat162float(__float2bfloat16(v1));
            *(uint32_t*)(g_Xhi + (size_t)row*HID + col) = pkbf2(v0, v1);
            *(uint32_t*)(g_Xlo + (size_t)row*HID + col) = pkbf2(v0 - h0, v1 - h1);
        }
    }
}

// ---------------- transpose+convert W -> bf16 hi/lo [n][k] ----------------
__global__ void k_cvtW(const float* __restrict__ Wq, const float* __restrict__ Wk,
                       const float* __restrict__ Wv) {
    __shared__ float tile[32][33];
    int w = blockIdx.x;
    const float* W = (w == 0) ? Wq : (w == 1) ? Wk : Wv;
    int kb = blockIdx.y * 32, nb = blockIdx.z * 32;
    #pragma unroll
    for (int i = 0; i < 4; i++)
        tile[threadIdx.y + i*8][threadIdx.x] =
            W[(size_t)(kb + threadIdx.y + i*8)*HID + nb + threadIdx.x];
    __syncthreads();
    #pragma unroll
    for (int i = 0; i < 4; i++) {
        int n = nb + threadIdx.y + i*8, k = kb + threadIdx.x;
        float v = tile[threadIdx.x][threadIdx.y + i*8];
        __nv_bfloat16 h = __float2bfloat16(v);
        size_t o = (size_t)w*HID*HID + (size_t)n*HID + k;
        g_Wthi[o] = h;
        g_Wtlo[o] = __float2bfloat16(v - __bfloat162float(h));
    }
}

// ---------------- QKV GEMM via mma.sync bf16, outputs bf16 hi/lo ----------------
#define AHI 0
#define ALO 16384
#define BHI 32768
#define BLO 40960
#define QKV_SMEM 49152

__global__ void __launch_bounds__(256) k_qkv_mma(
        const float* __restrict__ bq, const float* __restrict__ bk,
        const float* __restrict__ bv) {
    extern __shared__ char smem[];
    uint32_t sb = smem_u32(smem);
    int tid = threadIdx.x;
    int wid = tid >> 5, lane = tid & 31;
    int m0 = blockIdx.x * 128;
    int nt = blockIdx.y;
    int wsel = nt >> 3, n0 = (nt & 7) * 64;
    const float* bias = (wsel == 0) ? bq : (wsel == 1) ? bk : bv;
    __nv_bfloat16* outhi = (wsel == 0) ? g_Qhi : (wsel == 1) ? g_Khi : g_Vhi;
    __nv_bfloat16* outlo = (wsel == 0) ? g_Qlo : (wsel == 1) ? g_Klo : (__nv_bfloat16*)0;
    const __nv_bfloat16* Bh = g_Wthi + (size_t)wsel*HID*HID;
    const __nv_bfloat16* Bl = g_Wtlo + (size_t)wsel*HID*HID;

    int wr = wid & 3, wc = wid >> 2;

    float acc[2][4][4];
    #pragma unroll
    for (int a = 0; a < 2; a++)
        #pragma unroll
        for (int b = 0; b < 4; b++)
            #pragma unroll
            for (int c = 0; c < 4; c++) acc[a][b][c] = 0.f;

    for (int ch = 0; ch < 8; ch++) {
        int k0 = ch * 64;
        __syncthreads();
        for (int u = tid; u < 1024; u += 256) {
            int row = u >> 3, c = u & 7;
            uint32_t dst = (uint32_t)(((row << 3) | (c ^ (row & 7))) << 4);
            size_t go = (size_t)(m0 + row)*HID + k0 + c*8;
            *(uint4*)(smem + AHI + dst) = *(const uint4*)(g_Xhi + go);
            *(uint4*)(smem + ALO + dst) = *(const uint4*)(g_Xlo + go);
        }
        for (int u = tid; u < 512; u += 256) {
            int row = u >> 3, c = u & 7;
            uint32_t dst = (uint32_t)(((row << 3) | (c ^ (row & 7))) << 4);
            size_t go = (size_t)(n0 + row)*HID + k0 + c*8;
            *(uint4*)(smem + BHI + dst) = *(const uint4*)(Bh + go);
            *(uint4*)(smem + BLO + dst) = *(const uint4*)(Bl + go);
        }
        __syncthreads();
        #pragma unroll
        for (int s = 0; s < 4; s++) {
            uint32_t ah[2][4], al[2][4];
            {
                int arow = wr*32 + (lane & 15);
                int ac   = s*2 + (lane >> 4);
                #pragma unroll
                for (int mt = 0; mt < 2; mt++) {
                    int r = arow + mt*16;
                    uint32_t off = (uint32_t)(((r << 3) | (ac ^ (r & 7))) << 4);
                    ldsm_x4(ah[mt], sb + AHI + off);
                    ldsm_x4(al[mt], sb + ALO + off);
                }
            }
            uint32_t bh[2][4], bl[2][4];
            {
                int brow = wc*32 + (lane & 7) + ((lane >> 4) << 3);
                int bc   = s*2 + ((lane >> 3) & 1);
                #pragma unroll
                for (int bt = 0; bt < 2; bt++) {
                    int r = brow + bt*16;
                    uint32_t off = (uint32_t)(((r << 3) | (bc ^ (r & 7))) << 4);
                    ldsm_x4(bh[bt], sb + BHI + off);
                    ldsm_x4(bl[bt], sb + BLO + off);
                }
            }
            #pragma unroll
            for (int mt = 0; mt < 2; mt++)
                #pragma unroll
                for (int n8 = 0; n8 < 4; n8++) {
                    const uint32_t* B0 = &bh[n8 >> 1][(n8 & 1) * 2];
                    const uint32_t* L0 = &bl[n8 >> 1][(n8 & 1) * 2];
                    mma16816(acc[mt][n8], ah[mt], B0);
                    mma16816(acc[mt][n8], ah[mt], L0);
                    mma16816(acc[mt][n8], al[mt], B0);
                }
        }
    }
    int rbase = m0 + wr*32 + (lane >> 2);
    int cbase = n0 + wc*32 + 2*(lane & 3);
    #pragma unroll
    for (int mt = 0; mt < 2; mt++) {
        #pragma unroll
        for (int n8 = 0; n8 < 4; n8++) {
            int col = cbase + n8*8;
            float b0 = bias[col], b1 = bias[col+1];
            #pragma unroll
            for (int half = 0; half < 2; half++) {
                int r0 = rbase + mt*16 + half*8;
                if (r0 >= NROWS) continue;
                float v0 = acc[mt][n8][half*2+0] + b0;
                float v1 = acc[mt][n8][half*2+1] + b1;
                float h0 = __bfloat162float(__float2bfloat16(v0));
                float h1 = __bfloat162float(__float2bfloat16(v1));
                *(uint32_t*)(outhi + (size_t)r0*HID + col) = pkbf2(v0, v1);
                if (outlo)
                    *(uint32_t*)(outlo + (size_t)r0*HID + col) = pkbf2(v0 - h0, v1 - h1);
            }
        }
    }
}

// ---------------- flash attention via mma.sync bf16, fused per-cell mean ----------------
#define AQH 0
#define AQL 8192
#define AKH 16384
#define AKL 24576
#define AVH 32768
#define ATTN_SMEM 40960

__global__ void __launch_bounds__(128) k_attn_mma(const int* __restrict__ cell_ids,
                                                  const int* __restrict__ counts) {
    extern __shared__ char smem[];
    uint32_t sb = smem_u32(smem);
    int g = blockIdx.x, h = blockIdx.y;
    int tid = threadIdx.x, wid = tid >> 5, lane = tid & 31;
    int c = cell_ids[g];
    int nt = counts[c];
    int ks0 = g_cs[c];

    for (int u = tid; u < 512; u += 128) {
        int row = u >> 3, ch = u & 7;
        uint32_t dst = (uint32_t)(((row << 3) | (ch ^ (row & 7))) << 4);
        size_t go = (size_t)(g*64 + row)*HID + h*64 + ch*8;
        *(uint4*)(smem + AQH + dst) = *(const uint4*)(g_Qhi + go);
        *(uint4*)(smem + AQL + dst) = *(const uint4*)(g_Qlo + go);
    }

    float oacc[8][4];
    #pragma unroll
    for (int t = 0; t < 8; t++)
        #pragma unroll
        for (int j = 0; j < 4; j++) oacc[t][j] = 0.f;
    float mA = -1e30f, mB = -1e30f, lA = 0.f, lB = 0.f;

    int arow = wid*16 + (lane & 15);

    for (int kt = 0; kt < nt; kt++) {
        int kg = ks0 + kt;
        __syncthreads();
        for (int u = tid; u < 512; u += 128) {
            int row = u >> 3, ch = u & 7;
            uint32_t dst = (uint32_t)(((row << 3) | (ch ^ (row & 7))) << 4);
            size_t go = (size_t)(kg*64 + row)*HID + h*64 + ch*8;
            *(uint4*)(smem + AKH + dst) = *(const uint4*)(g_Khi + go);
            *(uint4*)(smem + AKL + dst) = *(const uint4*)(g_Klo + go);
            *(uint4*)(smem + AVH + dst) = *(const uint4*)(g_Vhi + go);
        }
        __syncthreads();

        float sacc[8][4];
        #pragma unroll
        for (int t = 0; t < 8; t++)
            #pragma unroll
            for (int j = 0; j < 4; j++) sacc[t][j] = 0.f;
        #pragma unroll
        for (int s = 0; s < 4; s++) {
            int ac = s*2 + (lane >> 4);
            uint32_t aoff = (uint32_t)(((arow << 3) | (ac ^ (arow & 7))) << 4);
            uint32_t ah[4], al[4];
            ldsm_x4(ah, sb + AQH + aoff);
            ldsm_x4(al, sb + AQL + aoff);
            #pragma unroll
            for (int bt = 0; bt < 4; bt++) {
                int brow = bt*16 + (lane & 7) + ((lane >> 4) << 3);
                int bc   = s*2 + ((lane >> 3) & 1);
                uint32_t boff = (uint32_t)(((brow << 3) | (bc ^ (brow & 7))) << 4);
                uint32_t bh[4], bl[4];
                ldsm_x4(bh, sb + AKH + boff);
                ldsm_x4(bl, sb + AKL + boff);
                mma16816(sacc[bt*2],   ah, &bh[0]);
                mma16816(sacc[bt*2],   ah, &bl[0]);
                mma16816(sacc[bt*2],   al, &bh[0]);
                mma16816(sacc[bt*2+1], ah, &bh[2]);
                mma16816(sacc[bt*2+1], ah, &bl[2]);
                mma16816(sacc[bt*2+1], al, &bh[2]);
            }
        }
        float mtA = -1e30f, mtB = -1e30f;
        #pragma unroll
        for (int t = 0; t < 8; t++) {
            sacc[t][0] *= 0.125f; sacc[t][1] *= 0.125f;
            sacc[t][2] *= 0.125f; sacc[t][3] *= 0.125f;
            mtA = fmaxf(mtA, fmaxf(sacc[t][0], sacc[t][1]));
            mtB = fmaxf(mtB, fmaxf(sacc[t][2], sacc[t][3]));
        }
        mtA = fmaxf(mtA, __shfl_xor_sync(~0u, mtA, 1));
        mtA = fmaxf(mtA, __shfl_xor_sync(~0u, mtA, 2));
        mtB = fmaxf(mtB, __shfl_xor_sync(~0u, mtB, 1));
        mtB = fmaxf(mtB, __shfl_xor_sync(~0u, mtB, 2));
        float mnA = fmaxf(mA, mtA), mnB = fmaxf(mB, mtB);
        float alA = __expf(mA - mnA), alB = __expf(mB - mnB);
        float ltA = 0.f, ltB = 0.f;
        #pragma unroll
        for (int t = 0; t < 8; t++) {
            sacc[t][0] = __expf(sacc[t][0] - mnA);
            sacc[t][1] = __expf(sacc[t][1] - mnA);
            sacc[t][2] = __expf(sacc[t][2] - mnB);
            sacc[t][3] = __expf(sacc[t][3] - mnB);
            ltA += sacc[t][0] + sacc[t][1];
            ltB += sacc[t][2] + sacc[t][3];
        }
        ltA += __shfl_xor_sync(~0u, ltA, 1); ltA += __shfl_xor_sync(~0u, ltA, 2);
        ltB += __shfl_xor_sync(~0u, ltB, 1); ltB += __shfl_xor_sync(~0u, ltB, 2);
        lA = lA*alA + ltA; lB = lB*alB + ltB;
        mA = mnA; mB = mnB;
        #pragma unroll
        for (int t = 0; t < 8; t++) {
            oacc[t][0] *= alA; oacc[t][1] *= alA;
            oacc[t][2] *= alB; oacc[t][3] *= alB;
        }
        #pragma unroll
        for (int t2 = 0; t2 < 4; t2++) {
            uint32_t pa[4];
            pa[0] = pkbf2(sacc[2*t2][0],   sacc[2*t2][1]);
            pa[1] = pkbf2(sacc[2*t2][2],   sacc[2*t2][3]);
            pa[2] = pkbf2(sacc[2*t2+1][0], sacc[2*t2+1][1]);
            pa[3] = pkbf2(sacc[2*t2+1][2], sacc[2*t2+1][3]);
            int grp = lane >> 3;
            int vrow = t2*16 + (lane & 7) + ((grp & 1) << 3);
            #pragma unroll
            for (int dblk = 0; dblk < 4; dblk++) {
                int vch = dblk*2 + (grp >> 1);
                uint32_t voff = (uint32_t)(((vrow << 3) | (vch ^ (vrow & 7))) << 4);
                uint32_t vb[4];
                ldsm_x4_t(vb, sb + AVH + voff);
                mma16816(oacc[dblk*2],   pa, &vb[0]);
                mma16816(oacc[dblk*2+1], pa, &vb[2]);
            }
        }
    }
    float invA = 1.f / lA, invB = 1.f / lB;
    float invS = 1.f / (float)(nt * 64);
    #pragma unroll
    for (int t = 0; t < 8; t++) {
        float s0 = oacc[t][0]*invA + oacc[t][2]*invB;
        float s1 = oacc[t][1]*invA + oacc[t][3]*invB;
        #pragma unroll
        for (int off = 4; off < 32; off <<= 1) {
            s0 += __shfl_xor_sync(~0u, s0, off);
            s1 += __shfl_xor_sync(~0u, s1, off);
        }
        if (lane < 4) {
            int col = h*64 + 2*lane + t*8;
            atomicAdd(g_csum + c*HID + col,     s0 * invS);
            atomicAdd(g_csum + c*HID + col + 1, s1 * invS);
        }
    }
}

// ---------------- k-split batched vec-mat: vout += A[64,128slice] @ W ----------------
// grid (NCOL/64, KDIM/128). Bias added by k-block 0. Optional relu on input read.
template<int KDIM, int NCOL, int RELUIN, int SRC>
__global__ void __launch_bounds__(256) k_vm2(const float* __restrict__ W,
                                             const float* __restrict__ bias) {
    const float* vin  = (SRC == 0) ? g_csum  : (SRC == 1) ? g_meanh : g_h1;
    float*       vout = (SRC == 0) ? g_meanh : (SRC == 1) ? g_h1    : g_h2;
    int n0 = blockIdx.x * 64, kb = blockIdx.y * 128;
    int tid = threadIdx.x;
    __shared__ float sp[128][68];  // A^T: [k local][cell]
    __shared__ float sw[16][68];
    for (int u = tid; u < 2048; u += 256) {
        int c = u >> 5, kq = (u & 31) * 4;
        float4 v = *(const float4*)(vin + c*KDIM + kb + kq);
        if (RELUIN) {
            v.x = fmaxf(v.x, 0.f); v.y = fmaxf(v.y, 0.f);
            v.z = fmaxf(v.z, 0.f); v.w = fmaxf(v.w, 0.f);
        }
        sp[kq+0][c] = v.x; sp[kq+1][c] = v.y;
        sp[kq+2][c] = v.z; sp[kq+3][c] = v.w;
    }
    u64 acc2[4][2];
    #pragma unroll
    for (int i = 0; i < 4; i++) { acc2[i][0] = 0ull; acc2[i][1] = 0ull; }
    int tb = (tid & 15) * 4;   // cells
    int th = (tid >> 4) * 4;   // n
    int lr = tid >> 4, lc = (tid & 15) * 4;
    __syncthreads();
    for (int k0 = 0; k0 < 128; k0 += 16) {
        *(float4*)&sw[lr][lc] = *(const float4*)(W + (size_t)(kb + k0 + lr)*NCOL + n0 + lc);
        __syncthreads();
        #pragma unroll
        for (int kk = 0; kk < 16; kk++) {
            float4 a = *(float4*)&sp[k0+kk][tb];
            u64 b0 = *(u64*)&sw[kk][th];
            u64 b1 = *(u64*)&sw[kk][th+2];
            float av[4] = {a.x, a.y, a.z, a.w};
            #pragma unroll
            for (int i = 0; i < 4; i++) {
                u64 ad = dup2(av[i]);
                acc2[i][0] = ffma2(ad, b0, acc2[i][0]);
                acc2[i][1] = ffma2(ad, b1, acc2[i][1]);
            }
        }
        __syncthreads();
    }
    #pragma unroll
    for (int i = 0; i < 4; i++) {
        int c = tb + i;
        float2 f0 = up2(acc2[i][0]), f1 = up2(acc2[i][1]);
        float o[4] = {f0.x, f0.y, f1.x, f1.y};
        #pragma unroll
        for (int j = 0; j < 4; j++) {
            if (blockIdx.y == 0) o[j] += bias[n0 + th + j];
            atomicAdd(vout + (size_t)c*NCOL + n0 + th + j, o[j]);
        }
    }
}

// ---------------- layernorm ----------------
__global__ void k_ln(const float* __restrict__ lng, const float* __restrict__ lnb,
                     float* __restrict__ out) {
    int c = blockIdx.x, t = threadIdx.x;
    __shared__ float sh[34];
    float v0 = g_h2[c*HID + t], v1 = g_h2[c*HID + 256 + t];
    int lane = t & 31, w = t >> 5;
    float s = v0 + v1;
    #pragma unroll
    for (int off = 16; off; off >>= 1) s += __shfl_xor_sync(~0u, s, off);
    if (lane == 0) sh[w] = s;
    __syncthreads();
    if (w == 0) {
        float tot = (t < 8) ? sh[t] : 0.f;
        #pragma unroll
        for (int off = 4; off; off >>= 1) tot += __shfl_xor_sync(~0u, tot, off);
        if (t == 0) sh[32] = tot;
    }
    __syncthreads();
    float mu = sh[32] * (1.f/512.f);
    float d0 = v0 - mu, d1 = v1 - mu;
    float q = d0*d0 + d1*d1;
    #pragma unroll
    for (int off = 16; off; off >>= 1) q += __shfl_xor_sync(~0u, q, off);
    if (lane == 0) sh[w] = q;
    __syncthreads();
    if (w == 0) {
        float tot = (t < 8) ? sh[t] : 0.f;
        #pragma unroll
        for (int off = 4; off; off >>= 1) tot += __shfl_xor_sync(~0u, tot, off);
        if (t == 0) sh[33] = tot;
    }
    __syncthreads();
    float inv = rsqrtf(sh[33] * (1.f/512.f) + 1e-5f);
    float r0 = d0*inv*lng[t]     + lnb[t];
    float r1 = d1*inv*lng[256+t] + lnb[256+t];
    g_int[c*HID + t]       = r0;
    g_int[c*HID + 256 + t] = r1;
    out[64 + c*HID + t]       = r0;
    out[64 + c*HID + 256 + t] = r1;
}

// ---------------- per-cell affinity head (4 blocks/cell) ----------------
__global__ void k_aff(const float* __restrict__ Aw1, const float* __restrict__ Ab1,
                      const float* __restrict__ Aw2) {
    int c = blockIdx.x;
    int k = blockIdx.y * 128 + threadIdx.x;
    __shared__ float a[HID];
    __shared__ float red[4];
    for (int j = threadIdx.x; j < HID; j += 128) a[j] = g_int[c*HID + j];
    __syncthreads();
    float acc = Ab1[c*HID + k];
    const float* W = Aw1 + (size_t)c*HID*HID + k;
    #pragma unroll 8
    for (int j = 0; j < HID; j++) acc += a[j] * W[(size_t)j*HID];
    float part = fmaxf(acc, 0.f) * Aw2[c*HID + k];
    int lane = threadIdx.x & 31, w = threadIdx.x >> 5;
    #pragma unroll
    for (int off = 16; off; off >>= 1) part += __shfl_xor_sync(~0u, part, off);
    if (lane == 0) red[w] = part;
    __syncthreads();
    if (threadIdx.x == 0)
        atomicAdd(&g_affacc[c], red[0] + red[1] + red[2] + red[3]);
}

__global__ void k_sig(const float* __restrict__ Ab2, float* __restrict__ out) {
    int c = threadIdx.x;
    out[c] = 1.f / (1.f + expf(-(g_affacc[c] + Ab2[c])));
}

extern "C" void kernel_launch(void* const* d_in, const int* in_sizes, int n_in,
                              void* d_out, int out_size) {
    const float* x       = (const float*)d_in[0];
    const int*   ei      = (const int*)  d_in[1];
    const float* gene_W  = (const float*)d_in[3];
    const float* gene_b  = (const float*)d_in[4];
    const int*   cell_ids= (const int*)  d_in[5];
    const int*   counts  = (const int*)  d_in[7];
    const float* Wq = (const float*)d_in[8],  *bq = (const float*)d_in[9];
    const float* Wk = (const float*)d_in[10], *bk = (const float*)d_in[11];
    const float* Wv = (const float*)d_in[12], *bv = (const float*)d_in[13];
    const float* Wo = (const float*)d_in[14], *bo = (const float*)d_in[15];
    const float* Wi1= (const float*)d_in[16], *bi1= (const float*)d_in[17];
    const float* Wi2= (const float*)d_in[18], *bi2= (const float*)d_in[19];
    const float* lng= (const float*)d_in[20], *lnb= (const float*)d_in[21];
    const float* Aw1= (const float*)d_in[22], *Ab1= (const float*)d_in[23];
    const float* Aw2= (const float*)d_in[24], *Ab2= (const float*)d_in[25];
    float* out = (float*)d_out;

    cudaFuncSetAttribute(k_attn_mma, cudaFuncAttributeMaxDynamicSharedMemorySize, ATTN_SMEM);
    cudaFuncSetAttribute(k_qkv_mma, cudaFuncAttributeMaxDynamicSharedMemorySize, QKV_SMEM);
    cudaFuncSetAttribute(k_gene_mma, cudaFuncAttributeMaxDynamicSharedMemorySize, GENE_SMEM);

    k_init <<<256, 256>>>(counts);
    k_edges<<<(NEDGES*32)/256, 256>>>(x, ei);
    k_pool <<<NB, 128>>>(x);
    k_gene_mma<<<dim3(NG, 4), 256, GENE_SMEM>>>(gene_W, gene_b);
    k_cvtW <<<dim3(3, 16, 16), dim3(32, 8)>>>(Wq, Wk, Wv);
    k_qkv_mma<<<dim3(MTILES, 24), 256, QKV_SMEM>>>(bq, bk, bv);
    k_attn_mma<<<dim3(NG, 8), 128, ATTN_SMEM>>>(cell_ids, counts);
    k_vm2<512,  512, 0, 0><<<dim3(8, 4),  256>>>(Wo,  bo);
    k_vm2<512, 1024, 0, 1><<<dim3(16, 4), 256>>>(Wi1, bi1);
    k_vm2<1024, 512, 1, 2><<<dim3(8, 8),  256>>>(Wi2, bi2);
    k_ln  <<<NC, 256>>>(lng, lnb, out);
    k_aff <<<dim3(NC, 4), 128>>>(Aw1, Ab1, Aw2);
    k_sig <<<1, NC>>>(Ab2, out);
}

// round 9
// speedup vs baseline: 2.6437x; 1.0568x over previous
#include <cuda_runtime.h>
#include <cuda_bf16.h>
#include <math.h>
#include <cstdint>

#define NNODES 4096
#define FEAT   128
#define NEDGES 65536
#define NG     317
#define NB     64
#define NC     64
#define HID    512
#define DH     64
#define NROWS  (NG*NB)
#define FFD    1024
#define MTILES 159
#define PADROWS (MTILES*128)

typedef unsigned long long u64;

// ---------------- f32x2 helpers ----------------
__device__ __forceinline__ u64 dup2(float x) {
    u64 r; asm("mov.b64 %0,{%1,%1};" : "=l"(r) : "f"(x)); return r;
}
__device__ __forceinline__ u64 ffma2(u64 a, u64 b, u64 c) {
    u64 d; asm("fma.rn.f32x2 %0,%1,%2,%3;" : "=l"(d) : "l"(a), "l"(b), "l"(c)); return d;
}
__device__ __forceinline__ float2 up2(u64 v) {
    float2 f; asm("mov.b64 {%0,%1},%2;" : "=f"(f.x), "=f"(f.y) : "l"(v)); return f;
}

// ---------------- mma.sync / cp.async helpers ----------------
__device__ __forceinline__ uint32_t smem_u32(const void* p) {
    uint32_t a; asm("{ .reg .u64 t; cvta.to.shared.u64 t, %1; cvt.u32.u64 %0, t; }"
                    : "=r"(a) : "l"(p)); return a;
}
__device__ __forceinline__ void ldsm_x4(uint32_t* r, uint32_t addr) {
    asm volatile("ldmatrix.sync.aligned.m8n8.x4.shared.b16 {%0,%1,%2,%3}, [%4];"
        : "=r"(r[0]), "=r"(r[1]), "=r"(r[2]), "=r"(r[3]) : "r"(addr));
}
__device__ __forceinline__ void ldsm_x4_t(uint32_t* r, uint32_t addr) {
    asm volatile("ldmatrix.sync.aligned.m8n8.x4.trans.shared.b16 {%0,%1,%2,%3}, [%4];"
        : "=r"(r[0]), "=r"(r[1]), "=r"(r[2]), "=r"(r[3]) : "r"(addr));
}
__device__ __forceinline__ void mma16816(float* d, const uint32_t* a, const uint32_t* b) {
    asm volatile("mma.sync.aligned.m16n8k16.row.col.f32.bf16.bf16.f32 "
        "{%0,%1,%2,%3}, {%4,%5,%6,%7}, {%8,%9}, {%0,%1,%2,%3};"
        : "+f"(d[0]), "+f"(d[1]), "+f"(d[2]), "+f"(d[3])
        : "r"(a[0]), "r"(a[1]), "r"(a[2]), "r"(a[3]), "r"(b[0]), "r"(b[1]));
}
__device__ __forceinline__ uint32_t pkbf2(float lo, float hi) {
    uint32_t r; asm("cvt.rn.bf16x2.f32 %0, %1, %2;" : "=r"(r) : "f"(hi), "f"(lo)); return r;
}
__device__ __forceinline__ void cpa16(uint32_t dst, const void* src) {
    asm volatile("cp.async.ca.shared.global [%0], [%1], 16;" :: "r"(dst), "l"(src));
}
#define CP_COMMIT() asm volatile("cp.async.commit_group;" ::: "memory")
#define CP_WAIT(n)  asm volatile("cp.async.wait_group %0;" :: "n"(n) : "memory")

// ---------------- scratch ----------------
__device__ float g_deg[NNODES];
__device__ float g_agg[NNODES*FEAT];
__device__ float g_csum[NC*HID];
__device__ float g_meanh[NC*HID];
__device__ float g_h1[NC*FFD];
__device__ float g_h2[NC*HID];
__device__ float g_int[NC*HID];
__device__ float g_affacc[NC];
__device__ int   g_cs[NC+1];
__device__ __nv_bfloat16 g_ph[NB*FEAT];
__device__ __nv_bfloat16 g_pl[NB*FEAT];
__device__ __nv_bfloat16 g_Xhi[(size_t)PADROWS*HID];
__device__ __nv_bfloat16 g_Xlo[(size_t)PADROWS*HID];
__device__ __nv_bfloat16 g_Wthi[3*HID*HID];   // [w][n][k]
__device__ __nv_bfloat16 g_Wtlo[3*HID*HID];
__device__ __nv_bfloat16 g_Qhi[(size_t)NROWS*HID];
__device__ __nv_bfloat16 g_Qlo[(size_t)NROWS*HID];
__device__ __nv_bfloat16 g_Khi[(size_t)NROWS*HID];
__device__ __nv_bfloat16 g_Klo[(size_t)NROWS*HID];
__device__ __nv_bfloat16 g_Vhi[(size_t)NROWS*HID];

// ---------------- init ----------------
__global__ void k_init(const int* __restrict__ counts) {
    int i = blockIdx.x * blockDim.x + threadIdx.x;
    int nt = gridDim.x * blockDim.x;
    if (i < NNODES) g_deg[i] = 0.f;
    for (int j = i; j < NNODES*FEAT; j += nt) g_agg[j] = 0.f;
    if (i < NC*HID) { g_csum[i] = 0.f; g_meanh[i] = 0.f; g_h2[i] = 0.f; }
    for (int j = i; j < NC*FFD; j += nt) g_h1[j] = 0.f;
    if (i < NC) g_affacc[i] = 0.f;
    if (i < (PADROWS - NROWS) * HID) {
        g_Xhi[(size_t)NROWS*HID + i] = __float2bfloat16(0.f);
        g_Xlo[(size_t)NROWS*HID + i] = __float2bfloat16(0.f);
    }
    if (i == 0) {
        int s = 0;
        for (int c = 0; c < NC; c++) { g_cs[c] = s; s += counts[c]; }
        g_cs[NC] = s;
    }
}

// ---------------- edge aggregation ----------------
__global__ void k_edges(const float* __restrict__ x, const int* __restrict__ ei) {
    int t = blockIdx.x * blockDim.x + threadIdx.x;
    int e = t >> 5, lane = t & 31;
    if (e >= NEDGES) return;
    int s = ei[e], d = ei[NEDGES + e];
    float4 v = *(const float4*)(x + (size_t)s*FEAT + lane*4);
    float* a = g_agg + (size_t)d*FEAT + lane*4;
    atomicAdd(a+0, v.x); atomicAdd(a+1, v.y);
    atomicAdd(a+2, v.z); atomicAdd(a+3, v.w);
    if (lane == 0) atomicAdd(g_deg + d, 1.f);
}

// ---------------- per-graph mean pool -> bf16 hi/lo ----------------
__global__ void k_pool(const float* __restrict__ x) {
    int g = blockIdx.x, f = threadIdx.x;
    float s = 0.f;
    for (int n = g*64; n < g*64 + 64; n++) {
        float inv = 1.f / fmaxf(g_deg[n], 1.f);
        s += x[(size_t)n*FEAT + f] + g_agg[(size_t)n*FEAT + f] * inv;
    }
    s *= (1.f/64.f);
    __nv_bfloat16 h = __float2bfloat16(s);
    g_ph[g*FEAT + f] = h;
    g_pl[g*FEAT + f] = __float2bfloat16(s - __bfloat162float(h));
}

// ---------------- per-gene GEMM via mma.sync bf16, single-stage k=128 ----------------
// smem: GAH 16K (64r x 16c) | GAL 16K | GBH 32K (128r x 16c) | GBL 32K = 96KB
#define GAH 0
#define GAL 16384
#define GBH 32768
#define GBL 65536
#define GENE_SMEM 98304

__global__ void __launch_bounds__(256) k_gene_mma(const float* __restrict__ gW,
                                                  const float* __restrict__ gb) {
    extern __shared__ char smem[];
    uint32_t sb = smem_u32(smem);
    int tid = threadIdx.x, wid = tid >> 5, lane = tid & 31;
    int g = blockIdx.x, n0 = blockIdx.y * 128;
    int wr = wid & 3, wc = wid >> 2;

    // A: pooled hi/lo 64 rows x 16 chunks via cp.async
    for (int u = tid; u < 1024; u += 256) {
        int row = u >> 4, c = u & 15;
        uint32_t dst = (uint32_t)(((row << 4) | (c ^ (row & 7))) << 4);
        int go = row*FEAT + c*8;
        cpa16(sb + GAH + dst, g_ph + go);
        cpa16(sb + GAL + dst, g_pl + go);
    }
    CP_COMMIT();
    // B: gene_W fp32 -> bf16 hi/lo, 128 k-rows x 16 n-chunks
    for (int u = tid; u < 2048; u += 256) {
        int row = u >> 4, c = u & 15;
        const float* src = gW + (size_t)g*FEAT*HID + (size_t)row*HID + n0 + c*8;
        float4 f0 = *(const float4*)src;
        float4 f1 = *(const float4*)(src + 4);
        float v[8] = {f0.x,f0.y,f0.z,f0.w,f1.x,f1.y,f1.z,f1.w};
        float hh[8];
        #pragma unroll
        for (int p = 0; p < 8; p++) hh[p] = __bfloat162float(__float2bfloat16(v[p]));
        uint4 hv, lv;
        hv.x = pkbf2(v[0],v[1]); hv.y = pkbf2(v[2],v[3]);
        hv.z = pkbf2(v[4],v[5]); hv.w = pkbf2(v[6],v[7]);
        lv.x = pkbf2(v[0]-hh[0],v[1]-hh[1]); lv.y = pkbf2(v[2]-hh[2],v[3]-hh[3]);
        lv.z = pkbf2(v[4]-hh[4],v[5]-hh[5]); lv.w = pkbf2(v[6]-hh[6],v[7]-hh[7]);
        uint32_t dst = (uint32_t)(((row << 4) | (c ^ (row & 7))) << 4);
        *(uint4*)(smem + GBH + dst) = hv;
        *(uint4*)(smem + GBL + dst) = lv;
    }
    CP_WAIT(0);
    __syncthreads();

    float acc[8][4];
    #pragma unroll
    for (int t = 0; t < 8; t++)
        #pragma unroll
        for (int j = 0; j < 4; j++) acc[t][j] = 0.f;

    #pragma unroll
    for (int s = 0; s < 8; s++) {
        int arow = wr*16 + (lane & 15);
        int ac   = s*2 + (lane >> 4);
        uint32_t aoff = (uint32_t)(((arow << 4) | (ac ^ (arow & 7))) << 4);
        uint32_t ah[4], al[4];
        ldsm_x4(ah, sb + GAH + aoff);
        ldsm_x4(al, sb + GAL + aoff);
        int grp = lane >> 3;
        int vrow = s*16 + (lane & 7) + ((grp & 1) << 3);
        #pragma unroll
        for (int dblk = 0; dblk < 4; dblk++) {
            int vch = wc*8 + dblk*2 + (grp >> 1);
            uint32_t voff = (uint32_t)(((vrow << 4) | (vch ^ (vrow & 7))) << 4);
            uint32_t vbh[4], vbl[4];
            ldsm_x4_t(vbh, sb + GBH + voff);
            ldsm_x4_t(vbl, sb + GBL + voff);
            mma16816(acc[dblk*2],   ah, &vbh[0]);
            mma16816(acc[dblk*2],   ah, &vbl[0]);
            mma16816(acc[dblk*2],   al, &vbh[0]);
            mma16816(acc[dblk*2+1], ah, &vbh[2]);
            mma16816(acc[dblk*2+1], ah, &vbl[2]);
            mma16816(acc[dblk*2+1], al, &vbh[2]);
        }
    }
    int row0 = wr*16 + (lane >> 2);
    int cb = n0 + wc*64 + 2*(lane & 3);
    #pragma unroll
    for (int n8 = 0; n8 < 8; n8++) {
        int col = cb + n8*8;
        float b0 = gb[(size_t)g*HID + col], b1 = gb[(size_t)g*HID + col + 1];
        #pragma unroll
        for (int half = 0; half < 2; half++) {
            int row = g*64 + row0 + half*8;
            float v0 = fmaxf(acc[n8][half*2+0] + b0, 0.f);
            float v1 = fmaxf(acc[n8][half*2+1] + b1, 0.f);
            float h0 = __bfloat162float(__float2bfloat16(v0));
            float h1 = __bfloat162float(__float2bfloat16(v1));
            *(uint32_t*)(g_Xhi + (size_t)row*HID + col) = pkbf2(v0, v1);
            *(uint32_t*)(g_Xlo + (size_t)row*HID + col) = pkbf2(v0 - h0, v1 - h1);
        }
    }
}

// ---------------- transpose+convert W -> bf16 hi/lo [n][k] ----------------
__global__ void k_cvtW(const float* __restrict__ Wq, const float* __restrict__ Wk,
                       const float* __restrict__ Wv) {
    __shared__ float tile[32][33];
    int w = blockIdx.x;
    const float* W = (w == 0) ? Wq : (w == 1) ? Wk : Wv;
    int kb = blockIdx.y * 32, nb = blockIdx.z * 32;
    #pragma unroll
    for (int i = 0; i < 4; i++)
        tile[threadIdx.y + i*8][threadIdx.x] =
            W[(size_t)(kb + threadIdx.y + i*8)*HID + nb + threadIdx.x];
    __syncthreads();
    #pragma unroll
    for (int i = 0; i < 4; i++) {
        int n = nb + threadIdx.y + i*8, k = kb + threadIdx.x;
        float v = tile[threadIdx.x][threadIdx.y + i*8];
        __nv_bfloat16 h = __float2bfloat16(v);
        size_t o = (size_t)w*HID*HID + (size_t)n*HID + k;
        g_Wthi[o] = h;
        g_Wtlo[o] = __float2bfloat16(v - __bfloat162float(h));
    }
}

// ---------------- fused Q+K+V GEMM, double-buffered cp.async ----------------
// per-buffer (80KB): AH 16K | AL 16K | B[w]: H 8K + L 8K (w=0..2)
#define QBUF 81920
#define QAH 0
#define QAL 16384
#define QB0 32768
#define QKV_SMEM (2*QBUF)

__global__ void __launch_bounds__(256, 1) k_qkv_mma(
        const float* __restrict__ bq, const float* __restrict__ bk,
        const float* __restrict__ bv) {
    extern __shared__ char smem[];
    uint32_t sb = smem_u32(smem);
    int tid = threadIdx.x;
    int wid = tid >> 5, lane = tid & 31;
    int m0 = blockIdx.x * 128;
    int n0 = blockIdx.y * 64;
    int wr = wid & 3, wc = wid >> 2;

    float acc[3][2][4][4];
    #pragma unroll
    for (int w = 0; w < 3; w++)
        #pragma unroll
        for (int a = 0; a < 2; a++)
            #pragma unroll
            for (int b = 0; b < 4; b++)
                #pragma unroll
                for (int c = 0; c < 4; c++) acc[w][a][b][c] = 0.f;

    // stage chunk 0
    {
        uint32_t base = sb;
        for (int u = tid; u < 1024; u += 256) {
            int row = u >> 3, c = u & 7;
            uint32_t dst = (uint32_t)(((row << 3) | (c ^ (row & 7))) << 4);
            size_t go = (size_t)(m0 + row)*HID + c*8;
            cpa16(base + QAH + dst, g_Xhi + go);
            cpa16(base + QAL + dst, g_Xlo + go);
        }
        for (int u = tid; u < 1536; u += 256) {
            int w = u >> 9, r = (u >> 3) & 63, c = u & 7;
            uint32_t dst = (uint32_t)(((r << 3) | (c ^ (r & 7))) << 4);
            size_t go = (size_t)w*HID*HID + (size_t)(n0 + r)*HID + c*8;
            cpa16(base + QB0 + w*16384 + dst,        g_Wthi + go);
            cpa16(base + QB0 + w*16384 + 8192 + dst, g_Wtlo + go);
        }
        CP_COMMIT();
    }

    for (int ch = 0; ch < 8; ch++) {
        uint32_t cbase = sb + (uint32_t)(ch & 1)*QBUF;
        if (ch < 7) {
            uint32_t nbase = sb + (uint32_t)((ch+1) & 1)*QBUF;
            int k0 = (ch+1) * 64;
            for (int u = tid; u < 1024; u += 256) {
                int row = u >> 3, c = u & 7;
                uint32_t dst = (uint32_t)(((row << 3) | (c ^ (row & 7))) << 4);
                size_t go = (size_t)(m0 + row)*HID + k0 + c*8;
                cpa16(nbase + QAH + dst, g_Xhi + go);
                cpa16(nbase + QAL + dst, g_Xlo + go);
            }
            for (int u = tid; u < 1536; u += 256) {
                int w = u >> 9, r = (u >> 3) & 63, c = u & 7;
                uint32_t dst = (uint32_t)(((r << 3) | (c ^ (r & 7))) << 4);
                size_t go = (size_t)w*HID*HID + (size_t)(n0 + r)*HID + k0 + c*8;
                cpa16(nbase + QB0 + w*16384 + dst,        g_Wthi + go);
                cpa16(nbase + QB0 + w*16384 + 8192 + dst, g_Wtlo + go);
            }
            CP_COMMIT();
            CP_WAIT(1);
        } else {
            CP_WAIT(0);
        }
        __syncthreads();
        #pragma unroll
        for (int s = 0; s < 4; s++) {
            uint32_t ah[2][4], al[2][4];
            {
                int arow = wr*32 + (lane & 15);
                int ac   = s*2 + (lane >> 4);
                #pragma unroll
                for (int mt = 0; mt < 2; mt++) {
                    int r = arow + mt*16;
                    uint32_t off = (uint32_t)(((r << 3) | (ac ^ (r & 7))) << 4);
                    ldsm_x4(ah[mt], cbase + QAH + off);
                    ldsm_x4(al[mt], cbase + QAL + off);
                }
            }
            int brow = wc*32 + (lane & 7) + ((lane >> 4) << 3);
            int bc   = s*2 + ((lane >> 3) & 1);
            #pragma unroll
            for (int w = 0; w < 3; w++) {
                uint32_t bh[2][4], bl[2][4];
                #pragma unroll
                for (int bt = 0; bt < 2; bt++) {
                    int r = brow + bt*16;
                    uint32_t off = (uint32_t)(((r << 3) | (bc ^ (r & 7))) << 4);
                    ldsm_x4(bh[bt], cbase + QB0 + w*16384 + off);
                    ldsm_x4(bl[bt], cbase + QB0 + w*16384 + 8192 + off);
                }
                #pragma unroll
                for (int mt = 0; mt < 2; mt++)
                    #pragma unroll
                    for (int n8 = 0; n8 < 4; n8++) {
                        const uint32_t* B0 = &bh[n8 >> 1][(n8 & 1) * 2];
                        const uint32_t* L0 = &bl[n8 >> 1][(n8 & 1) * 2];
                        mma16816(acc[w][mt][n8], ah[mt], B0);
                        mma16816(acc[w][mt][n8], ah[mt], L0);
                        mma16816(acc[w][mt][n8], al[mt], B0);
                    }
            }
        }
        __syncthreads();
    }
    int rbase = m0 + wr*32 + (lane >> 2);
    int cbase2 = n0 + wc*32 + 2*(lane & 3);
    #pragma unroll
    for (int w = 0; w < 3; w++) {
        const float* bias = (w == 0) ? bq : (w == 1) ? bk : bv;
        __nv_bfloat16* outhi = (w == 0) ? g_Qhi : (w == 1) ? g_Khi : g_Vhi;
        __nv_bfloat16* outlo = (w == 0) ? g_Qlo : (w == 1) ? g_Klo : (__nv_bfloat16*)0;
        #pragma unroll
        for (int mt = 0; mt < 2; mt++) {
            #pragma unroll
            for (int n8 = 0; n8 < 4; n8++) {
                int col = cbase2 + n8*8;
                float b0 = bias[col], b1 = bias[col+1];
                #pragma unroll
                for (int half = 0; half < 2; half++) {
                    int r0 = rbase + mt*16 + half*8;
                    if (r0 >= NROWS) continue;
                    float v0 = acc[w][mt][n8][half*2+0] + b0;
                    float v1 = acc[w][mt][n8][half*2+1] + b1;
                    float h0 = __bfloat162float(__float2bfloat16(v0));
                    float h1 = __bfloat162float(__float2bfloat16(v1));
                    *(uint32_t*)(outhi + (size_t)r0*HID + col) = pkbf2(v0, v1);
                    if (outlo)
                        *(uint32_t*)(outlo + (size_t)r0*HID + col) = pkbf2(v0 - h0, v1 - h1);
                }
            }
        }
    }
}

// ---------------- flash attention, double-buffered K/V via cp.async ----------------
// smem: QH 8K | QL 8K | 2 x (KH 8K | KL 8K | VH 8K) = 64KB
#define AQH 0
#define AQL 8192
#define AKV 16384
#define AKVBUF 24576
#define ATTN_SMEM 65536

__global__ void __launch_bounds__(128) k_attn_mma(const int* __restrict__ cell_ids,
                                                  const int* __restrict__ counts) {
    extern __shared__ char smem[];
    uint32_t sb = smem_u32(smem);
    int g = blockIdx.x, h = blockIdx.y;
    int tid = threadIdx.x, wid = tid >> 5, lane = tid & 31;
    int c = cell_ids[g];
    int nt = counts[c];
    int ks0 = g_cs[c];

    // Q hi/lo
    for (int u = tid; u < 512; u += 128) {
        int row = u >> 3, ch = u & 7;
        uint32_t dst = (uint32_t)(((row << 3) | (ch ^ (row & 7))) << 4);
        size_t go = (size_t)(g*64 + row)*HID + h*64 + ch*8;
        *(uint4*)(smem + AQH + dst) = *(const uint4*)(g_Qhi + go);
        *(uint4*)(smem + AQL + dst) = *(const uint4*)(g_Qlo + go);
    }
    // stage kt=0
    {
        uint32_t kb = sb + AKV;
        for (int u = tid; u < 512; u += 128) {
            int row = u >> 3, ch = u & 7;
            uint32_t dst = (uint32_t)(((row << 3) | (ch ^ (row & 7))) << 4);
            size_t go = (size_t)(ks0*64 + row)*HID + h*64 + ch*8;
            cpa16(kb + dst,         g_Khi + go);
            cpa16(kb + 8192 + dst,  g_Klo + go);
            cpa16(kb + 16384 + dst, g_Vhi + go);
        }
        CP_COMMIT();
    }

    float oacc[8][4];
    #pragma unroll
    for (int t = 0; t < 8; t++)
        #pragma unroll
        for (int j = 0; j < 4; j++) oacc[t][j] = 0.f;
    float mA = -1e30f, mB = -1e30f, lA = 0.f, lB = 0.f;

    int arow = wid*16 + (lane & 15);

    for (int kt = 0; kt < nt; kt++) {
        uint32_t kb = sb + AKV + (uint32_t)(kt & 1)*AKVBUF;
        if (kt + 1 < nt) {
            uint32_t nb = sb + AKV + (uint32_t)((kt+1) & 1)*AKVBUF;
            int kg = ks0 + kt + 1;
            for (int u = tid; u < 512; u += 128) {
                int row = u >> 3, ch = u & 7;
                uint32_t dst = (uint32_t)(((row << 3) | (ch ^ (row & 7))) << 4);
                size_t go = (size_t)(kg*64 + row)*HID + h*64 + ch*8;
                cpa16(nb + dst,         g_Khi + go);
                cpa16(nb + 8192 + dst,  g_Klo + go);
                cpa16(nb + 16384 + dst, g_Vhi + go);
            }
            CP_COMMIT();
            CP_WAIT(1);
        } else {
            CP_WAIT(0);
        }
        __syncthreads();

        float sacc[8][4];
        #pragma unroll
        for (int t = 0; t < 8; t++)
            #pragma unroll
            for (int j = 0; j < 4; j++) sacc[t][j] = 0.f;
        #pragma unroll
        for (int s = 0; s < 4; s++) {
            int ac = s*2 + (lane >> 4);
            uint32_t aoff = (uint32_t)(((arow << 3) | (ac ^ (arow & 7))) << 4);
            uint32_t ah[4], al[4];
            ldsm_x4(ah, sb + AQH + aoff);
            ldsm_x4(al, sb + AQL + aoff);
            #pragma unroll
            for (int bt = 0; bt < 4; bt++) {
                int brow = bt*16 + (lane & 7) + ((lane >> 4) << 3);
                int bc   = s*2 + ((lane >> 3) & 1);
                uint32_t boff = (uint32_t)(((brow << 3) | (bc ^ (brow & 7))) << 4);
                uint32_t bh[4], bl[4];
                ldsm_x4(bh, kb + boff);
                ldsm_x4(bl, kb + 8192 + boff);
                mma16816(sacc[bt*2],   ah, &bh[0]);
                mma16816(sacc[bt*2],   ah, &bl[0]);
                mma16816(sacc[bt*2],   al, &bh[0]);
                mma16816(sacc[bt*2+1], ah, &bh[2]);
                mma16816(sacc[bt*2+1], ah, &bl[2]);
                mma16816(sacc[bt*2+1], al, &bh[2]);
            }
        }
        float mtA = -1e30f, mtB = -1e30f;
        #pragma unroll
        for (int t = 0; t < 8; t++) {
            sacc[t][0] *= 0.125f; sacc[t][1] *= 0.125f;
            sacc[t][2] *= 0.125f; sacc[t][3] *= 0.125f;
            mtA = fmaxf(mtA, fmaxf(sacc[t][0], sacc[t][1]));
            mtB = fmaxf(mtB, fmaxf(sacc[t][2], sacc[t][3]));
        }
        mtA = fmaxf(mtA, __shfl_xor_sync(~0u, mtA, 1));
        mtA = fmaxf(mtA, __shfl_xor_sync(~0u, mtA, 2));
        mtB = fmaxf(mtB, __shfl_xor_sync(~0u, mtB, 1));
        mtB = fmaxf(mtB, __shfl_xor_sync(~0u, mtB, 2));
        float mnA = fmaxf(mA, mtA), mnB = fmaxf(mB, mtB);
        float alA = __expf(mA - mnA), alB = __expf(mB - mnB);
        float ltA = 0.f, ltB = 0.f;
        #pragma unroll
        for (int t = 0; t < 8; t++) {
            sacc[t][0] = __expf(sacc[t][0] - mnA);
            sacc[t][1] = __expf(sacc[t][1] - mnA);
            sacc[t][2] = __expf(sacc[t][2] - mnB);
            sacc[t][3] = __expf(sacc[t][3] - mnB);
            ltA += sacc[t][0] + sacc[t][1];
            ltB += sacc[t][2] + sacc[t][3];
        }
        ltA += __shfl_xor_sync(~0u, ltA, 1); ltA += __shfl_xor_sync(~0u, ltA, 2);
        ltB += __shfl_xor_sync(~0u, ltB, 1); ltB += __shfl_xor_sync(~0u, ltB, 2);
        lA = lA*alA + ltA; lB = lB*alB + ltB;
        mA = mnA; mB = mnB;
        #pragma unroll
        for (int t = 0; t < 8; t++) {
            oacc[t][0] *= alA; oacc[t][1] *= alA;
            oacc[t][2] *= alB; oacc[t][3] *= alB;
        }
        #pragma unroll
        for (int t2 = 0; t2 < 4; t2++) {
            uint32_t pa[4];
            pa[0] = pkbf2(sacc[2*t2][0],   sacc[2*t2][1]);
            pa[1] = pkbf2(sacc[2*t2][2],   sacc[2*t2][3]);
            pa[2] = pkbf2(sacc[2*t2+1][0], sacc[2*t2+1][1]);
            pa[3] = pkbf2(sacc[2*t2+1][2], sacc[2*t2+1][3]);
            int grp = lane >> 3;
            int vrow = t2*16 + (lane & 7) + ((grp & 1) << 3);
            #pragma unroll
            for (int dblk = 0; dblk < 4; dblk++) {
                int vch = dblk*2 + (grp >> 1);
                uint32_t voff = (uint32_t)(((vrow << 3) | (vch ^ (vrow & 7))) << 4);
                uint32_t vb[4];
                ldsm_x4_t(vb, kb + 16384 + voff);
                mma16816(oacc[dblk*2],   pa, &vb[0]);
                mma16816(oacc[dblk*2+1], pa, &vb[2]);
            }
        }
        __syncthreads();
    }
    float invA = 1.f / lA, invB = 1.f / lB;
    float invS = 1.f / (float)(nt * 64);
    #pragma unroll
    for (int t = 0; t < 8; t++) {
        float s0 = oacc[t][0]*invA + oacc[t][2]*invB;
        float s1 = oacc[t][1]*invA + oacc[t][3]*invB;
        #pragma unroll
        for (int off = 4; off < 32; off <<= 1) {
            s0 += __shfl_xor_sync(~0u, s0, off);
            s1 += __shfl_xor_sync(~0u, s1, off);
        }
        if (lane < 4) {
            int col = h*64 + 2*lane + t*8;
            atomicAdd(g_csum + c*HID + col,     s0 * invS);
            atomicAdd(g_csum + c*HID + col + 1, s1 * invS);
        }
    }
}

// ---------------- k-split batched vec-mat ----------------
template<int KDIM, int NCOL, int RELUIN, int SRC>
__global__ void __launch_bounds__(256) k_vm2(const float* __restrict__ W,
                                             const float* __restrict__ bias) {
    const float* vin  = (SRC == 0) ? g_csum  : (SRC == 1) ? g_meanh : g_h1;
    float*       vout = (SRC == 0) ? g_meanh : (SRC == 1) ? g_h1    : g_h2;
    int n0 = blockIdx.x * 64, kb = blockIdx.y * 128;
    int tid = threadIdx.x;
    __shared__ float sp[128][68];
    __shared__ float sw[16][68];
    for (int u = tid; u < 2048; u += 256) {
        int c = u >> 5, kq = (u & 31) * 4;
        float4 v = *(const float4*)(vin + c*KDIM + kb + kq);
        if (RELUIN) {
            v.x = fmaxf(v.x, 0.f); v.y = fmaxf(v.y, 0.f);
            v.z = fmaxf(v.z, 0.f); v.w = fmaxf(v.w, 0.f);
        }
        sp[kq+0][c] = v.x; sp[kq+1][c] = v.y;
        sp[kq+2][c] = v.z; sp[kq+3][c] = v.w;
    }
    u64 acc2[4][2];
    #pragma unroll
    for (int i = 0; i < 4; i++) { acc2[i][0] = 0ull; acc2[i][1] = 0ull; }
    int tb = (tid & 15) * 4;
    int th = (tid >> 4) * 4;
    int lr = tid >> 4, lc = (tid & 15) * 4;
    __syncthreads();
    for (int k0 = 0; k0 < 128; k0 += 16) {
        *(float4*)&sw[lr][lc] = *(const float4*)(W + (size_t)(kb + k0 + lr)*NCOL + n0 + lc);
        __syncthreads();
        #pragma unroll
        for (int kk = 0; kk < 16; kk++) {
            float4 a = *(float4*)&sp[k0+kk][tb];
            u64 b0 = *(u64*)&sw[kk][th];
            u64 b1 = *(u64*)&sw[kk][th+2];
            float av[4] = {a.x, a.y, a.z, a.w};
            #pragma unroll
            for (int i = 0; i < 4; i++) {
                u64 ad = dup2(av[i]);
                acc2[i][0] = ffma2(ad, b0, acc2[i][0]);
                acc2[i][1] = ffma2(ad, b1, acc2[i][1]);
            }
        }
        __syncthreads();
    }
    #pragma unroll
    for (int i = 0; i < 4; i++) {
        int c = tb + i;
        float2 f0 = up2(acc2[i][0]), f1 = up2(acc2[i][1]);
        float o[4] = {f0.x, f0.y, f1.x, f1.y};
        #pragma unroll
        for (int j = 0; j < 4; j++) {
            if (blockIdx.y == 0) o[j] += bias[n0 + th + j];
            atomicAdd(vout + (size_t)c*NCOL + n0 + th + j, o[j]);
        }
    }
}

// ---------------- layernorm ----------------
__global__ void k_ln(const float* __restrict__ lng, const float* __restrict__ lnb,
                     float* __restrict__ out) {
    int c = blockIdx.x, t = threadIdx.x;
    __shared__ float sh[34];
    float v0 = g_h2[c*HID + t], v1 = g_h2[c*HID + 256 + t];
    int lane = t & 31, w = t >> 5;
    float s = v0 + v1;
    #pragma unroll
    for (int off = 16; off; off >>= 1) s += __shfl_xor_sync(~0u, s, off);
    if (lane == 0) sh[w] = s;
    __syncthreads();
    if (w == 0) {
        float tot = (t < 8) ? sh[t] : 0.f;
        #pragma unroll
        for (int off = 4; off; off >>= 1) tot += __shfl_xor_sync(~0u, tot, off);
        if (t == 0) sh[32] = tot;
    }
    __syncthreads();
    float mu = sh[32] * (1.f/512.f);
    float d0 = v0 - mu, d1 = v1 - mu;
    float q = d0*d0 + d1*d1;
    #pragma unroll
    for (int off = 16; off; off >>= 1) q += __shfl_xor_sync(~0u, q, off);
    if (lane == 0) sh[w] = q;
    __syncthreads();
    if (w == 0) {
        float tot = (t < 8) ? sh[t] : 0.f;
        #pragma unroll
        for (int off = 4; off; off >>= 1) tot += __shfl_xor_sync(~0u, tot, off);
        if (t == 0) sh[33] = tot;
    }
    __syncthreads();
    float inv = rsqrtf(sh[33] * (1.f/512.f) + 1e-5f);
    float r0 = d0*inv*lng[t]     + lnb[t];
    float r1 = d1*inv*lng[256+t] + lnb[256+t];
    g_int[c*HID + t]       = r0;
    g_int[c*HID + 256 + t] = r1;
    out[64 + c*HID + t]       = r0;
    out[64 + c*HID + 256 + t] = r1;
}

// ---------------- per-cell affinity head (4 blocks/cell) ----------------
__global__ void k_aff(const float* __restrict__ Aw1, const float* __restrict__ Ab1,
                      const float* __restrict__ Aw2) {
    int c = blockIdx.x;
    int k = blockIdx.y * 128 + threadIdx.x;
    __shared__ float a[HID];
    __shared__ float red[4];
    for (int j = threadIdx.x; j < HID; j += 128) a[j] = g_int[c*HID + j];
    __syncthreads();
    float acc = Ab1[c*HID + k];
    const float* W = Aw1 + (size_t)c*HID*HID + k;
    #pragma unroll 8
    for (int j = 0; j < HID; j++) acc += a[j] * W[(size_t)j*HID];
    float part = fmaxf(acc, 0.f) * Aw2[c*HID + k];
    int lane = threadIdx.x & 31, w = threadIdx.x >> 5;
    #pragma unroll
    for (int off = 16; off; off >>= 1) part += __shfl_xor_sync(~0u, part, off);
    if (lane == 0) red[w] = part;
    __syncthreads();
    if (threadIdx.x == 0)
        atomicAdd(&g_affacc[c], red[0] + red[1] + red[2] + red[3]);
}

__global__ void k_sig(const float* __restrict__ Ab2, float* __restrict__ out) {
    int c = threadIdx.x;
    out[c] = 1.f / (1.f + expf(-(g_affacc[c] + Ab2[c])));
}

extern "C" void kernel_launch(void* const* d_in, const int* in_sizes, int n_in,
                              void* d_out, int out_size) {
    const float* x       = (const float*)d_in[0];
    const int*   ei      = (const int*)  d_in[1];
    const float* gene_W  = (const float*)d_in[3];
    const float* gene_b  = (const float*)d_in[4];
    const int*   cell_ids= (const int*)  d_in[5];
    const int*   counts  = (const int*)  d_in[7];
    const float* Wq = (const float*)d_in[8],  *bq = (const float*)d_in[9];
    const float* Wk = (const float*)d_in[10], *bk = (const float*)d_in[11];
    const float* Wv = (const float*)d_in[12], *bv = (const float*)d_in[13];
    const float* Wo = (const float*)d_in[14], *bo = (const float*)d_in[15];
    const float* Wi1= (const float*)d_in[16], *bi1= (const float*)d_in[17];
    const float* Wi2= (const float*)d_in[18], *bi2= (const float*)d_in[19];
    const float* lng= (const float*)d_in[20], *lnb= (const float*)d_in[21];
    const float* Aw1= (const float*)d_in[22], *Ab1= (const float*)d_in[23];
    const float* Aw2= (const float*)d_in[24], *Ab2= (const float*)d_in[25];
    float* out = (float*)d_out;

    cudaFuncSetAttribute(k_attn_mma, cudaFuncAttributeMaxDynamicSharedMemorySize, ATTN_SMEM);
    cudaFuncSetAttribute(k_qkv_mma, cudaFuncAttributeMaxDynamicSharedMemorySize, QKV_SMEM);
    cudaFuncSetAttribute(k_gene_mma, cudaFuncAttributeMaxDynamicSharedMemorySize, GENE_SMEM);

    k_init <<<256, 256>>>(counts);
    k_edges<<<(NEDGES*32)/256, 256>>>(x, ei);
    k_pool <<<NB, 128>>>(x);
    k_gene_mma<<<dim3(NG, 4), 256, GENE_SMEM>>>(gene_W, gene_b);
    k_cvtW <<<dim3(3, 16, 16), dim3(32, 8)>>>(Wq, Wk, Wv);
    k_qkv_mma<<<dim3(MTILES, 8), 256, QKV_SMEM>>>(bq, bk, bv);
    k_attn_mma<<<dim3(NG, 8), 128, ATTN_SMEM>>>(cell_ids, counts);
    k_vm2<512,  512, 0, 0><<<dim3(8, 4),  256>>>(Wo,  bo);
    k_vm2<512, 1024, 0, 1><<<dim3(16, 4), 256>>>(Wi1, bi1);
    k_vm2<1024, 512, 1, 2><<<dim3(8, 8),  256>>>(Wi2, bi2);
    k_ln  <<<NC, 256>>>(lng, lnb, out);
    k_aff <<<dim3(NC, 4), 128>>>(Aw1, Ab1, Aw2);
    k_sig <<<1, NC>>>(Ab2, out);
}

// round 10
// speedup vs baseline: 2.7323x; 1.0335x over previous
#include <cuda_runtime.h>
#include <cuda_bf16.h>
#include <math.h>
#include <cstdint>

#define NNODES 4096
#define FEAT   128
#define NEDGES 65536
#define NG     317
#define NB     64
#define NC     64
#define HID    512
#define DH     64
#define NROWS  (NG*NB)
#define FFD    1024
#define MTILES 159
#define PADROWS (MTILES*128)

typedef unsigned long long u64;

// ---------------- f32x2 helpers ----------------
__device__ __forceinline__ u64 dup2(float x) {
    u64 r; asm("mov.b64 %0,{%1,%1};" : "=l"(r) : "f"(x)); return r;
}
__device__ __forceinline__ u64 ffma2(u64 a, u64 b, u64 c) {
    u64 d; asm("fma.rn.f32x2 %0,%1,%2,%3;" : "=l"(d) : "l"(a), "l"(b), "l"(c)); return d;
}
__device__ __forceinline__ float2 up2(u64 v) {
    float2 f; asm("mov.b64 {%0,%1},%2;" : "=f"(f.x), "=f"(f.y) : "l"(v)); return f;
}

// ---------------- mma.sync / cp.async helpers ----------------
__device__ __forceinline__ uint32_t smem_u32(const void* p) {
    uint32_t a; asm("{ .reg .u64 t; cvta.to.shared.u64 t, %1; cvt.u32.u64 %0, t; }"
                    : "=r"(a) : "l"(p)); return a;
}
__device__ __forceinline__ void ldsm_x4(uint32_t* r, uint32_t addr) {
    asm volatile("ldmatrix.sync.aligned.m8n8.x4.shared.b16 {%0,%1,%2,%3}, [%4];"
        : "=r"(r[0]), "=r"(r[1]), "=r"(r[2]), "=r"(r[3]) : "r"(addr));
}
__device__ __forceinline__ void ldsm_x4_t(uint32_t* r, uint32_t addr) {
    asm volatile("ldmatrix.sync.aligned.m8n8.x4.trans.shared.b16 {%0,%1,%2,%3}, [%4];"
        : "=r"(r[0]), "=r"(r[1]), "=r"(r[2]), "=r"(r[3]) : "r"(addr));
}
__device__ __forceinline__ void mma16816(float* d, const uint32_t* a, const uint32_t* b) {
    asm volatile("mma.sync.aligned.m16n8k16.row.col.f32.bf16.bf16.f32 "
        "{%0,%1,%2,%3}, {%4,%5,%6,%7}, {%8,%9}, {%0,%1,%2,%3};"
        : "+f"(d[0]), "+f"(d[1]), "+f"(d[2]), "+f"(d[3])
        : "r"(a[0]), "r"(a[1]), "r"(a[2]), "r"(a[3]), "r"(b[0]), "r"(b[1]));
}
__device__ __forceinline__ uint32_t pkbf2(float lo, float hi) {
    uint32_t r; asm("cvt.rn.bf16x2.f32 %0, %1, %2;" : "=r"(r) : "f"(hi), "f"(lo)); return r;
}
__device__ __forceinline__ void cpa16(uint32_t dst, const void* src) {
    asm volatile("cp.async.ca.shared.global [%0], [%1], 16;" :: "r"(dst), "l"(src));
}
#define CP_COMMIT() asm volatile("cp.async.commit_group;" ::: "memory")
#define CP_WAIT(n)  asm volatile("cp.async.wait_group %0;" :: "n"(n) : "memory")
__device__ __forceinline__ void red4(float* p, float4 v) {
    asm volatile("red.global.add.v4.f32 [%0], {%1,%2,%3,%4};"
        :: "l"(p), "f"(v.x), "f"(v.y), "f"(v.z), "f"(v.w) : "memory");
}

// ---------------- scratch ----------------
__device__ float g_deg[NNODES];
__device__ float g_agg[NNODES*FEAT];
__device__ float g_csum[NC*HID];
__device__ float g_meanh[NC*HID];
__device__ float g_h1[NC*FFD];
__device__ float g_h2[NC*HID];
__device__ float g_int[NC*HID];
__device__ float g_affacc[NC];
__device__ int   g_affcnt[NC];
__device__ int   g_cs[NC+1];
__device__ __nv_bfloat16 g_ph[NB*FEAT];
__device__ __nv_bfloat16 g_pl[NB*FEAT];
__device__ __nv_bfloat16 g_Xhi[(size_t)PADROWS*HID];
__device__ __nv_bfloat16 g_Xlo[(size_t)PADROWS*HID];
__device__ __nv_bfloat16 g_Wthi[3*HID*HID];   // [w][n][k]
__device__ __nv_bfloat16 g_Wtlo[3*HID*HID];
__device__ __nv_bfloat16 g_Qhi[(size_t)NROWS*HID];
__device__ __nv_bfloat16 g_Qlo[(size_t)NROWS*HID];
__device__ __nv_bfloat16 g_Khi[(size_t)NROWS*HID];
__device__ __nv_bfloat16 g_Klo[(size_t)NROWS*HID];
__device__ __nv_bfloat16 g_Vhi[(size_t)NROWS*HID];

// ---------------- prep: cvtW (blocks 0..767) + init (blocks 768..1023) ----------------
__global__ void __launch_bounds__(256) k_prep(const int* __restrict__ counts,
                                              const float* __restrict__ Wq,
                                              const float* __restrict__ Wk,
                                              const float* __restrict__ Wv) {
    int bid = blockIdx.x;
    if (bid < 768) {
        // transpose+convert W -> bf16 hi/lo [n][k]
        __shared__ float tile[32][33];
        int w = bid / 256;
        int rem = bid % 256;
        int kb = (rem / 16) * 32, nb = (rem % 16) * 32;
        const float* W = (w == 0) ? Wq : (w == 1) ? Wk : Wv;
        int tx = threadIdx.x & 31, ty = threadIdx.x >> 5;
        #pragma unroll
        for (int i = 0; i < 4; i++)
            tile[ty + i*8][tx] = W[(size_t)(kb + ty + i*8)*HID + nb + tx];
        __syncthreads();
        #pragma unroll
        for (int i = 0; i < 4; i++) {
            int n = nb + ty + i*8, k = kb + tx;
            float v = tile[tx][ty + i*8];
            __nv_bfloat16 h = __float2bfloat16(v);
            size_t o = (size_t)w*HID*HID + (size_t)n*HID + k;
            g_Wthi[o] = h;
            g_Wtlo[o] = __float2bfloat16(v - __bfloat162float(h));
        }
    } else {
        int i = (bid - 768) * 256 + threadIdx.x;   // 0..65535
        const int nt = 256*256;
        if (i < NNODES) g_deg[i] = 0.f;
        for (int j = i; j < NNODES*FEAT; j += nt) g_agg[j] = 0.f;
        if (i < NC*HID) { g_csum[i] = 0.f; g_meanh[i] = 0.f; g_h2[i] = 0.f; }
        for (int j = i; j < NC*FFD; j += nt) g_h1[j] = 0.f;
        if (i < NC) { g_affacc[i] = 0.f; g_affcnt[i] = 0; }
        for (int j = i; j < (PADROWS - NROWS) * HID; j += nt) {
            g_Xhi[(size_t)NROWS*HID + j] = __float2bfloat16(0.f);
            g_Xlo[(size_t)NROWS*HID + j] = __float2bfloat16(0.f);
        }
        if (i == 0) {
            int s = 0;
            for (int c = 0; c < NC; c++) { g_cs[c] = s; s += counts[c]; }
            g_cs[NC] = s;
        }
    }
}

// ---------------- edge aggregation (vectorized red) ----------------
__global__ void k_edges(const float* __restrict__ x, const int* __restrict__ ei) {
    int t = blockIdx.x * blockDim.x + threadIdx.x;
    int e = t >> 5, lane = t & 31;
    if (e >= NEDGES) return;
    int s = ei[e], d = ei[NEDGES + e];
    float4 v = *(const float4*)(x + (size_t)s*FEAT + lane*4);
    red4(g_agg + (size_t)d*FEAT + lane*4, v);
    if (lane == 0) atomicAdd(g_deg + d, 1.f);
}

// ---------------- per-graph mean pool -> bf16 hi/lo ----------------
__global__ void k_pool(const float* __restrict__ x) {
    int g = blockIdx.x, f = threadIdx.x;
    float s = 0.f;
    for (int n = g*64; n < g*64 + 64; n++) {
        float inv = 1.f / fmaxf(g_deg[n], 1.f);
        s += x[(size_t)n*FEAT + f] + g_agg[(size_t)n*FEAT + f] * inv;
    }
    s *= (1.f/64.f);
    __nv_bfloat16 h = __float2bfloat16(s);
    g_ph[g*FEAT + f] = h;
    g_pl[g*FEAT + f] = __float2bfloat16(s - __bfloat162float(h));
}

// ---------------- per-gene GEMM via mma.sync bf16, n-block=64 (64KB smem) ----------------
// smem: GAH 16K (64r x 16c of 16B) | GAL 16K | GBH 16K (128r x 8c) | GBL 16K
#define GAH 0
#define GAL 16384
#define GBH 32768
#define GBL 49152
#define GENE_SMEM 65536

__global__ void __launch_bounds__(256) k_gene_mma(const float* __restrict__ gW,
                                                  const float* __restrict__ gb) {
    extern __shared__ char smem[];
    uint32_t sb = smem_u32(smem);
    int tid = threadIdx.x, wid = tid >> 5, lane = tid & 31;
    int g = blockIdx.x, n0 = blockIdx.y * 64;
    int wr = wid & 3, wc = wid >> 2;   // 4 row groups x 16 rows; 2 col groups x 32 n

    // A: pooled hi/lo 64 rows x 16 chunks (256B rows) via cp.async
    for (int u = tid; u < 1024; u += 256) {
        int row = u >> 4, c = u & 15;
        uint32_t dst = (uint32_t)(((row << 4) | (c ^ (row & 7))) << 4);
        int go = row*FEAT + c*8;
        cpa16(sb + GAH + dst, g_ph + go);
        cpa16(sb + GAL + dst, g_pl + go);
    }
    CP_COMMIT();
    // B: gene_W fp32 -> bf16 hi/lo, 128 k-rows x 8 n-chunks (128B rows)
    for (int u = tid; u < 1024; u += 256) {
        int row = u >> 3, c = u & 7;
        const float* src = gW + (size_t)g*FEAT*HID + (size_t)row*HID + n0 + c*8;
        float4 f0 = *(const float4*)src;
        float4 f1 = *(const float4*)(src + 4);
        float v[8] = {f0.x,f0.y,f0.z,f0.w,f1.x,f1.y,f1.z,f1.w};
        float hh[8];
        #pragma unroll
        for (int p = 0; p < 8; p++) hh[p] = __bfloat162float(__float2bfloat16(v[p]));
        uint4 hv, lv;
        hv.x = pkbf2(v[0],v[1]); hv.y = pkbf2(v[2],v[3]);
        hv.z = pkbf2(v[4],v[5]); hv.w = pkbf2(v[6],v[7]);
        lv.x = pkbf2(v[0]-hh[0],v[1]-hh[1]); lv.y = pkbf2(v[2]-hh[2],v[3]-hh[3]);
        lv.z = pkbf2(v[4]-hh[4],v[5]-hh[5]); lv.w = pkbf2(v[6]-hh[6],v[7]-hh[7]);
        uint32_t dst = (uint32_t)(((row << 3) | (c ^ (row & 7))) << 4);
        *(uint4*)(smem + GBH + dst) = hv;
        *(uint4*)(smem + GBL + dst) = lv;
    }
    CP_WAIT(0);
    __syncthreads();

    float acc[4][4];
    #pragma unroll
    for (int t = 0; t < 4; t++)
        #pragma unroll
        for (int j = 0; j < 4; j++) acc[t][j] = 0.f;

    #pragma unroll
    for (int s = 0; s < 8; s++) {
        int arow = wr*16 + (lane & 15);
        int ac   = s*2 + (lane >> 4);
        uint32_t aoff = (uint32_t)(((arow << 4) | (ac ^ (arow & 7))) << 4);
        uint32_t ah[4], al[4];
        ldsm_x4(ah, sb + GAH + aoff);
        ldsm_x4(al, sb + GAL + aoff);
        int grp = lane >> 3;
        int vrow = s*16 + (lane & 7) + ((grp & 1) << 3);
        #pragma unroll
        for (int dblk = 0; dblk < 2; dblk++) {
            int vch = wc*4 + dblk*2 + (grp >> 1);
            uint32_t voff = (uint32_t)(((vrow << 3) | (vch ^ (vrow & 7))) << 4);
            uint32_t vbh[4], vbl[4];
            ldsm_x4_t(vbh, sb + GBH + voff);
            ldsm_x4_t(vbl, sb + GBL + voff);
            mma16816(acc[dblk*2],   ah, &vbh[0]);
            mma16816(acc[dblk*2],   ah, &vbl[0]);
            mma16816(acc[dblk*2],   al, &vbh[0]);
            mma16816(acc[dblk*2+1], ah, &vbh[2]);
            mma16816(acc[dblk*2+1], ah, &vbl[2]);
            mma16816(acc[dblk*2+1], al, &vbh[2]);
        }
    }
    int row0 = wr*16 + (lane >> 2);
    int cb = n0 + wc*32 + 2*(lane & 3);
    #pragma unroll
    for (int n8 = 0; n8 < 4; n8++) {
        int col = cb + n8*8;
        float b0 = gb[(size_t)g*HID + col], b1 = gb[(size_t)g*HID + col + 1];
        #pragma unroll
        for (int half = 0; half < 2; half++) {
            int row = g*64 + row0 + half*8;
            float v0 = fmaxf(acc[n8][half*2+0] + b0, 0.f);
            float v1 = fmaxf(acc[n8][half*2+1] + b1, 0.f);
            float h0 = __bfloat162float(__float2bfloat16(v0));
            float h1 = __bfloat162float(__float2bfloat16(v1));
            *(uint32_t*)(g_Xhi + (size_t)row*HID + col) = pkbf2(v0, v1);
            *(uint32_t*)(g_Xlo + (size_t)row*HID + col) = pkbf2(v0 - h0, v1 - h1);
        }
    }
}

// ---------------- fused Q+K+V GEMM, double-buffered cp.async ----------------
#define QBUF 81920
#define QAH 0
#define QAL 16384
#define QB0 32768
#define QKV_SMEM (2*QBUF)

__global__ void __launch_bounds__(256, 1) k_qkv_mma(
        const float* __restrict__ bq, const float* __restrict__ bk,
        const float* __restrict__ bv) {
    extern __shared__ char smem[];
    uint32_t sb = smem_u32(smem);
    int tid = threadIdx.x;
    int wid = tid >> 5, lane = tid & 31;
    int m0 = blockIdx.x * 128;
    int n0 = blockIdx.y * 64;
    int wr = wid & 3, wc = wid >> 2;

    float acc[3][2][4][4];
    #pragma unroll
    for (int w = 0; w < 3; w++)
        #pragma unroll
        for (int a = 0; a < 2; a++)
            #pragma unroll
            for (int b = 0; b < 4; b++)
                #pragma unroll
                for (int c = 0; c < 4; c++) acc[w][a][b][c] = 0.f;

    {
        uint32_t base = sb;
        for (int u = tid; u < 1024; u += 256) {
            int row = u >> 3, c = u & 7;
            uint32_t dst = (uint32_t)(((row << 3) | (c ^ (row & 7))) << 4);
            size_t go = (size_t)(m0 + row)*HID + c*8;
            cpa16(base + QAH + dst, g_Xhi + go);
            cpa16(base + QAL + dst, g_Xlo + go);
        }
        for (int u = tid; u < 1536; u += 256) {
            int w = u >> 9, r = (u >> 3) & 63, c = u & 7;
            uint32_t dst = (uint32_t)(((r << 3) | (c ^ (r & 7))) << 4);
            size_t go = (size_t)w*HID*HID + (size_t)(n0 + r)*HID + c*8;
            cpa16(base + QB0 + w*16384 + dst,        g_Wthi + go);
            cpa16(base + QB0 + w*16384 + 8192 + dst, g_Wtlo + go);
        }
        CP_COMMIT();
    }

    for (int ch = 0; ch < 8; ch++) {
        uint32_t cbase = sb + (uint32_t)(ch & 1)*QBUF;
        if (ch < 7) {
            uint32_t nbase = sb + (uint32_t)((ch+1) & 1)*QBUF;
            int k0 = (ch+1) * 64;
            for (int u = tid; u < 1024; u += 256) {
                int row = u >> 3, c = u & 7;
                uint32_t dst = (uint32_t)(((row << 3) | (c ^ (row & 7))) << 4);
                size_t go = (size_t)(m0 + row)*HID + k0 + c*8;
                cpa16(nbase + QAH + dst, g_Xhi + go);
                cpa16(nbase + QAL + dst, g_Xlo + go);
            }
            for (int u = tid; u < 1536; u += 256) {
                int w = u >> 9, r = (u >> 3) & 63, c = u & 7;
                uint32_t dst = (uint32_t)(((r << 3) | (c ^ (r & 7))) << 4);
                size_t go = (size_t)w*HID*HID + (size_t)(n0 + r)*HID + k0 + c*8;
                cpa16(nbase + QB0 + w*16384 + dst,        g_Wthi + go);
                cpa16(nbase + QB0 + w*16384 + 8192 + dst, g_Wtlo + go);
            }
            CP_COMMIT();
            CP_WAIT(1);
        } else {
            CP_WAIT(0);
        }
        __syncthreads();
        #pragma unroll
        for (int s = 0; s < 4; s++) {
            uint32_t ah[2][4], al[2][4];
            {
                int arow = wr*32 + (lane & 15);
                int ac   = s*2 + (lane >> 4);
                #pragma unroll
                for (int mt = 0; mt < 2; mt++) {
                    int r = arow + mt*16;
                    uint32_t off = (uint32_t)(((r << 3) | (ac ^ (r & 7))) << 4);
                    ldsm_x4(ah[mt], cbase + QAH + off);
                    ldsm_x4(al[mt], cbase + QAL + off);
                }
            }
            int brow = wc*32 + (lane & 7) + ((lane >> 4) << 3);
            int bc   = s*2 + ((lane >> 3) & 1);
            #pragma unroll
            for (int w = 0; w < 3; w++) {
                uint32_t bh[2][4], bl[2][4];
                #pragma unroll
                for (int bt = 0; bt < 2; bt++) {
                    int r = brow + bt*16;
                    uint32_t off = (uint32_t)(((r << 3) | (bc ^ (r & 7))) << 4);
                    ldsm_x4(bh[bt], cbase + QB0 + w*16384 + off);
                    ldsm_x4(bl[bt], cbase + QB0 + w*16384 + 8192 + off);
                }
                #pragma unroll
                for (int mt = 0; mt < 2; mt++)
                    #pragma unroll
                    for (int n8 = 0; n8 < 4; n8++) {
                        const uint32_t* B0 = &bh[n8 >> 1][(n8 & 1) * 2];
                        const uint32_t* L0 = &bl[n8 >> 1][(n8 & 1) * 2];
                        mma16816(acc[w][mt][n8], ah[mt], B0);
                        mma16816(acc[w][mt][n8], ah[mt], L0);
                        mma16816(acc[w][mt][n8], al[mt], B0);
                    }
            }
        }
        __syncthreads();
    }
    int rbase = m0 + wr*32 + (lane >> 2);
    int cbase2 = n0 + wc*32 + 2*(lane & 3);
    #pragma unroll
    for (int w = 0; w < 3; w++) {
        const float* bias = (w == 0) ? bq : (w == 1) ? bk : bv;
        __nv_bfloat16* outhi = (w == 0) ? g_Qhi : (w == 1) ? g_Khi : g_Vhi;
        __nv_bfloat16* outlo = (w == 0) ? g_Qlo : (w == 1) ? g_Klo : (__nv_bfloat16*)0;
        #pragma unroll
        for (int mt = 0; mt < 2; mt++) {
            #pragma unroll
            for (int n8 = 0; n8 < 4; n8++) {
                int col = cbase2 + n8*8;
                float b0 = bias[col], b1 = bias[col+1];
                #pragma unroll
                for (int half = 0; half < 2; half++) {
                    int r0 = rbase + mt*16 + half*8;
                    if (r0 >= NROWS) continue;
                    float v0 = acc[w][mt][n8][half*2+0] + b0;
                    float v1 = acc[w][mt][n8][half*2+1] + b1;
                    float h0 = __bfloat162float(__float2bfloat16(v0));
                    float h1 = __bfloat162float(__float2bfloat16(v1));
                    *(uint32_t*)(outhi + (size_t)r0*HID + col) = pkbf2(v0, v1);
                    if (outlo)
                        *(uint32_t*)(outlo + (size_t)r0*HID + col) = pkbf2(v0 - h0, v1 - h1);
                }
            }
        }
    }
}

// ---------------- flash attention, double-buffered K/V via cp.async ----------------
#define AQH 0
#define AQL 8192
#define AKV 16384
#define AKVBUF 24576
#define ATTN_SMEM 65536

__global__ void __launch_bounds__(128) k_attn_mma(const int* __restrict__ cell_ids,
                                                  const int* __restrict__ counts) {
    extern __shared__ char smem[];
    uint32_t sb = smem_u32(smem);
    int g = blockIdx.x, h = blockIdx.y;
    int tid = threadIdx.x, wid = tid >> 5, lane = tid & 31;
    int c = cell_ids[g];
    int nt = counts[c];
    int ks0 = g_cs[c];

    for (int u = tid; u < 512; u += 128) {
        int row = u >> 3, ch = u & 7;
        uint32_t dst = (uint32_t)(((row << 3) | (ch ^ (row & 7))) << 4);
        size_t go = (size_t)(g*64 + row)*HID + h*64 + ch*8;
        *(uint4*)(smem + AQH + dst) = *(const uint4*)(g_Qhi + go);
        *(uint4*)(smem + AQL + dst) = *(const uint4*)(g_Qlo + go);
    }
    {
        uint32_t kb = sb + AKV;
        for (int u = tid; u < 512; u += 128) {
            int row = u >> 3, ch = u & 7;
            uint32_t dst = (uint32_t)(((row << 3) | (ch ^ (row & 7))) << 4);
            size_t go = (size_t)(ks0*64 + row)*HID + h*64 + ch*8;
            cpa16(kb + dst,         g_Khi + go);
            cpa16(kb + 8192 + dst,  g_Klo + go);
            cpa16(kb + 16384 + dst, g_Vhi + go);
        }
        CP_COMMIT();
    }

    float oacc[8][4];
    #pragma unroll
    for (int t = 0; t < 8; t++)
        #pragma unroll
        for (int j = 0; j < 4; j++) oacc[t][j] = 0.f;
    float mA = -1e30f, mB = -1e30f, lA = 0.f, lB = 0.f;

    int arow = wid*16 + (lane & 15);

    for (int kt = 0; kt < nt; kt++) {
        uint32_t kb = sb + AKV + (uint32_t)(kt & 1)*AKVBUF;
        if (kt + 1 < nt) {
            uint32_t nb = sb + AKV + (uint32_t)((kt+1) & 1)*AKVBUF;
            int kg = ks0 + kt + 1;
            for (int u = tid; u < 512; u += 128) {
                int row = u >> 3, ch = u & 7;
                uint32_t dst = (uint32_t)(((row << 3) | (ch ^ (row & 7))) << 4);
                size_t go = (size_t)(kg*64 + row)*HID + h*64 + ch*8;
                cpa16(nb + dst,         g_Khi + go);
                cpa16(nb + 8192 + dst,  g_Klo + go);
                cpa16(nb + 16384 + dst, g_Vhi + go);
            }
            CP_COMMIT();
            CP_WAIT(1);
        } else {
            CP_WAIT(0);
        }
        __syncthreads();

        float sacc[8][4];
        #pragma unroll
        for (int t = 0; t < 8; t++)
            #pragma unroll
            for (int j = 0; j < 4; j++) sacc[t][j] = 0.f;
        #pragma unroll
        for (int s = 0; s < 4; s++) {
            int ac = s*2 + (lane >> 4);
            uint32_t aoff = (uint32_t)(((arow << 3) | (ac ^ (arow & 7))) << 4);
            uint32_t ah[4], al[4];
            ldsm_x4(ah, sb + AQH + aoff);
            ldsm_x4(al, sb + AQL + aoff);
            #pragma unroll
            for (int bt = 0; bt < 4; bt++) {
                int brow = bt*16 + (lane & 7) + ((lane >> 4) << 3);
                int bc   = s*2 + ((lane >> 3) & 1);
                uint32_t boff = (uint32_t)(((brow << 3) | (bc ^ (brow & 7))) << 4);
                uint32_t bh[4], bl[4];
                ldsm_x4(bh, kb + boff);
                ldsm_x4(bl, kb + 8192 + boff);
                mma16816(sacc[bt*2],   ah, &bh[0]);
                mma16816(sacc[bt*2],   ah, &bl[0]);
                mma16816(sacc[bt*2],   al, &bh[0]);
                mma16816(sacc[bt*2+1], ah, &bh[2]);
                mma16816(sacc[bt*2+1], ah, &bl[2]);
                mma16816(sacc[bt*2+1], al, &bh[2]);
            }
        }
        float mtA = -1e30f, mtB = -1e30f;
        #pragma unroll
        for (int t = 0; t < 8; t++) {
            sacc[t][0] *= 0.125f; sacc[t][1] *= 0.125f;
            sacc[t][2] *= 0.125f; sacc[t][3] *= 0.125f;
            mtA = fmaxf(mtA, fmaxf(sacc[t][0], sacc[t][1]));
            mtB = fmaxf(mtB, fmaxf(sacc[t][2], sacc[t][3]));
        }
        mtA = fmaxf(mtA, __shfl_xor_sync(~0u, mtA, 1));
        mtA = fmaxf(mtA, __shfl_xor_sync(~0u, mtA, 2));
        mtB = fmaxf(mtB, __shfl_xor_sync(~0u, mtB, 1));
        mtB = fmaxf(mtB, __shfl_xor_sync(~0u, mtB, 2));
        float mnA = fmaxf(mA, mtA), mnB = fmaxf(mB, mtB);
        float alA = __expf(mA - mnA), alB = __expf(mB - mnB);
        float ltA = 0.f, ltB = 0.f;
        #pragma unroll
        for (int t = 0; t < 8; t++) {
            sacc[t][0] = __expf(sacc[t][0] - mnA);
            sacc[t][1] = __expf(sacc[t][1] - mnA);
            sacc[t][2] = __expf(sacc[t][2] - mnB);
            sacc[t][3] = __expf(sacc[t][3] - mnB);
            ltA += sacc[t][0] + sacc[t][1];
            ltB += sacc[t][2] + sacc[t][3];
        }
        ltA += __shfl_xor_sync(~0u, ltA, 1); ltA += __shfl_xor_sync(~0u, ltA, 2);
        ltB += __shfl_xor_sync(~0u, ltB, 1); ltB += __shfl_xor_sync(~0u, ltB, 2);
        lA = lA*alA + ltA; lB = lB*alB + ltB;
        mA = mnA; mB = mnB;
        #pragma unroll
        for (int t = 0; t < 8; t++) {
            oacc[t][0] *= alA; oacc[t][1] *= alA;
            oacc[t][2] *= alB; oacc[t][3] *= alB;
        }
        #pragma unroll
        for (int t2 = 0; t2 < 4; t2++) {
            uint32_t pa[4];
            pa[0] = pkbf2(sacc[2*t2][0],   sacc[2*t2][1]);
            pa[1] = pkbf2(sacc[2*t2][2],   sacc[2*t2][3]);
            pa[2] = pkbf2(sacc[2*t2+1][0], sacc[2*t2+1][1]);
            pa[3] = pkbf2(sacc[2*t2+1][2], sacc[2*t2+1][3]);
            int grp = lane >> 3;
            int vrow = t2*16 + (lane & 7) + ((grp & 1) << 3);
            #pragma unroll
            for (int dblk = 0; dblk < 4; dblk++) {
                int vch = dblk*2 + (grp >> 1);
                uint32_t voff = (uint32_t)(((vrow << 3) | (vch ^ (vrow & 7))) << 4);
                uint32_t vb[4];
                ldsm_x4_t(vb, kb + 16384 + voff);
                mma16816(oacc[dblk*2],   pa, &vb[0]);
                mma16816(oacc[dblk*2+1], pa, &vb[2]);
            }
        }
        __syncthreads();
    }
    float invA = 1.f / lA, invB = 1.f / lB;
    float invS = 1.f / (float)(nt * 64);
    #pragma unroll
    for (int t = 0; t < 8; t++) {
        float s0 = oacc[t][0]*invA + oacc[t][2]*invB;
        float s1 = oacc[t][1]*invA + oacc[t][3]*invB;
        #pragma unroll
        for (int off = 4; off < 32; off <<= 1) {
            s0 += __shfl_xor_sync(~0u, s0, off);
            s1 += __shfl_xor_sync(~0u, s1, off);
        }
        if (lane < 4) {
            int col = h*64 + 2*lane + t*8;
            atomicAdd(g_csum + c*HID + col,     s0 * invS);
            atomicAdd(g_csum + c*HID + col + 1, s1 * invS);
        }
    }
}

// ---------------- k-split batched vec-mat ----------------
template<int KDIM, int NCOL, int RELUIN, int SRC>
__global__ void __launch_bounds__(256) k_vm2(const float* __restrict__ W,
                                             const float* __restrict__ bias) {
    const float* vin  = (SRC == 0) ? g_csum  : (SRC == 1) ? g_meanh : g_h1;
    float*       vout = (SRC == 0) ? g_meanh : (SRC == 1) ? g_h1    : g_h2;
    int n0 = blockIdx.x * 64, kb = blockIdx.y * 128;
    int tid = threadIdx.x;
    __shared__ float sp[128][68];
    __shared__ float sw[16][68];
    for (int u = tid; u < 2048; u += 256) {
        int c = u >> 5, kq = (u & 31) * 4;
        float4 v = *(const float4*)(vin + c*KDIM + kb + kq);
        if (RELUIN) {
            v.x = fmaxf(v.x, 0.f); v.y = fmaxf(v.y, 0.f);
            v.z = fmaxf(v.z, 0.f); v.w = fmaxf(v.w, 0.f);
        }
        sp[kq+0][c] = v.x; sp[kq+1][c] = v.y;
        sp[kq+2][c] = v.z; sp[kq+3][c] = v.w;
    }
    u64 acc2[4][2];
    #pragma unroll
    for (int i = 0; i < 4; i++) { acc2[i][0] = 0ull; acc2[i][1] = 0ull; }
    int tb = (tid & 15) * 4;
    int th = (tid >> 4) * 4;
    int lr = tid >> 4, lc = (tid & 15) * 4;
    __syncthreads();
    for (int k0 = 0; k0 < 128; k0 += 16) {
        *(float4*)&sw[lr][lc] = *(const float4*)(W + (size_t)(kb + k0 + lr)*NCOL + n0 + lc);
        __syncthreads();
        #pragma unroll
        for (int kk = 0; kk < 16; kk++) {
            float4 a = *(float4*)&sp[k0+kk][tb];
            u64 b0 = *(u64*)&sw[kk][th];
            u64 b1 = *(u64*)&sw[kk][th+2];
            float av[4] = {a.x, a.y, a.z, a.w};
            #pragma unroll
            for (int i = 0; i < 4; i++) {
                u64 ad = dup2(av[i]);
                acc2[i][0] = ffma2(ad, b0, acc2[i][0]);
                acc2[i][1] = ffma2(ad, b1, acc2[i][1]);
            }
        }
        __syncthreads();
    }
    #pragma unroll
    for (int i = 0; i < 4; i++) {
        int c = tb + i;
        float2 f0 = up2(acc2[i][0]), f1 = up2(acc2[i][1]);
        float o[4] = {f0.x, f0.y, f1.x, f1.y};
        #pragma unroll
        for (int j = 0; j < 4; j++) {
            if (blockIdx.y == 0) o[j] += bias[n0 + th + j];
            atomicAdd(vout + (size_t)c*NCOL + n0 + th + j, o[j]);
        }
    }
}

// ---------------- layernorm ----------------
__global__ void k_ln(const float* __restrict__ lng, const float* __restrict__ lnb,
                     float* __restrict__ out) {
    int c = blockIdx.x, t = threadIdx.x;
    __shared__ float sh[34];
    float v0 = g_h2[c*HID + t], v1 = g_h2[c*HID + 256 + t];
    int lane = t & 31, w = t >> 5;
    float s = v0 + v1;
    #pragma unroll
    for (int off = 16; off; off >>= 1) s += __shfl_xor_sync(~0u, s, off);
    if (lane == 0) sh[w] = s;
    __syncthreads();
    if (w == 0) {
        float tot = (t < 8) ? sh[t] : 0.f;
        #pragma unroll
        for (int off = 4; off; off >>= 1) tot += __shfl_xor_sync(~0u, tot, off);
        if (t == 0) sh[32] = tot;
    }
    __syncthreads();
    float mu = sh[32] * (1.f/512.f);
    float d0 = v0 - mu, d1 = v1 - mu;
    float q = d0*d0 + d1*d1;
    #pragma unroll
    for (int off = 16; off; off >>= 1) q += __shfl_xor_sync(~0u, q, off);
    if (lane == 0) sh[w] = q;
    __syncthreads();
    if (w == 0) {
        float tot = (t < 8) ? sh[t] : 0.f;
        #pragma unroll
        for (int off = 4; off; off >>= 1) tot += __shfl_xor_sync(~0u, tot, off);
        if (t == 0) sh[33] = tot;
    }
    __syncthreads();
    float inv = rsqrtf(sh[33] * (1.f/512.f) + 1e-5f);
    float r0 = d0*inv*lng[t]     + lnb[t];
    float r1 = d1*inv*lng[256+t] + lnb[256+t];
    g_int[c*HID + t]       = r0;
    g_int[c*HID + 256 + t] = r1;
    out[64 + c*HID + t]       = r0;
    out[64 + c*HID + 256 + t] = r1;
}

// ---------------- per-cell affinity head (8 blocks/cell, fused sigmoid) ----------------
__global__ void __launch_bounds__(64) k_aff(const float* __restrict__ Aw1,
                                            const float* __restrict__ Ab1,
                                            const float* __restrict__ Aw2,
                                            const float* __restrict__ Ab2,
                                            float* __restrict__ out) {
    int c = blockIdx.x;
    int k = blockIdx.y * 64 + threadIdx.x;
    __shared__ float a[HID];
    __shared__ float red[2];
    for (int j = threadIdx.x; j < HID; j += 64) a[j] = g_int[c*HID + j];
    __syncthreads();
    float acc = Ab1[c*HID + k];
    const float* W = Aw1 + (size_t)c*HID*HID + k;
    #pragma unroll 8
    for (int j = 0; j < HID; j++) acc += a[j] * W[(size_t)j*HID];
    float part = fmaxf(acc, 0.f) * Aw2[c*HID + k];
    int lane = threadIdx.x & 31, w = threadIdx.x >> 5;
    #pragma unroll
    for (int off = 16; off; off >>= 1) part += __shfl_xor_sync(~0u, part, off);
    if (lane == 0) red[w] = part;
    __syncthreads();
    if (threadIdx.x == 0) {
        atomicAdd(&g_affacc[c], red[0] + red[1]);
        __threadfence();
        int done = atomicAdd(&g_affcnt[c], 1);
        if (done == 7) {
            float s = *((volatile float*)&g_affacc[c]);
            out[c] = 1.f / (1.f + expf(-(s + Ab2[c])));
        }
    }
}

extern "C" void kernel_launch(void* const* d_in, const int* in_sizes, int n_in,
                              void* d_out, int out_size) {
    const float* x       = (const float*)d_in[0];
    const int*   ei      = (const int*)  d_in[1];
    const float* gene_W  = (const float*)d_in[3];
    const float* gene_b  = (const float*)d_in[4];
    const int*   cell_ids= (const int*)  d_in[5];
    const int*   counts  = (const int*)  d_in[7];
    const float* Wq = (const float*)d_in[8],  *bq = (const float*)d_in[9];
    const float* Wk = (const float*)d_in[10], *bk = (const float*)d_in[11];
    const float* Wv = (const float*)d_in[12], *bv = (const float*)d_in[13];
    const float* Wo = (const float*)d_in[14], *bo = (const float*)d_in[15];
    const float* Wi1= (const float*)d_in[16], *bi1= (const float*)d_in[17];
    const float* Wi2= (const float*)d_in[18], *bi2= (const float*)d_in[19];
    const float* lng= (const float*)d_in[20], *lnb= (const float*)d_in[21];
    const float* Aw1= (const float*)d_in[22], *Ab1= (const float*)d_in[23];
    const float* Aw2= (const float*)d_in[24], *Ab2= (const float*)d_in[25];
    float* out = (float*)d_out;

    cudaFuncSetAttribute(k_attn_mma, cudaFuncAttributeMaxDynamicSharedMemorySize, ATTN_SMEM);
    cudaFuncSetAttribute(k_qkv_mma, cudaFuncAttributeMaxDynamicSharedMemorySize, QKV_SMEM);
    cudaFuncSetAttribute(k_gene_mma, cudaFuncAttributeMaxDynamicSharedMemorySize, GENE_SMEM);

    k_prep <<<1024, 256>>>(counts, Wq, Wk, Wv);
    k_edges<<<(NEDGES*32)/256, 256>>>(x, ei);
    k_pool <<<NB, 128>>>(x);
    k_gene_mma<<<dim3(NG, 8), 256, GENE_SMEM>>>(gene_W, gene_b);
    k_qkv_mma<<<dim3(MTILES, 8), 256, QKV_SMEM>>>(bq, bk, bv);
    k_attn_mma<<<dim3(NG, 8), 128, ATTN_SMEM>>>(cell_ids, counts);
    k_vm2<512,  512, 0, 0><<<dim3(8, 4),  256>>>(Wo,  bo);
    k_vm2<512, 1024, 0, 1><<<dim3(16, 4), 256>>>(Wi1, bi1);
    k_vm2<1024, 512, 1, 2><<<dim3(8, 8),  256>>>(Wi2, bi2);
    k_ln  <<<NC, 256>>>(lng, lnb, out);
    k_aff <<<dim3(NC, 8), 64>>>(Aw1, Ab1, Aw2, Ab2, out);
}